// round 12
// baseline (speedup 1.0000x reference)
#include <cuda_runtime.h>
#include <cuda_bf16.h>
#include <cuda_fp16.h>
#include <cstdint>

// Problem constants
#define Tn   2048
#define Cdim 4096
#define NH   32
#define NKV  8
#define Dh   128
#define HDq  (NH*Dh)    // 4096
#define HDkv (NKV*Dh)   // 1024
#define HDA  (HDq + 2*HDkv)   // 6144 merged Q|K|V
#define LOG2E 1.4426950408889634f

// ---------------- scratch (device globals; no allocation) ----------------
__device__ __align__(256) float g_tqkv[(size_t)Tn * HDA];

__device__ __align__(256) __nv_bfloat16 g_xhi[Tn * Cdim];
__device__ __align__(256) __nv_bfloat16 g_xlo[Tn * Cdim];
__device__ __align__(256) __nv_bfloat16 g_qhi[(size_t)NH * Tn * Dh];
__device__ __align__(256) __nv_bfloat16 g_qlo[(size_t)NH * Tn * Dh];
__device__ __align__(256) __nv_bfloat16 g_khi[(size_t)NKV * Tn * Dh];
__device__ __align__(256) __nv_bfloat16 g_klo[(size_t)NKV * Tn * Dh];
__device__ __align__(256) __half       g_vh [(size_t)NKV * Tn * Dh];
__device__ __align__(256) __half       g_ybhi[Tn * Cdim];
__device__ __align__(256) __half       g_yblo[Tn * Cdim];
__device__ __align__(256) __nv_bfloat16 g_wahi[(size_t)HDA * Cdim];
__device__ __align__(256) __nv_bfloat16 g_walo[(size_t)HDA * Cdim];
__device__ __align__(256) __half       g_wohi[(size_t)Cdim * Cdim];

// ---------------- baseline-ISA helpers (sm_80+ PTX only) ----------------
__device__ __forceinline__ uint32_t smem_u32(const void* p) {
    uint32_t a;
    asm("{ .reg .u64 t; cvta.to.shared.u64 t, %1; cvt.u32.u64 %0, t; }" : "=r"(a) : "l"(p));
    return a;
}

#define CP_ASYNC16(sm, gp) \
    asm volatile("cp.async.cg.shared.global [%0], [%1], 16;" :: "r"(sm), "l"(gp) : "memory")
#define CP_COMMIT() asm volatile("cp.async.commit_group;" ::: "memory")
#define CP_WAIT(n)  asm volatile("cp.async.wait_group %0;" :: "n"(n) : "memory")

__device__ __forceinline__ void ldsm4(uint32_t* r, uint32_t addr) {
    asm volatile("ldmatrix.sync.aligned.m8n8.x4.shared.b16 {%0,%1,%2,%3}, [%4];"
        : "=r"(r[0]), "=r"(r[1]), "=r"(r[2]), "=r"(r[3]) : "r"(addr));
}
__device__ __forceinline__ void ldsm4t(uint32_t* r, uint32_t addr) {
    asm volatile("ldmatrix.sync.aligned.m8n8.x4.trans.shared.b16 {%0,%1,%2,%3}, [%4];"
        : "=r"(r[0]), "=r"(r[1]), "=r"(r[2]), "=r"(r[3]) : "r"(addr));
}

__device__ __forceinline__ void mma_bf16(float* c, const uint32_t* a, const uint32_t* b) {
    asm volatile(
        "mma.sync.aligned.m16n8k16.row.col.f32.bf16.bf16.f32 "
        "{%0,%1,%2,%3}, {%4,%5,%6,%7}, {%8,%9}, {%0,%1,%2,%3};"
        : "+f"(c[0]), "+f"(c[1]), "+f"(c[2]), "+f"(c[3])
        : "r"(a[0]), "r"(a[1]), "r"(a[2]), "r"(a[3]), "r"(b[0]), "r"(b[1]));
}
__device__ __forceinline__ void mma_f16(float* c, const uint32_t* a, const uint32_t* b) {
    asm volatile(
        "mma.sync.aligned.m16n8k16.row.col.f32.f16.f16.f32 "
        "{%0,%1,%2,%3}, {%4,%5,%6,%7}, {%8,%9}, {%0,%1,%2,%3};"
        : "+f"(c[0]), "+f"(c[1]), "+f"(c[2]), "+f"(c[3])
        : "r"(a[0]), "r"(a[1]), "r"(a[2]), "r"(a[3]), "r"(b[0]), "r"(b[1]));
}

__device__ __forceinline__ void split2h(float a, float b, uint32_t& hi, uint32_t& lo) {
    __half2 H = __floats2half2_rn(a, b);
    float ra = a - __half2float(__low2half(H));
    float rb = b - __half2float(__high2half(H));
    __half2 L = __floats2half2_rn(ra, rb);
    hi = *reinterpret_cast<uint32_t*>(&H);
    lo = *reinterpret_cast<uint32_t*>(&L);
}

// pack 4 floats -> 4 bf16 hi (uint2) + 4 bf16 lo (uint2)
__device__ __forceinline__ void pack4b(float a, float b, float c, float d,
                                       uint2& hi, uint2& lo) {
    __nv_bfloat16 h0 = __float2bfloat16(a), h1 = __float2bfloat16(b);
    __nv_bfloat16 h2 = __float2bfloat16(c), h3 = __float2bfloat16(d);
    __nv_bfloat162 H01; H01.x = h0; H01.y = h1;
    __nv_bfloat162 H23; H23.x = h2; H23.y = h3;
    __nv_bfloat162 L01, L23;
    L01.x = __float2bfloat16(a - __bfloat162float(h0));
    L01.y = __float2bfloat16(b - __bfloat162float(h1));
    L23.x = __float2bfloat16(c - __bfloat162float(h2));
    L23.y = __float2bfloat16(d - __bfloat162float(h3));
    hi.x = *reinterpret_cast<uint32_t*>(&H01);
    hi.y = *reinterpret_cast<uint32_t*>(&H23);
    lo.x = *reinterpret_cast<uint32_t*>(&L01);
    lo.y = *reinterpret_cast<uint32_t*>(&L23);
}

// ---------------- merged prep: x split + W transposes, one launch ----------------
#define PREP_X   4096
#define PREP_WQ  (PREP_X + 16384)
#define PREP_WK  (PREP_WQ + 4096)
#define PREP_WV  (PREP_WK + 4096)
#define PREP_END (PREP_WV + 16384)

__global__ void __launch_bounds__(256) prep_kernel(
    const float* __restrict__ x,
    const float* __restrict__ Wq, const float* __restrict__ Wk,
    const float* __restrict__ Wv, const float* __restrict__ Wo)
{
    __shared__ float tile[32][33];
    const int bid = blockIdx.x;
    if (bid < PREP_X) {
        int base = (bid * 256 + threadIdx.x) * 8;
#pragma unroll
        for (int half = 0; half < 2; half++) {
            int idx = base + half * 4;
            float4 v = *(const float4*)&x[idx];
            uint2 hi, lo;
            pack4b(v.x, v.y, v.z, v.w, hi, lo);
            *(uint2*)&g_xhi[idx] = hi;
            *(uint2*)&g_xlo[idx] = lo;
        }
        return;
    }
    const float* W;
    __nv_bfloat16 *Thi, *Tlo;
    int N, rel;
    bool is_half = false;
    if (bid < PREP_WQ)      { rel = bid - PREP_X;  W = Wq; N = HDq;
                              Thi = g_wahi; Tlo = g_walo; }
    else if (bid < PREP_WK) { rel = bid - PREP_WQ; W = Wk; N = HDkv;
                              Thi = g_wahi + (size_t)HDq * Cdim;
                              Tlo = g_walo + (size_t)HDq * Cdim; }
    else if (bid < PREP_WV) { rel = bid - PREP_WK; W = Wv; N = HDkv;
                              Thi = g_wahi + (size_t)(HDq + HDkv) * Cdim;
                              Tlo = g_walo + (size_t)(HDq + HDkv) * Cdim; }
    else                    { rel = bid - PREP_WV; W = Wo; N = Cdim;
                              Thi = nullptr; Tlo = nullptr; is_half = true; }

    const int ntiles = N / 32;
    int n0 = (rel % ntiles) * 32, k0 = (rel / ntiles) * 32;
    int tx = threadIdx.x & 31, ty = threadIdx.x >> 5;
#pragma unroll
    for (int j = 0; j < 4; j++)
        tile[ty + 8 * j][tx] = W[(size_t)(k0 + ty + 8 * j) * N + n0 + tx];
    __syncthreads();

    int n  = threadIdx.x >> 3;
    int kq = (threadIdx.x & 7) * 4;
    float v0 = tile[kq + 0][n], v1 = tile[kq + 1][n];
    float v2 = tile[kq + 2][n], v3 = tile[kq + 3][n];
    size_t o = (size_t)(n0 + n) * Cdim + k0 + kq;
    if (is_half) {
        __half2 a = __floats2half2_rn(v0, v1);
        __half2 b = __floats2half2_rn(v2, v3);
        uint2 pk;
        pk.x = *reinterpret_cast<uint32_t*>(&a);
        pk.y = *reinterpret_cast<uint32_t*>(&b);
        *(uint2*)&g_wohi[o] = pk;
    } else {
        uint2 hi, lo;
        pack4b(v0, v1, v2, v3, hi, lo);
        *(uint2*)&Thi[o] = hi;
        *(uint2*)&Tlo[o] = lo;
    }
}

// ---------------- GEMM common geometry ----------------
#define PITCH   80
#define T_A     10240                  // 128 rows * 80B

// ---------------- bf16 3-MMA GEMM: C = A(hi/lo) * B(hi/lo)^T ----------------
#define T_STAGE (4 * T_A)
#define G_SMEM  (2 * T_STAGE)          // 81920

__device__ __forceinline__ void g_load_pair(
    uint32_t sbase, const __nv_bfloat16* __restrict__ hi,
    const __nv_bfloat16* __restrict__ lo, int rbase, int kc, int K, int tid)
{
#pragma unroll
    for (int i = 0; i < 2; i++) {
        int s = tid + 256 * i;
        int row = s >> 2, part = s & 3;
        size_t go = (size_t)(rbase + row) * K + (size_t)kc * 32 + part * 8;
        uint32_t so = (uint32_t)(row * PITCH + part * 16);
        CP_ASYNC16(sbase + so, hi + go);
        CP_ASYNC16(sbase + T_A + so, lo + go);
    }
}

__global__ void __launch_bounds__(256, 2) tcgemm_kernel(
    const __nv_bfloat16* __restrict__ Ahi, const __nv_bfloat16* __restrict__ Alo,
    const __nv_bfloat16* __restrict__ Bhi, const __nv_bfloat16* __restrict__ Blo,
    float* __restrict__ C, int N, int K)
{
    extern __shared__ char smc[];
    const uint32_t sb0 = smem_u32(smc);
    const int tid  = threadIdx.x;
    const int lane = tid & 31;
    const int wid  = tid >> 5;
    const int wm   = wid & 1;
    const int wn   = wid >> 1;
    const int row0 = blockIdx.y * 128;
    const int col0 = blockIdx.x * 128;

    float acc[4][4][4];
#pragma unroll
    for (int m = 0; m < 4; m++)
#pragma unroll
        for (int n = 0; n < 4; n++)
#pragma unroll
            for (int e = 0; e < 4; e++) acc[m][n][e] = 0.f;

    const uint32_t a_row = (uint32_t)(wm * 64 + (lane & 15));
    const uint32_t a_kb  = (uint32_t)((lane >> 4) * 16);
    const int bmat = lane >> 3, bwin = lane & 7;
    const uint32_t b_n  = (uint32_t)(wn * 32 + bwin + (bmat >> 1) * 8);
    const uint32_t b_kb = (uint32_t)((bmat & 1) * 16);

    const int nk = K >> 5;

    g_load_pair(sb0,           Ahi, Alo, row0, 0, K, tid);
    g_load_pair(sb0 + 2 * T_A, Bhi, Blo, col0, 0, K, tid);
    CP_COMMIT();

    for (int kc = 0; kc < nk; kc++) {
        uint32_t sb = sb0 + (uint32_t)(kc & 1) * T_STAGE;
        if (kc + 1 < nk) {
            uint32_t sb2 = sb0 + (uint32_t)((kc + 1) & 1) * T_STAGE;
            g_load_pair(sb2,           Ahi, Alo, row0, kc + 1, K, tid);
            g_load_pair(sb2 + 2 * T_A, Bhi, Blo, col0, kc + 1, K, tid);
            CP_COMMIT();
            CP_WAIT(1);
        } else {
            CP_WAIT(0);
        }
        __syncthreads();

        const uint32_t aB = sb + a_row * PITCH + a_kb;
        const uint32_t bB = sb + 2 * T_A + b_n * PITCH + b_kb;

#pragma unroll
        for (int ks = 0; ks < 2; ks++) {
            uint32_t ah[4][4], al[4][4], bh[2][4], bl[2][4];
#pragma unroll
            for (int m = 0; m < 4; m++) {
                ldsm4(ah[m], aB + (uint32_t)(m * 16 * PITCH) + ks * 32);
                ldsm4(al[m], aB + T_A + (uint32_t)(m * 16 * PITCH) + ks * 32);
            }
#pragma unroll
            for (int p = 0; p < 2; p++) {
                ldsm4(bh[p], bB + (uint32_t)(p * 16 * PITCH) + ks * 32);
                ldsm4(bl[p], bB + T_A + (uint32_t)(p * 16 * PITCH) + ks * 32);
            }
#pragma unroll
            for (int m = 0; m < 4; m++)
#pragma unroll
                for (int p = 0; p < 2; p++)
#pragma unroll
                    for (int h = 0; h < 2; h++) {
                        float* c = acc[m][p * 2 + h];
                        uint32_t bhh[2] = {bh[p][h * 2], bh[p][h * 2 + 1]};
                        uint32_t bll[2] = {bl[p][h * 2], bl[p][h * 2 + 1]};
                        mma_bf16(c, ah[m], bhh);
                        mma_bf16(c, ah[m], bll);
                        mma_bf16(c, al[m], bhh);
                    }
        }
        __syncthreads();
    }

    const int g = lane >> 2, t = lane & 3;
#pragma unroll
    for (int m = 0; m < 4; m++) {
        int r0 = row0 + wm * 64 + m * 16 + g;
#pragma unroll
        for (int n = 0; n < 4; n++) {
            int c = col0 + wn * 32 + n * 8 + 2 * t;
            *(float2*)&C[(size_t)r0 * N + c] = make_float2(acc[m][n][0], acc[m][n][1]);
            *(float2*)&C[(size_t)(r0 + 8) * N + c] = make_float2(acc[m][n][2], acc[m][n][3]);
        }
    }
}

// ---------------- fp16 2-MMA GEMM (3-stage pipeline): C = (Ahi+Alo) * Bhi^T ------
#define T2_STAGE (3 * T_A)             // Ah, Al, Bh = 30720
#define G2_SMEM  (3 * T2_STAGE)        // 92160 (3-stage ring)

__global__ void __launch_bounds__(256, 2) tcgemm2_kernel(
    const __half* __restrict__ Ahi, const __half* __restrict__ Alo,
    const __half* __restrict__ Bhi,
    float* __restrict__ C, int N, int K)
{
    extern __shared__ char smc[];
    const uint32_t sb0 = smem_u32(smc);
    const int tid  = threadIdx.x;
    const int lane = tid & 31;
    const int wid  = tid >> 5;
    const int wm   = wid & 1;
    const int wn   = wid >> 1;
    const int row0 = blockIdx.y * 128;
    const int col0 = blockIdx.x * 128;

    float acc[4][4][4];
#pragma unroll
    for (int m = 0; m < 4; m++)
#pragma unroll
        for (int n = 0; n < 4; n++)
#pragma unroll
            for (int e = 0; e < 4; e++) acc[m][n][e] = 0.f;

    const uint32_t a_row = (uint32_t)(wm * 64 + (lane & 15));
    const uint32_t a_kb  = (uint32_t)((lane >> 4) * 16);
    const int bmat = lane >> 3, bwin = lane & 7;
    const uint32_t b_n  = (uint32_t)(wn * 32 + bwin + (bmat >> 1) * 8);
    const uint32_t b_kb = (uint32_t)((bmat & 1) * 16);

    const int nk = K >> 5;

    auto load_stage = [&](uint32_t sb, int kc) {
#pragma unroll
        for (int i = 0; i < 2; i++) {
            int s = tid + 256 * i;
            int row = s >> 2, part = s & 3;
            size_t goA = (size_t)(row0 + row) * K + (size_t)kc * 32 + part * 8;
            size_t goB = (size_t)(col0 + row) * K + (size_t)kc * 32 + part * 8;
            uint32_t so = (uint32_t)(row * PITCH + part * 16);
            CP_ASYNC16(sb + so,           Ahi + goA);
            CP_ASYNC16(sb + T_A + so,     Alo + goA);
            CP_ASYNC16(sb + 2 * T_A + so, Bhi + goB);
        }
    };

    // prologue: stages 0 and 1 in flight (nk = 128 >= 2 always)
    load_stage(sb0, 0);
    CP_COMMIT();
    load_stage(sb0 + T2_STAGE, 1);
    CP_COMMIT();

    for (int kc = 0; kc < nk; kc++) {
        if (kc + 1 < nk) CP_WAIT(1); else CP_WAIT(0);
        __syncthreads();
        // issue stage kc+2 (ring slot free since iter kc-1 done by the barrier)
        if (kc + 2 < nk) {
            load_stage(sb0 + (uint32_t)((kc + 2) % 3) * T2_STAGE, kc + 2);
            CP_COMMIT();
        }

        uint32_t sb = sb0 + (uint32_t)(kc % 3) * T2_STAGE;
        const uint32_t aB = sb + a_row * PITCH + a_kb;
        const uint32_t bB = sb + 2 * T_A + b_n * PITCH + b_kb;

#pragma unroll
        for (int ks = 0; ks < 2; ks++) {
            uint32_t ah[4][4], al[4][4], bh[2][4];
#pragma unroll
            for (int m = 0; m < 4; m++) {
                ldsm4(ah[m], aB + (uint32_t)(m * 16 * PITCH) + ks * 32);
                ldsm4(al[m], aB + T_A + (uint32_t)(m * 16 * PITCH) + ks * 32);
            }
#pragma unroll
            for (int p = 0; p < 2; p++)
                ldsm4(bh[p], bB + (uint32_t)(p * 16 * PITCH) + ks * 32);
#pragma unroll
            for (int m = 0; m < 4; m++)
#pragma unroll
                for (int p = 0; p < 2; p++)
#pragma unroll
                    for (int h = 0; h < 2; h++) {
                        float* c = acc[m][p * 2 + h];
                        uint32_t bhh[2] = {bh[p][h * 2], bh[p][h * 2 + 1]};
                        mma_f16(c, ah[m], bhh);
                        mma_f16(c, al[m], bhh);
                    }
        }
    }

    const int g = lane >> 2, t = lane & 3;
#pragma unroll
    for (int m = 0; m < 4; m++) {
        int r0 = row0 + wm * 64 + m * 16 + g;
#pragma unroll
        for (int n = 0; n < 4; n++) {
            int c = col0 + wn * 32 + n * 8 + 2 * t;
            *(float2*)&C[(size_t)r0 * N + c] = make_float2(acc[m][n][0], acc[m][n][1]);
            *(float2*)&C[(size_t)(r0 + 8) * N + c] = make_float2(acc[m][n][2], acc[m][n][3]);
        }
    }
}

// ---------------- merged RoPE (vectorized): q part + kv part, one launch --------
// q additionally scaled by log2(e) so flash can use exp2f.
#define ROPE_QBLOCKS ((NH * Tn * 16) / 256)     // 4096
#define ROPE_KVBLOCKS ((NKV * Tn * 16) / 256)   // 1024

__global__ void __launch_bounds__(256) rope_all_kernel(
    const float* __restrict__ cosb, const float* __restrict__ sinb,
    float* __restrict__ outK, float* __restrict__ outV)
{
    int bid = blockIdx.x;
    if (bid < ROPE_QBLOCKS) {
        int idx = bid * 256 + threadIdx.x;
        int d = (idx & 15) * 4;
        int t = (idx >> 4) & (Tn - 1);
        int h = idx >> 15;
        const float* src = g_tqkv + (size_t)t * HDA + h * Dh;
        float4 u1 = *(const float4*)(src + d);
        float4 u2 = *(const float4*)(src + d + 64);
        float4 c1 = *(const float4*)&cosb[t * Dh + d];
        float4 s1 = *(const float4*)&sinb[t * Dh + d];
        float4 c2 = *(const float4*)&cosb[t * Dh + d + 64];
        float4 s2 = *(const float4*)&sinb[t * Dh + d + 64];
        float4 y1 = make_float4((u1.x * c1.x - u2.x * s1.x) * LOG2E,
                                (u1.y * c1.y - u2.y * s1.y) * LOG2E,
                                (u1.z * c1.z - u2.z * s1.z) * LOG2E,
                                (u1.w * c1.w - u2.w * s1.w) * LOG2E);
        float4 y2 = make_float4((u2.x * c2.x + u1.x * s2.x) * LOG2E,
                                (u2.y * c2.y + u1.y * s2.y) * LOG2E,
                                (u2.z * c2.z + u1.z * s2.z) * LOG2E,
                                (u2.w * c2.w + u1.w * s2.w) * LOG2E);
        size_t o = ((size_t)h * Tn + t) * Dh + d;
        uint2 hi1, lo1, hi2, lo2;
        pack4b(y1.x, y1.y, y1.z, y1.w, hi1, lo1);
        pack4b(y2.x, y2.y, y2.z, y2.w, hi2, lo2);
        *(uint2*)&g_qhi[o]      = hi1;
        *(uint2*)&g_qlo[o]      = lo1;
        *(uint2*)&g_qhi[o + 64] = hi2;
        *(uint2*)&g_qlo[o + 64] = lo2;
    } else {
        int idx = (bid - ROPE_QBLOCKS) * 256 + threadIdx.x;
        int d  = (idx & 15) * 4;
        int t  = (idx >> 4) & (Tn - 1);
        int kh = idx >> 15;
        const float* srck = g_tqkv + (size_t)t * HDA + HDq + kh * Dh;
        float4 u1 = *(const float4*)(srck + d);
        float4 u2 = *(const float4*)(srck + d + 64);
        float4 c1 = *(const float4*)&cosb[t * Dh + d];
        float4 s1 = *(const float4*)&sinb[t * Dh + d];
        float4 c2 = *(const float4*)&cosb[t * Dh + d + 64];
        float4 s2 = *(const float4*)&sinb[t * Dh + d + 64];
        float4 y1 = make_float4(u1.x * c1.x - u2.x * s1.x, u1.y * c1.y - u2.y * s1.y,
                                u1.z * c1.z - u2.z * s1.z, u1.w * c1.w - u2.w * s1.w);
        float4 y2 = make_float4(u2.x * c2.x + u1.x * s2.x, u2.y * c2.y + u1.y * s2.y,
                                u2.z * c2.z + u1.z * s2.z, u2.w * c2.w + u1.w * s2.w);
        size_t o = ((size_t)kh * Tn + t) * Dh + d;
        *(float4*)(outK + o)      = y1;
        *(float4*)(outK + o + 64) = y2;
        uint2 hi1, lo1, hi2, lo2;
        pack4b(y1.x, y1.y, y1.z, y1.w, hi1, lo1);
        pack4b(y2.x, y2.y, y2.z, y2.w, hi2, lo2);
        *(uint2*)&g_khi[o]      = hi1;
        *(uint2*)&g_klo[o]      = lo1;
        *(uint2*)&g_khi[o + 64] = hi2;
        *(uint2*)&g_klo[o + 64] = lo2;
        const float* srcv = srck + HDkv;
        float4 v1 = *(const float4*)(srcv + d);
        float4 v2 = *(const float4*)(srcv + d + 64);
        *(float4*)(outV + o)      = v1;
        *(float4*)(outV + o + 64) = v2;
        __half2 a1 = __floats2half2_rn(v1.x, v1.y);
        __half2 b1 = __floats2half2_rn(v1.z, v1.w);
        __half2 a2 = __floats2half2_rn(v2.x, v2.y);
        __half2 b2 = __floats2half2_rn(v2.z, v2.w);
        uint2 p1, p2;
        p1.x = *reinterpret_cast<uint32_t*>(&a1);
        p1.y = *reinterpret_cast<uint32_t*>(&b1);
        p2.x = *reinterpret_cast<uint32_t*>(&a2);
        p2.y = *reinterpret_cast<uint32_t*>(&b2);
        *(uint2*)&g_vh[o]      = p1;
        *(uint2*)&g_vh[o + 64] = p2;
    }
}

// ---------------- flash attention (QK: bf16 3-MMA, PV: fp16 2-MMA) ----------------
// q pre-scaled by log2(e) -> softmax uses exp2f.
#define FP272   272
#define QTILE   (128 * FP272)          // 34816
#define KTILE   (64 * FP272)           // 17408
#define FSTAGE  (3 * KTILE)            // Kh, Kl, Vh = 52224
#define F_SMEM  (2 * QTILE + 3 * FSTAGE)  // 226304

__device__ __forceinline__ void f_load_kv(
    uint32_t st, const __nv_bfloat16* __restrict__ kh,
    const __nv_bfloat16* __restrict__ kl, const __half* __restrict__ vh, int tid)
{
#pragma unroll
    for (int i = 0; i < 4; i++) {
        int s = tid + 256 * i;
        int r = s >> 4, c = s & 15;
        uint32_t so = (uint32_t)(r * FP272 + c * 16);
        size_t go = (size_t)r * Dh + c * 8;
        CP_ASYNC16(st + so,             kh + go);
        CP_ASYNC16(st + KTILE + so,     kl + go);
        CP_ASYNC16(st + 2 * KTILE + so, vh + go);
    }
}

__global__ void __launch_bounds__(256) flash_mma_kernel(
    __half* __restrict__ ybhi, __half* __restrict__ yblo)
{
    extern __shared__ char smc[];
    const uint32_t sb = smem_u32(smc);
    const int tid = threadIdx.x, lane = tid & 31, w = tid >> 5;
    const int h  = blockIdx.y;
    const int qi = (int)gridDim.x - 1 - (int)blockIdx.x;   // big tiles first
    const int q0 = qi * 128;
    const int kvh = h >> 2;
    const int nb = 2 * qi + 2;

    const uint32_t sQh = sb, sQl = sb + QTILE;
    const uint32_t sKV = sb + 2 * QTILE;

    const uint32_t aQoff = (uint32_t)((16 * w + (lane & 15)) * FP272 + (lane >> 4) * 16);
    const int bmat = lane >> 3, bwin = lane & 7;
    const uint32_t bKoff = (uint32_t)((bwin + ((bmat >> 1) << 3)) * FP272 + ((bmat & 1) << 4));
    const uint32_t bVoff = (uint32_t)((lane & 15) * FP272 + ((lane >> 4) << 4));

    const __nv_bfloat16* gKh = g_khi + (size_t)kvh * Tn * Dh;
    const __nv_bfloat16* gKl = g_klo + (size_t)kvh * Tn * Dh;
    const __half*        gVh = g_vh  + (size_t)kvh * Tn * Dh;

    {
        const __nv_bfloat16* gqh = g_qhi + ((size_t)h * Tn + q0) * Dh;
        const __nv_bfloat16* gql = g_qlo + ((size_t)h * Tn + q0) * Dh;
#pragma unroll
        for (int i = 0; i < 8; i++) {
            int s = tid + 256 * i;
            int r = s >> 4, c = s & 15;
            uint32_t so = (uint32_t)(r * FP272 + c * 16);
            size_t go = (size_t)r * Dh + c * 8;
            CP_ASYNC16(sQh + so, gqh + go);
            CP_ASYNC16(sQl + so, gql + go);
        }
        f_load_kv(sKV, gKh, gKl, gVh, tid);
        CP_COMMIT();
        f_load_kv(sKV + FSTAGE, gKh + (size_t)64 * Dh, gKl + (size_t)64 * Dh,
                  gVh + (size_t)64 * Dh, tid);
        CP_COMMIT();
    }

    CP_WAIT(1);
    __syncthreads();
    uint32_t qh_f[8][4], ql_f[8][4];
#pragma unroll
    for (int ks = 0; ks < 8; ks++) {
        ldsm4(qh_f[ks], sQh + aQoff + ks * 32);
        ldsm4(ql_f[ks], sQl + aQoff + ks * 32);
    }

    float o[16][4];
#pragma unroll
    for (int dt = 0; dt < 16; dt++)
#pragma unroll
        for (int e = 0; e < 4; e++) o[dt][e] = 0.f;
    float m0 = -1e30f, m1 = -1e30f, l0 = 0.f, l1 = 0.f;

    const int row_lo = q0 + 16 * w + (lane >> 2);
    const int row_hi = row_lo + 8;

    for (int j = 0; j < nb; j++) {
        if (j > 0) {
            if (j + 1 < nb) CP_WAIT(1); else CP_WAIT(0);
            __syncthreads();
        }
        if (j + 2 < nb) {
            size_t kb = (size_t)(j + 2) * 64;
            f_load_kv(sKV + (uint32_t)((j + 2) % 3) * FSTAGE,
                      gKh + kb * Dh, gKl + kb * Dh, gVh + kb * Dh, tid);
            CP_COMMIT();
        }

        const uint32_t stg = sKV + (uint32_t)(j % 3) * FSTAGE;
        const int kb0 = j * 64;
        const bool active = (q0 + 16 * w + 15) >= kb0;

        if (active) {
            float sc[8][4];
#pragma unroll
            for (int nt = 0; nt < 8; nt++)
#pragma unroll
                for (int e = 0; e < 4; e++) sc[nt][e] = 0.f;

#pragma unroll
            for (int ks = 0; ks < 8; ks++) {
#pragma unroll
                for (int p = 0; p < 4; p++) {
                    uint32_t khf[4], klf[4];
                    uint32_t ka = stg + bKoff + (uint32_t)(p * 16 * FP272) + ks * 32;
                    ldsm4(khf, ka);
                    ldsm4(klf, ka + KTILE);
#pragma unroll
                    for (int hh = 0; hh < 2; hh++) {
                        float* c = sc[p * 2 + hh];
                        uint32_t bh2[2] = {khf[hh * 2], khf[hh * 2 + 1]};
                        uint32_t bl2[2] = {klf[hh * 2], klf[hh * 2 + 1]};
                        mma_bf16(c, qh_f[ks], bh2);
                        mma_bf16(c, qh_f[ks], bl2);
                        mma_bf16(c, ql_f[ks], bh2);
                    }
                }
            }

            if (kb0 + 63 > row_lo) {
#pragma unroll
                for (int nt = 0; nt < 8; nt++) {
                    int col = kb0 + nt * 8 + 2 * (lane & 3);
                    if (col > row_lo)     sc[nt][0] = -1e30f;
                    if (col + 1 > row_lo) sc[nt][1] = -1e30f;
                    if (col > row_hi)     sc[nt][2] = -1e30f;
                    if (col + 1 > row_hi) sc[nt][3] = -1e30f;
                }
            }

            float ml0 = -1e30f, ml1 = -1e30f;
#pragma unroll
            for (int nt = 0; nt < 8; nt++) {
                ml0 = fmaxf(ml0, fmaxf(sc[nt][0], sc[nt][1]));
                ml1 = fmaxf(ml1, fmaxf(sc[nt][2], sc[nt][3]));
            }
            ml0 = fmaxf(ml0, __shfl_xor_sync(0xffffffffu, ml0, 1));
            ml0 = fmaxf(ml0, __shfl_xor_sync(0xffffffffu, ml0, 2));
            ml1 = fmaxf(ml1, __shfl_xor_sync(0xffffffffu, ml1, 1));
            ml1 = fmaxf(ml1, __shfl_xor_sync(0xffffffffu, ml1, 2));
            float mn0 = fmaxf(m0, ml0), mn1 = fmaxf(m1, ml1);
            float es0 = exp2f(m0 - mn0), es1 = exp2f(m1 - mn1);
            float ls0 = 0.f, ls1 = 0.f;
#pragma unroll
            for (int nt = 0; nt < 8; nt++) {
                sc[nt][0] = exp2f(sc[nt][0] - mn0);
                sc[nt][1] = exp2f(sc[nt][1] - mn0);
                sc[nt][2] = exp2f(sc[nt][2] - mn1);
                sc[nt][3] = exp2f(sc[nt][3] - mn1);
                ls0 += sc[nt][0] + sc[nt][1];
                ls1 += sc[nt][2] + sc[nt][3];
            }
            ls0 += __shfl_xor_sync(0xffffffffu, ls0, 1);
            ls0 += __shfl_xor_sync(0xffffffffu, ls0, 2);
            ls1 += __shfl_xor_sync(0xffffffffu, ls1, 1);
            ls1 += __shfl_xor_sync(0xffffffffu, ls1, 2);
            l0 = l0 * es0 + ls0;  m0 = mn0;
            l1 = l1 * es1 + ls1;  m1 = mn1;
#pragma unroll
            for (int dt = 0; dt < 16; dt++) {
                o[dt][0] *= es0;  o[dt][1] *= es0;
                o[dt][2] *= es1;  o[dt][3] *= es1;
            }

#pragma unroll
            for (int j2 = 0; j2 < 4; j2++) {
                uint32_t ph[4], pl[4];
                split2h(sc[2 * j2][0],     sc[2 * j2][1],     ph[0], pl[0]);
                split2h(sc[2 * j2][2],     sc[2 * j2][3],     ph[1], pl[1]);
                split2h(sc[2 * j2 + 1][0], sc[2 * j2 + 1][1], ph[2], pl[2]);
                split2h(sc[2 * j2 + 1][2], sc[2 * j2 + 1][3], ph[3], pl[3]);
#pragma unroll
                for (int dt2 = 0; dt2 < 8; dt2++) {
                    uint32_t vhf[4];
                    uint32_t va = stg + 2 * KTILE + bVoff +
                                  (uint32_t)(j2 * 16 * FP272) + (uint32_t)(dt2 * 32);
                    ldsm4t(vhf, va);
#pragma unroll
                    for (int hf = 0; hf < 2; hf++) {
                        float* c = o[dt2 * 2 + hf];
                        uint32_t bh2[2] = {vhf[hf * 2], vhf[hf * 2 + 1]};
                        mma_f16(c, ph, bh2);
                        mma_f16(c, pl, bh2);
                    }
                }
            }
        }
    }

    float inv0 = 1.f / l0, inv1 = 1.f / l1;
#pragma unroll
    for (int dt = 0; dt < 16; dt++) {
        int d = dt * 8 + 2 * (lane & 3);
        size_t o0 = (size_t)row_lo * Cdim + h * Dh + d;
        size_t o1 = (size_t)row_hi * Cdim + h * Dh + d;
        uint32_t hi0, lo0, hi1, lo1;
        split2h(o[dt][0] * inv0, o[dt][1] * inv0, hi0, lo0);
        split2h(o[dt][2] * inv1, o[dt][3] * inv1, hi1, lo1);
        *reinterpret_cast<uint32_t*>(ybhi + o0) = hi0;
        *reinterpret_cast<uint32_t*>(yblo + o0) = lo0;
        *reinterpret_cast<uint32_t*>(ybhi + o1) = hi1;
        *reinterpret_cast<uint32_t*>(yblo + o1) = lo1;
    }
}

// ---------------- launch ----------------
extern "C" void kernel_launch(void* const* d_in, const int* in_sizes, int n_in,
                              void* d_out, int out_size)
{
    const float* x    = (const float*)d_in[0];
    const float* Wq   = (const float*)d_in[1];
    const float* Wk   = (const float*)d_in[2];
    const float* Wv   = (const float*)d_in[3];
    const float* Wo   = (const float*)d_in[4];
    const float* cosb = (const float*)d_in[5];
    const float* sinb = (const float*)d_in[6];
    // d_in[7] = mask (reproduced exactly by causal structure; unused)

    float* out  = (float*)d_out;
    float* outY = out;
    float* outK = out + (size_t)Tn * Cdim;
    float* outV = outK + (size_t)NKV * Tn * Dh;

    float* tqkv;
    cudaGetSymbolAddress((void**)&tqkv, g_tqkv);
    __nv_bfloat16 *xhi, *xlo, *wahi, *walo;
    __half *ybhi, *yblo, *wohi;
    cudaGetSymbolAddress((void**)&xhi, g_xhi);
    cudaGetSymbolAddress((void**)&xlo, g_xlo);
    cudaGetSymbolAddress((void**)&wahi, g_wahi);
    cudaGetSymbolAddress((void**)&walo, g_walo);
    cudaGetSymbolAddress((void**)&ybhi, g_ybhi);
    cudaGetSymbolAddress((void**)&yblo, g_yblo);
    cudaGetSymbolAddress((void**)&wohi, g_wohi);

    cudaFuncSetAttribute(tcgemm_kernel, cudaFuncAttributeMaxDynamicSharedMemorySize,
                         G_SMEM);
    cudaFuncSetAttribute(tcgemm2_kernel, cudaFuncAttributeMaxDynamicSharedMemorySize,
                         G2_SMEM);
    cudaFuncSetAttribute(flash_mma_kernel, cudaFuncAttributeMaxDynamicSharedMemorySize,
                         F_SMEM);

    // 0. merged prep: x split + all weight transposes (ONE launch, vectorized)
    prep_kernel<<<PREP_END, 256>>>(x, Wq, Wk, Wv, Wo);

    // 1. merged QKV projection (bf16 3-MMA, one launch, N=6144)
    tcgemm_kernel<<<dim3(HDA / 128, Tn / 128), 256, G_SMEM>>>(
        xhi, xlo, wahi, walo, tqkv, HDA, Cdim);

    // 2. merged RoPE + plane conversion (q scaled by log2e for exp2 softmax)
    rope_all_kernel<<<ROPE_QBLOCKS + ROPE_KVBLOCKS, 256>>>(cosb, sinb, outK, outV);

    // 3. causal flash attention (tensor cores, 3-stage KV pipeline)
    flash_mma_kernel<<<dim3(Tn / 128, NH), 256, F_SMEM>>>(ybhi, yblo);

    // 4. output projection (fp16 2-MMA, 3-stage pipeline)
    tcgemm2_kernel<<<dim3(Cdim / 128, Tn / 128), 256, G2_SMEM>>>(
        ybhi, yblo, wohi, outY, Cdim, Cdim);
}

// round 13
// speedup vs baseline: 1.0090x; 1.0090x over previous
#include <cuda_runtime.h>
#include <cuda_bf16.h>
#include <cuda_fp16.h>
#include <cstdint>

// Problem constants
#define Tn   2048
#define Cdim 4096
#define NH   32
#define NKV  8
#define Dh   128
#define HDq  (NH*Dh)    // 4096
#define HDkv (NKV*Dh)   // 1024
#define HDA  (HDq + 2*HDkv)   // 6144 merged Q|K|V
#define LOG2E 1.4426950408889634f

// ---------------- scratch (device globals; no allocation) ----------------
__device__ __align__(256) float g_tqkv[(size_t)Tn * HDA];

__device__ __align__(256) __nv_bfloat16 g_xhi[Tn * Cdim];
__device__ __align__(256) __nv_bfloat16 g_xlo[Tn * Cdim];
__device__ __align__(256) __nv_bfloat16 g_qhi[(size_t)NH * Tn * Dh];
__device__ __align__(256) __nv_bfloat16 g_qlo[(size_t)NH * Tn * Dh];
__device__ __align__(256) __nv_bfloat16 g_khi[(size_t)NKV * Tn * Dh];
__device__ __align__(256) __nv_bfloat16 g_klo[(size_t)NKV * Tn * Dh];
__device__ __align__(256) __half       g_vh [(size_t)NKV * Tn * Dh];
__device__ __align__(256) __half       g_ybhi[Tn * Cdim];
__device__ __align__(256) __half       g_yblo[Tn * Cdim];
__device__ __align__(256) __nv_bfloat16 g_wahi[(size_t)HDA * Cdim];
__device__ __align__(256) __nv_bfloat16 g_walo[(size_t)HDA * Cdim];
__device__ __align__(256) __half       g_wohi[(size_t)Cdim * Cdim];

// ---------------- baseline-ISA helpers (sm_80+ PTX only) ----------------
__device__ __forceinline__ uint32_t smem_u32(const void* p) {
    uint32_t a;
    asm("{ .reg .u64 t; cvta.to.shared.u64 t, %1; cvt.u32.u64 %0, t; }" : "=r"(a) : "l"(p));
    return a;
}

#define CP_ASYNC16(sm, gp) \
    asm volatile("cp.async.cg.shared.global [%0], [%1], 16;" :: "r"(sm), "l"(gp) : "memory")
#define CP_COMMIT() asm volatile("cp.async.commit_group;" ::: "memory")
#define CP_WAIT(n)  asm volatile("cp.async.wait_group %0;" :: "n"(n) : "memory")

__device__ __forceinline__ void ldsm4(uint32_t* r, uint32_t addr) {
    asm volatile("ldmatrix.sync.aligned.m8n8.x4.shared.b16 {%0,%1,%2,%3}, [%4];"
        : "=r"(r[0]), "=r"(r[1]), "=r"(r[2]), "=r"(r[3]) : "r"(addr));
}
__device__ __forceinline__ void ldsm4t(uint32_t* r, uint32_t addr) {
    asm volatile("ldmatrix.sync.aligned.m8n8.x4.trans.shared.b16 {%0,%1,%2,%3}, [%4];"
        : "=r"(r[0]), "=r"(r[1]), "=r"(r[2]), "=r"(r[3]) : "r"(addr));
}

__device__ __forceinline__ void mma_bf16(float* c, const uint32_t* a, const uint32_t* b) {
    asm volatile(
        "mma.sync.aligned.m16n8k16.row.col.f32.bf16.bf16.f32 "
        "{%0,%1,%2,%3}, {%4,%5,%6,%7}, {%8,%9}, {%0,%1,%2,%3};"
        : "+f"(c[0]), "+f"(c[1]), "+f"(c[2]), "+f"(c[3])
        : "r"(a[0]), "r"(a[1]), "r"(a[2]), "r"(a[3]), "r"(b[0]), "r"(b[1]));
}
__device__ __forceinline__ void mma_f16(float* c, const uint32_t* a, const uint32_t* b) {
    asm volatile(
        "mma.sync.aligned.m16n8k16.row.col.f32.f16.f16.f32 "
        "{%0,%1,%2,%3}, {%4,%5,%6,%7}, {%8,%9}, {%0,%1,%2,%3};"
        : "+f"(c[0]), "+f"(c[1]), "+f"(c[2]), "+f"(c[3])
        : "r"(a[0]), "r"(a[1]), "r"(a[2]), "r"(a[3]), "r"(b[0]), "r"(b[1]));
}

__device__ __forceinline__ void split2h(float a, float b, uint32_t& hi, uint32_t& lo) {
    __half2 H = __floats2half2_rn(a, b);
    float ra = a - __half2float(__low2half(H));
    float rb = b - __half2float(__high2half(H));
    __half2 L = __floats2half2_rn(ra, rb);
    hi = *reinterpret_cast<uint32_t*>(&H);
    lo = *reinterpret_cast<uint32_t*>(&L);
}

// pack 4 floats -> 4 bf16 hi (uint2) + 4 bf16 lo (uint2)
__device__ __forceinline__ void pack4b(float a, float b, float c, float d,
                                       uint2& hi, uint2& lo) {
    __nv_bfloat16 h0 = __float2bfloat16(a), h1 = __float2bfloat16(b);
    __nv_bfloat16 h2 = __float2bfloat16(c), h3 = __float2bfloat16(d);
    __nv_bfloat162 H01; H01.x = h0; H01.y = h1;
    __nv_bfloat162 H23; H23.x = h2; H23.y = h3;
    __nv_bfloat162 L01, L23;
    L01.x = __float2bfloat16(a - __bfloat162float(h0));
    L01.y = __float2bfloat16(b - __bfloat162float(h1));
    L23.x = __float2bfloat16(c - __bfloat162float(h2));
    L23.y = __float2bfloat16(d - __bfloat162float(h3));
    hi.x = *reinterpret_cast<uint32_t*>(&H01);
    hi.y = *reinterpret_cast<uint32_t*>(&H23);
    lo.x = *reinterpret_cast<uint32_t*>(&L01);
    lo.y = *reinterpret_cast<uint32_t*>(&L23);
}

// ---------------- merged prep: x split + W transposes, one launch ----------------
#define PREP_X   4096
#define PREP_WQ  (PREP_X + 16384)
#define PREP_WK  (PREP_WQ + 4096)
#define PREP_WV  (PREP_WK + 4096)
#define PREP_END (PREP_WV + 16384)

__global__ void __launch_bounds__(256) prep_kernel(
    const float* __restrict__ x,
    const float* __restrict__ Wq, const float* __restrict__ Wk,
    const float* __restrict__ Wv, const float* __restrict__ Wo)
{
    __shared__ float tile[32][33];
    const int bid = blockIdx.x;
    if (bid < PREP_X) {
        int base = (bid * 256 + threadIdx.x) * 8;
#pragma unroll
        for (int half = 0; half < 2; half++) {
            int idx = base + half * 4;
            float4 v = *(const float4*)&x[idx];
            uint2 hi, lo;
            pack4b(v.x, v.y, v.z, v.w, hi, lo);
            *(uint2*)&g_xhi[idx] = hi;
            *(uint2*)&g_xlo[idx] = lo;
        }
        return;
    }
    const float* W;
    __nv_bfloat16 *Thi, *Tlo;
    int N, rel;
    bool is_half = false;
    if (bid < PREP_WQ)      { rel = bid - PREP_X;  W = Wq; N = HDq;
                              Thi = g_wahi; Tlo = g_walo; }
    else if (bid < PREP_WK) { rel = bid - PREP_WQ; W = Wk; N = HDkv;
                              Thi = g_wahi + (size_t)HDq * Cdim;
                              Tlo = g_walo + (size_t)HDq * Cdim; }
    else if (bid < PREP_WV) { rel = bid - PREP_WK; W = Wv; N = HDkv;
                              Thi = g_wahi + (size_t)(HDq + HDkv) * Cdim;
                              Tlo = g_walo + (size_t)(HDq + HDkv) * Cdim; }
    else                    { rel = bid - PREP_WV; W = Wo; N = Cdim;
                              Thi = nullptr; Tlo = nullptr; is_half = true; }

    const int ntiles = N / 32;
    int n0 = (rel % ntiles) * 32, k0 = (rel / ntiles) * 32;
    int tx = threadIdx.x & 31, ty = threadIdx.x >> 5;
#pragma unroll
    for (int j = 0; j < 4; j++)
        tile[ty + 8 * j][tx] = W[(size_t)(k0 + ty + 8 * j) * N + n0 + tx];
    __syncthreads();

    int n  = threadIdx.x >> 3;
    int kq = (threadIdx.x & 7) * 4;
    float v0 = tile[kq + 0][n], v1 = tile[kq + 1][n];
    float v2 = tile[kq + 2][n], v3 = tile[kq + 3][n];
    size_t o = (size_t)(n0 + n) * Cdim + k0 + kq;
    if (is_half) {
        __half2 a = __floats2half2_rn(v0, v1);
        __half2 b = __floats2half2_rn(v2, v3);
        uint2 pk;
        pk.x = *reinterpret_cast<uint32_t*>(&a);
        pk.y = *reinterpret_cast<uint32_t*>(&b);
        *(uint2*)&g_wohi[o] = pk;
    } else {
        uint2 hi, lo;
        pack4b(v0, v1, v2, v3, hi, lo);
        *(uint2*)&Thi[o] = hi;
        *(uint2*)&Tlo[o] = lo;
    }
}

// ---------------- GEMM common geometry ----------------
#define PITCH   80
#define T_A     10240                  // 128 rows * 80B

// ---------------- bf16 3-MMA GEMM: C = A(hi/lo) * B(hi/lo)^T ----------------
#define T_STAGE (4 * T_A)
#define G_SMEM  (2 * T_STAGE)          // 81920

__device__ __forceinline__ void g_load_pair(
    uint32_t sbase, const __nv_bfloat16* __restrict__ hi,
    const __nv_bfloat16* __restrict__ lo, int rbase, int kc, int K, int tid)
{
#pragma unroll
    for (int i = 0; i < 2; i++) {
        int s = tid + 256 * i;
        int row = s >> 2, part = s & 3;
        size_t go = (size_t)(rbase + row) * K + (size_t)kc * 32 + part * 8;
        uint32_t so = (uint32_t)(row * PITCH + part * 16);
        CP_ASYNC16(sbase + so, hi + go);
        CP_ASYNC16(sbase + T_A + so, lo + go);
    }
}

__global__ void __launch_bounds__(256, 2) tcgemm_kernel(
    const __nv_bfloat16* __restrict__ Ahi, const __nv_bfloat16* __restrict__ Alo,
    const __nv_bfloat16* __restrict__ Bhi, const __nv_bfloat16* __restrict__ Blo,
    float* __restrict__ C, int N, int K)
{
    extern __shared__ char smc[];
    const uint32_t sb0 = smem_u32(smc);
    const int tid  = threadIdx.x;
    const int lane = tid & 31;
    const int wid  = tid >> 5;
    const int wm   = wid & 1;
    const int wn   = wid >> 1;
    const int row0 = blockIdx.y * 128;
    const int col0 = blockIdx.x * 128;

    float acc[4][4][4];
#pragma unroll
    for (int m = 0; m < 4; m++)
#pragma unroll
        for (int n = 0; n < 4; n++)
#pragma unroll
            for (int e = 0; e < 4; e++) acc[m][n][e] = 0.f;

    const uint32_t a_row = (uint32_t)(wm * 64 + (lane & 15));
    const uint32_t a_kb  = (uint32_t)((lane >> 4) * 16);
    const int bmat = lane >> 3, bwin = lane & 7;
    const uint32_t b_n  = (uint32_t)(wn * 32 + bwin + (bmat >> 1) * 8);
    const uint32_t b_kb = (uint32_t)((bmat & 1) * 16);

    const int nk = K >> 5;

    g_load_pair(sb0,           Ahi, Alo, row0, 0, K, tid);
    g_load_pair(sb0 + 2 * T_A, Bhi, Blo, col0, 0, K, tid);
    CP_COMMIT();

    for (int kc = 0; kc < nk; kc++) {
        uint32_t sb = sb0 + (uint32_t)(kc & 1) * T_STAGE;
        if (kc + 1 < nk) {
            uint32_t sb2 = sb0 + (uint32_t)((kc + 1) & 1) * T_STAGE;
            g_load_pair(sb2,           Ahi, Alo, row0, kc + 1, K, tid);
            g_load_pair(sb2 + 2 * T_A, Bhi, Blo, col0, kc + 1, K, tid);
            CP_COMMIT();
            CP_WAIT(1);
        } else {
            CP_WAIT(0);
        }
        __syncthreads();

        const uint32_t aB = sb + a_row * PITCH + a_kb;
        const uint32_t bB = sb + 2 * T_A + b_n * PITCH + b_kb;

#pragma unroll
        for (int ks = 0; ks < 2; ks++) {
            uint32_t ah[4][4], al[4][4], bh[2][4], bl[2][4];
#pragma unroll
            for (int m = 0; m < 4; m++) {
                ldsm4(ah[m], aB + (uint32_t)(m * 16 * PITCH) + ks * 32);
                ldsm4(al[m], aB + T_A + (uint32_t)(m * 16 * PITCH) + ks * 32);
            }
#pragma unroll
            for (int p = 0; p < 2; p++) {
                ldsm4(bh[p], bB + (uint32_t)(p * 16 * PITCH) + ks * 32);
                ldsm4(bl[p], bB + T_A + (uint32_t)(p * 16 * PITCH) + ks * 32);
            }
#pragma unroll
            for (int m = 0; m < 4; m++)
#pragma unroll
                for (int p = 0; p < 2; p++)
#pragma unroll
                    for (int h = 0; h < 2; h++) {
                        float* c = acc[m][p * 2 + h];
                        uint32_t bhh[2] = {bh[p][h * 2], bh[p][h * 2 + 1]};
                        uint32_t bll[2] = {bl[p][h * 2], bl[p][h * 2 + 1]};
                        mma_bf16(c, ah[m], bhh);
                        mma_bf16(c, ah[m], bll);
                        mma_bf16(c, al[m], bhh);
                    }
        }
        __syncthreads();
    }

    const int g = lane >> 2, t = lane & 3;
#pragma unroll
    for (int m = 0; m < 4; m++) {
        int r0 = row0 + wm * 64 + m * 16 + g;
#pragma unroll
        for (int n = 0; n < 4; n++) {
            int c = col0 + wn * 32 + n * 8 + 2 * t;
            *(float2*)&C[(size_t)r0 * N + c] = make_float2(acc[m][n][0], acc[m][n][1]);
            *(float2*)&C[(size_t)(r0 + 8) * N + c] = make_float2(acc[m][n][2], acc[m][n][3]);
        }
    }
}

// ---------------- fp16 2-MMA GEMM (2-stage, proven form): C = (Ahi+Alo)*Bhi^T ----
#define T2_STAGE (3 * T_A)             // Ah, Al, Bh
#define G2_SMEM  (2 * T2_STAGE)        // 61440

__global__ void __launch_bounds__(256, 2) tcgemm2_kernel(
    const __half* __restrict__ Ahi, const __half* __restrict__ Alo,
    const __half* __restrict__ Bhi,
    float* __restrict__ C, int N, int K)
{
    extern __shared__ char smc[];
    const uint32_t sb0 = smem_u32(smc);
    const int tid  = threadIdx.x;
    const int lane = tid & 31;
    const int wid  = tid >> 5;
    const int wm   = wid & 1;
    const int wn   = wid >> 1;
    const int row0 = blockIdx.y * 128;
    const int col0 = blockIdx.x * 128;

    float acc[4][4][4];
#pragma unroll
    for (int m = 0; m < 4; m++)
#pragma unroll
        for (int n = 0; n < 4; n++)
#pragma unroll
            for (int e = 0; e < 4; e++) acc[m][n][e] = 0.f;

    const uint32_t a_row = (uint32_t)(wm * 64 + (lane & 15));
    const uint32_t a_kb  = (uint32_t)((lane >> 4) * 16);
    const int bmat = lane >> 3, bwin = lane & 7;
    const uint32_t b_n  = (uint32_t)(wn * 32 + bwin + (bmat >> 1) * 8);
    const uint32_t b_kb = (uint32_t)((bmat & 1) * 16);

    const int nk = K >> 5;

    auto load_stage = [&](uint32_t sb, int kc) {
#pragma unroll
        for (int i = 0; i < 2; i++) {
            int s = tid + 256 * i;
            int row = s >> 2, part = s & 3;
            size_t goA = (size_t)(row0 + row) * K + (size_t)kc * 32 + part * 8;
            size_t goB = (size_t)(col0 + row) * K + (size_t)kc * 32 + part * 8;
            uint32_t so = (uint32_t)(row * PITCH + part * 16);
            CP_ASYNC16(sb + so,           Ahi + goA);
            CP_ASYNC16(sb + T_A + so,     Alo + goA);
            CP_ASYNC16(sb + 2 * T_A + so, Bhi + goB);
        }
    };

    load_stage(sb0, 0);
    CP_COMMIT();

    for (int kc = 0; kc < nk; kc++) {
        uint32_t sb = sb0 + (uint32_t)(kc & 1) * T2_STAGE;
        if (kc + 1 < nk) {
            load_stage(sb0 + (uint32_t)((kc + 1) & 1) * T2_STAGE, kc + 1);
            CP_COMMIT();
            CP_WAIT(1);
        } else {
            CP_WAIT(0);
        }
        __syncthreads();

        const uint32_t aB = sb + a_row * PITCH + a_kb;
        const uint32_t bB = sb + 2 * T_A + b_n * PITCH + b_kb;

#pragma unroll
        for (int ks = 0; ks < 2; ks++) {
            uint32_t ah[4][4], al[4][4], bh[2][4];
#pragma unroll
            for (int m = 0; m < 4; m++) {
                ldsm4(ah[m], aB + (uint32_t)(m * 16 * PITCH) + ks * 32);
                ldsm4(al[m], aB + T_A + (uint32_t)(m * 16 * PITCH) + ks * 32);
            }
#pragma unroll
            for (int p = 0; p < 2; p++)
                ldsm4(bh[p], bB + (uint32_t)(p * 16 * PITCH) + ks * 32);
#pragma unroll
            for (int m = 0; m < 4; m++)
#pragma unroll
                for (int p = 0; p < 2; p++)
#pragma unroll
                    for (int h = 0; h < 2; h++) {
                        float* c = acc[m][p * 2 + h];
                        uint32_t bhh[2] = {bh[p][h * 2], bh[p][h * 2 + 1]};
                        mma_f16(c, ah[m], bhh);
                        mma_f16(c, al[m], bhh);
                    }
        }
        __syncthreads();
    }

    const int g = lane >> 2, t = lane & 3;
#pragma unroll
    for (int m = 0; m < 4; m++) {
        int r0 = row0 + wm * 64 + m * 16 + g;
#pragma unroll
        for (int n = 0; n < 4; n++) {
            int c = col0 + wn * 32 + n * 8 + 2 * t;
            *(float2*)&C[(size_t)r0 * N + c] = make_float2(acc[m][n][0], acc[m][n][1]);
            *(float2*)&C[(size_t)(r0 + 8) * N + c] = make_float2(acc[m][n][2], acc[m][n][3]);
        }
    }
}

// ---------------- merged RoPE (vectorized): q part + kv part, one launch --------
// q additionally scaled by log2(e) so flash can use exp2f.
#define ROPE_QBLOCKS ((NH * Tn * 16) / 256)     // 4096
#define ROPE_KVBLOCKS ((NKV * Tn * 16) / 256)   // 1024

__global__ void __launch_bounds__(256) rope_all_kernel(
    const float* __restrict__ cosb, const float* __restrict__ sinb,
    float* __restrict__ outK, float* __restrict__ outV)
{
    int bid = blockIdx.x;
    if (bid < ROPE_QBLOCKS) {
        int idx = bid * 256 + threadIdx.x;
        int d = (idx & 15) * 4;
        int t = (idx >> 4) & (Tn - 1);
        int h = idx >> 15;
        const float* src = g_tqkv + (size_t)t * HDA + h * Dh;
        float4 u1 = *(const float4*)(src + d);
        float4 u2 = *(const float4*)(src + d + 64);
        float4 c1 = *(const float4*)&cosb[t * Dh + d];
        float4 s1 = *(const float4*)&sinb[t * Dh + d];
        float4 c2 = *(const float4*)&cosb[t * Dh + d + 64];
        float4 s2 = *(const float4*)&sinb[t * Dh + d + 64];
        float4 y1 = make_float4((u1.x * c1.x - u2.x * s1.x) * LOG2E,
                                (u1.y * c1.y - u2.y * s1.y) * LOG2E,
                                (u1.z * c1.z - u2.z * s1.z) * LOG2E,
                                (u1.w * c1.w - u2.w * s1.w) * LOG2E);
        float4 y2 = make_float4((u2.x * c2.x + u1.x * s2.x) * LOG2E,
                                (u2.y * c2.y + u1.y * s2.y) * LOG2E,
                                (u2.z * c2.z + u1.z * s2.z) * LOG2E,
                                (u2.w * c2.w + u1.w * s2.w) * LOG2E);
        size_t o = ((size_t)h * Tn + t) * Dh + d;
        uint2 hi1, lo1, hi2, lo2;
        pack4b(y1.x, y1.y, y1.z, y1.w, hi1, lo1);
        pack4b(y2.x, y2.y, y2.z, y2.w, hi2, lo2);
        *(uint2*)&g_qhi[o]      = hi1;
        *(uint2*)&g_qlo[o]      = lo1;
        *(uint2*)&g_qhi[o + 64] = hi2;
        *(uint2*)&g_qlo[o + 64] = lo2;
    } else {
        int idx = (bid - ROPE_QBLOCKS) * 256 + threadIdx.x;
        int d  = (idx & 15) * 4;
        int t  = (idx >> 4) & (Tn - 1);
        int kh = idx >> 15;
        const float* srck = g_tqkv + (size_t)t * HDA + HDq + kh * Dh;
        float4 u1 = *(const float4*)(srck + d);
        float4 u2 = *(const float4*)(srck + d + 64);
        float4 c1 = *(const float4*)&cosb[t * Dh + d];
        float4 s1 = *(const float4*)&sinb[t * Dh + d];
        float4 c2 = *(const float4*)&cosb[t * Dh + d + 64];
        float4 s2 = *(const float4*)&sinb[t * Dh + d + 64];
        float4 y1 = make_float4(u1.x * c1.x - u2.x * s1.x, u1.y * c1.y - u2.y * s1.y,
                                u1.z * c1.z - u2.z * s1.z, u1.w * c1.w - u2.w * s1.w);
        float4 y2 = make_float4(u2.x * c2.x + u1.x * s2.x, u2.y * c2.y + u1.y * s2.y,
                                u2.z * c2.z + u1.z * s2.z, u2.w * c2.w + u1.w * s2.w);
        size_t o = ((size_t)kh * Tn + t) * Dh + d;
        *(float4*)(outK + o)      = y1;
        *(float4*)(outK + o + 64) = y2;
        uint2 hi1, lo1, hi2, lo2;
        pack4b(y1.x, y1.y, y1.z, y1.w, hi1, lo1);
        pack4b(y2.x, y2.y, y2.z, y2.w, hi2, lo2);
        *(uint2*)&g_khi[o]      = hi1;
        *(uint2*)&g_klo[o]      = lo1;
        *(uint2*)&g_khi[o + 64] = hi2;
        *(uint2*)&g_klo[o + 64] = lo2;
        const float* srcv = srck + HDkv;
        float4 v1 = *(const float4*)(srcv + d);
        float4 v2 = *(const float4*)(srcv + d + 64);
        *(float4*)(outV + o)      = v1;
        *(float4*)(outV + o + 64) = v2;
        __half2 a1 = __floats2half2_rn(v1.x, v1.y);
        __half2 b1 = __floats2half2_rn(v1.z, v1.w);
        __half2 a2 = __floats2half2_rn(v2.x, v2.y);
        __half2 b2 = __floats2half2_rn(v2.z, v2.w);
        uint2 p1, p2;
        p1.x = *reinterpret_cast<uint32_t*>(&a1);
        p1.y = *reinterpret_cast<uint32_t*>(&b1);
        p2.x = *reinterpret_cast<uint32_t*>(&a2);
        p2.y = *reinterpret_cast<uint32_t*>(&b2);
        *(uint2*)&g_vh[o]      = p1;
        *(uint2*)&g_vh[o + 64] = p2;
    }
}

// ---------------- flash attention (QK: bf16 3-MMA, PV: fp16 2-MMA) ----------------
// q pre-scaled by log2(e) -> softmax uses exp2f.
#define FP272   272
#define QTILE   (128 * FP272)          // 34816
#define KTILE   (64 * FP272)           // 17408
#define FSTAGE  (3 * KTILE)            // Kh, Kl, Vh = 52224
#define F_SMEM  (2 * QTILE + 3 * FSTAGE)  // 226304

__device__ __forceinline__ void f_load_kv(
    uint32_t st, const __nv_bfloat16* __restrict__ kh,
    const __nv_bfloat16* __restrict__ kl, const __half* __restrict__ vh, int tid)
{
#pragma unroll
    for (int i = 0; i < 4; i++) {
        int s = tid + 256 * i;
        int r = s >> 4, c = s & 15;
        uint32_t so = (uint32_t)(r * FP272 + c * 16);
        size_t go = (size_t)r * Dh + c * 8;
        CP_ASYNC16(st + so,             kh + go);
        CP_ASYNC16(st + KTILE + so,     kl + go);
        CP_ASYNC16(st + 2 * KTILE + so, vh + go);
    }
}

__global__ void __launch_bounds__(256) flash_mma_kernel(
    __half* __restrict__ ybhi, __half* __restrict__ yblo)
{
    extern __shared__ char smc[];
    const uint32_t sb = smem_u32(smc);
    const int tid = threadIdx.x, lane = tid & 31, w = tid >> 5;
    const int h  = blockIdx.y;
    const int qi = (int)gridDim.x - 1 - (int)blockIdx.x;   // big tiles first
    const int q0 = qi * 128;
    const int kvh = h >> 2;
    const int nb = 2 * qi + 2;

    const uint32_t sQh = sb, sQl = sb + QTILE;
    const uint32_t sKV = sb + 2 * QTILE;

    const uint32_t aQoff = (uint32_t)((16 * w + (lane & 15)) * FP272 + (lane >> 4) * 16);
    const int bmat = lane >> 3, bwin = lane & 7;
    const uint32_t bKoff = (uint32_t)((bwin + ((bmat >> 1) << 3)) * FP272 + ((bmat & 1) << 4));
    const uint32_t bVoff = (uint32_t)((lane & 15) * FP272 + ((lane >> 4) << 4));

    const __nv_bfloat16* gKh = g_khi + (size_t)kvh * Tn * Dh;
    const __nv_bfloat16* gKl = g_klo + (size_t)kvh * Tn * Dh;
    const __half*        gVh = g_vh  + (size_t)kvh * Tn * Dh;

    {
        const __nv_bfloat16* gqh = g_qhi + ((size_t)h * Tn + q0) * Dh;
        const __nv_bfloat16* gql = g_qlo + ((size_t)h * Tn + q0) * Dh;
#pragma unroll
        for (int i = 0; i < 8; i++) {
            int s = tid + 256 * i;
            int r = s >> 4, c = s & 15;
            uint32_t so = (uint32_t)(r * FP272 + c * 16);
            size_t go = (size_t)r * Dh + c * 8;
            CP_ASYNC16(sQh + so, gqh + go);
            CP_ASYNC16(sQl + so, gql + go);
        }
        f_load_kv(sKV, gKh, gKl, gVh, tid);
        CP_COMMIT();
        f_load_kv(sKV + FSTAGE, gKh + (size_t)64 * Dh, gKl + (size_t)64 * Dh,
                  gVh + (size_t)64 * Dh, tid);
        CP_COMMIT();
    }

    CP_WAIT(1);
    __syncthreads();
    uint32_t qh_f[8][4], ql_f[8][4];
#pragma unroll
    for (int ks = 0; ks < 8; ks++) {
        ldsm4(qh_f[ks], sQh + aQoff + ks * 32);
        ldsm4(ql_f[ks], sQl + aQoff + ks * 32);
    }

    float o[16][4];
#pragma unroll
    for (int dt = 0; dt < 16; dt++)
#pragma unroll
        for (int e = 0; e < 4; e++) o[dt][e] = 0.f;
    float m0 = -1e30f, m1 = -1e30f, l0 = 0.f, l1 = 0.f;

    const int row_lo = q0 + 16 * w + (lane >> 2);
    const int row_hi = row_lo + 8;

    for (int j = 0; j < nb; j++) {
        if (j > 0) {
            if (j + 1 < nb) CP_WAIT(1); else CP_WAIT(0);
            __syncthreads();
        }
        if (j + 2 < nb) {
            size_t kb = (size_t)(j + 2) * 64;
            f_load_kv(sKV + (uint32_t)((j + 2) % 3) * FSTAGE,
                      gKh + kb * Dh, gKl + kb * Dh, gVh + kb * Dh, tid);
            CP_COMMIT();
        }

        const uint32_t stg = sKV + (uint32_t)(j % 3) * FSTAGE;
        const int kb0 = j * 64;
        const bool active = (q0 + 16 * w + 15) >= kb0;

        if (active) {
            float sc[8][4];
#pragma unroll
            for (int nt = 0; nt < 8; nt++)
#pragma unroll
                for (int e = 0; e < 4; e++) sc[nt][e] = 0.f;

#pragma unroll
            for (int ks = 0; ks < 8; ks++) {
#pragma unroll
                for (int p = 0; p < 4; p++) {
                    uint32_t khf[4], klf[4];
                    uint32_t ka = stg + bKoff + (uint32_t)(p * 16 * FP272) + ks * 32;
                    ldsm4(khf, ka);
                    ldsm4(klf, ka + KTILE);
#pragma unroll
                    for (int hh = 0; hh < 2; hh++) {
                        float* c = sc[p * 2 + hh];
                        uint32_t bh2[2] = {khf[hh * 2], khf[hh * 2 + 1]};
                        uint32_t bl2[2] = {klf[hh * 2], klf[hh * 2 + 1]};
                        mma_bf16(c, qh_f[ks], bh2);
                        mma_bf16(c, qh_f[ks], bl2);
                        mma_bf16(c, ql_f[ks], bh2);
                    }
                }
            }

            if (kb0 + 63 > row_lo) {
#pragma unroll
                for (int nt = 0; nt < 8; nt++) {
                    int col = kb0 + nt * 8 + 2 * (lane & 3);
                    if (col > row_lo)     sc[nt][0] = -1e30f;
                    if (col + 1 > row_lo) sc[nt][1] = -1e30f;
                    if (col > row_hi)     sc[nt][2] = -1e30f;
                    if (col + 1 > row_hi) sc[nt][3] = -1e30f;
                }
            }

            float ml0 = -1e30f, ml1 = -1e30f;
#pragma unroll
            for (int nt = 0; nt < 8; nt++) {
                ml0 = fmaxf(ml0, fmaxf(sc[nt][0], sc[nt][1]));
                ml1 = fmaxf(ml1, fmaxf(sc[nt][2], sc[nt][3]));
            }
            ml0 = fmaxf(ml0, __shfl_xor_sync(0xffffffffu, ml0, 1));
            ml0 = fmaxf(ml0, __shfl_xor_sync(0xffffffffu, ml0, 2));
            ml1 = fmaxf(ml1, __shfl_xor_sync(0xffffffffu, ml1, 1));
            ml1 = fmaxf(ml1, __shfl_xor_sync(0xffffffffu, ml1, 2));
            float mn0 = fmaxf(m0, ml0), mn1 = fmaxf(m1, ml1);
            float es0 = exp2f(m0 - mn0), es1 = exp2f(m1 - mn1);
            float ls0 = 0.f, ls1 = 0.f;
#pragma unroll
            for (int nt = 0; nt < 8; nt++) {
                sc[nt][0] = exp2f(sc[nt][0] - mn0);
                sc[nt][1] = exp2f(sc[nt][1] - mn0);
                sc[nt][2] = exp2f(sc[nt][2] - mn1);
                sc[nt][3] = exp2f(sc[nt][3] - mn1);
                ls0 += sc[nt][0] + sc[nt][1];
                ls1 += sc[nt][2] + sc[nt][3];
            }
            ls0 += __shfl_xor_sync(0xffffffffu, ls0, 1);
            ls0 += __shfl_xor_sync(0xffffffffu, ls0, 2);
            ls1 += __shfl_xor_sync(0xffffffffu, ls1, 1);
            ls1 += __shfl_xor_sync(0xffffffffu, ls1, 2);
            l0 = l0 * es0 + ls0;  m0 = mn0;
            l1 = l1 * es1 + ls1;  m1 = mn1;
#pragma unroll
            for (int dt = 0; dt < 16; dt++) {
                o[dt][0] *= es0;  o[dt][1] *= es0;
                o[dt][2] *= es1;  o[dt][3] *= es1;
            }

#pragma unroll
            for (int j2 = 0; j2 < 4; j2++) {
                uint32_t ph[4], pl[4];
                split2h(sc[2 * j2][0],     sc[2 * j2][1],     ph[0], pl[0]);
                split2h(sc[2 * j2][2],     sc[2 * j2][3],     ph[1], pl[1]);
                split2h(sc[2 * j2 + 1][0], sc[2 * j2 + 1][1], ph[2], pl[2]);
                split2h(sc[2 * j2 + 1][2], sc[2 * j2 + 1][3], ph[3], pl[3]);
#pragma unroll
                for (int dt2 = 0; dt2 < 8; dt2++) {
                    uint32_t vhf[4];
                    uint32_t va = stg + 2 * KTILE + bVoff +
                                  (uint32_t)(j2 * 16 * FP272) + (uint32_t)(dt2 * 32);
                    ldsm4t(vhf, va);
#pragma unroll
                    for (int hf = 0; hf < 2; hf++) {
                        float* c = o[dt2 * 2 + hf];
                        uint32_t bh2[2] = {vhf[hf * 2], vhf[hf * 2 + 1]};
                        mma_f16(c, ph, bh2);
                        mma_f16(c, pl, bh2);
                    }
                }
            }
        }
    }

    float inv0 = 1.f / l0, inv1 = 1.f / l1;
#pragma unroll
    for (int dt = 0; dt < 16; dt++) {
        int d = dt * 8 + 2 * (lane & 3);
        size_t o0 = (size_t)row_lo * Cdim + h * Dh + d;
        size_t o1 = (size_t)row_hi * Cdim + h * Dh + d;
        uint32_t hi0, lo0, hi1, lo1;
        split2h(o[dt][0] * inv0, o[dt][1] * inv0, hi0, lo0);
        split2h(o[dt][2] * inv1, o[dt][3] * inv1, hi1, lo1);
        *reinterpret_cast<uint32_t*>(ybhi + o0) = hi0;
        *reinterpret_cast<uint32_t*>(yblo + o0) = lo0;
        *reinterpret_cast<uint32_t*>(ybhi + o1) = hi1;
        *reinterpret_cast<uint32_t*>(yblo + o1) = lo1;
    }
}

// ---------------- launch ----------------
extern "C" void kernel_launch(void* const* d_in, const int* in_sizes, int n_in,
                              void* d_out, int out_size)
{
    const float* x    = (const float*)d_in[0];
    const float* Wq   = (const float*)d_in[1];
    const float* Wk   = (const float*)d_in[2];
    const float* Wv   = (const float*)d_in[3];
    const float* Wo   = (const float*)d_in[4];
    const float* cosb = (const float*)d_in[5];
    const float* sinb = (const float*)d_in[6];
    // d_in[7] = mask (reproduced exactly by causal structure; unused)

    float* out  = (float*)d_out;
    float* outY = out;
    float* outK = out + (size_t)Tn * Cdim;
    float* outV = outK + (size_t)NKV * Tn * Dh;

    float* tqkv;
    cudaGetSymbolAddress((void**)&tqkv, g_tqkv);
    __nv_bfloat16 *xhi, *xlo, *wahi, *walo;
    __half *ybhi, *yblo, *wohi;
    cudaGetSymbolAddress((void**)&xhi, g_xhi);
    cudaGetSymbolAddress((void**)&xlo, g_xlo);
    cudaGetSymbolAddress((void**)&wahi, g_wahi);
    cudaGetSymbolAddress((void**)&walo, g_walo);
    cudaGetSymbolAddress((void**)&ybhi, g_ybhi);
    cudaGetSymbolAddress((void**)&yblo, g_yblo);
    cudaGetSymbolAddress((void**)&wohi, g_wohi);

    cudaFuncSetAttribute(tcgemm_kernel, cudaFuncAttributeMaxDynamicSharedMemorySize,
                         G_SMEM);
    cudaFuncSetAttribute(tcgemm2_kernel, cudaFuncAttributeMaxDynamicSharedMemorySize,
                         G2_SMEM);
    cudaFuncSetAttribute(flash_mma_kernel, cudaFuncAttributeMaxDynamicSharedMemorySize,
                         F_SMEM);

    // 0. merged prep: x split + all weight transposes (ONE launch, vectorized)
    prep_kernel<<<PREP_END, 256>>>(x, Wq, Wk, Wv, Wo);

    // 1. merged QKV projection (bf16 3-MMA, one launch, N=6144)
    tcgemm_kernel<<<dim3(HDA / 128, Tn / 128), 256, G_SMEM>>>(
        xhi, xlo, wahi, walo, tqkv, HDA, Cdim);

    // 2. merged RoPE + plane conversion (q scaled by log2e for exp2 softmax)
    rope_all_kernel<<<ROPE_QBLOCKS + ROPE_KVBLOCKS, 256>>>(cosb, sinb, outK, outV);

    // 3. causal flash attention (tensor cores, 3-stage KV pipeline)
    flash_mma_kernel<<<dim3(Tn / 128, NH), 256, F_SMEM>>>(ybhi, yblo);

    // 4. output projection (fp16 2-MMA, 2-stage proven pipeline)
    tcgemm2_kernel<<<dim3(Cdim / 128, Tn / 128), 256, G2_SMEM>>>(
        ybhi, yblo, wohi, outY, Cdim, Cdim);
}

// round 14
// speedup vs baseline: 1.1169x; 1.1069x over previous
#include <cuda_runtime.h>
#include <cuda_bf16.h>
#include <cuda_fp16.h>
#include <cstdint>

// Problem constants
#define Tn   2048
#define Cdim 4096
#define NH   32
#define NKV  8
#define Dh   128
#define HDq  (NH*Dh)    // 4096
#define HDkv (NKV*Dh)   // 1024
#define HDA  (HDq + 2*HDkv)   // 6144 merged Q|K|V
#define LOG2E 1.4426950408889634f

// ---------------- scratch (device globals; no allocation) ----------------
__device__ __align__(256) float g_tqkv[(size_t)Tn * HDA];

__device__ __align__(256) __nv_bfloat16 g_xhi[Tn * Cdim];
__device__ __align__(256) __nv_bfloat16 g_xlo[Tn * Cdim];
__device__ __align__(256) __nv_bfloat16 g_qhi[(size_t)NH * Tn * Dh];
__device__ __align__(256) __nv_bfloat16 g_qlo[(size_t)NH * Tn * Dh];
__device__ __align__(256) __nv_bfloat16 g_khi[(size_t)NKV * Tn * Dh];
__device__ __align__(256) __nv_bfloat16 g_klo[(size_t)NKV * Tn * Dh];
__device__ __align__(256) __half       g_vh [(size_t)NKV * Tn * Dh];
__device__ __align__(256) __half       g_ybhi[Tn * Cdim];
__device__ __align__(256) __nv_bfloat16 g_wahi[(size_t)HDA * Cdim];
__device__ __align__(256) __nv_bfloat16 g_walo[(size_t)HDA * Cdim];
__device__ __align__(256) __half       g_wohi[(size_t)Cdim * Cdim];

// ---------------- baseline-ISA helpers (sm_80+ PTX only) ----------------
__device__ __forceinline__ uint32_t smem_u32(const void* p) {
    uint32_t a;
    asm("{ .reg .u64 t; cvta.to.shared.u64 t, %1; cvt.u32.u64 %0, t; }" : "=r"(a) : "l"(p));
    return a;
}

#define CP_ASYNC16(sm, gp) \
    asm volatile("cp.async.cg.shared.global [%0], [%1], 16;" :: "r"(sm), "l"(gp) : "memory")
#define CP_COMMIT() asm volatile("cp.async.commit_group;" ::: "memory")
#define CP_WAIT(n)  asm volatile("cp.async.wait_group %0;" :: "n"(n) : "memory")

__device__ __forceinline__ void ldsm4(uint32_t* r, uint32_t addr) {
    asm volatile("ldmatrix.sync.aligned.m8n8.x4.shared.b16 {%0,%1,%2,%3}, [%4];"
        : "=r"(r[0]), "=r"(r[1]), "=r"(r[2]), "=r"(r[3]) : "r"(addr));
}
__device__ __forceinline__ void ldsm4t(uint32_t* r, uint32_t addr) {
    asm volatile("ldmatrix.sync.aligned.m8n8.x4.trans.shared.b16 {%0,%1,%2,%3}, [%4];"
        : "=r"(r[0]), "=r"(r[1]), "=r"(r[2]), "=r"(r[3]) : "r"(addr));
}

__device__ __forceinline__ void mma_bf16(float* c, const uint32_t* a, const uint32_t* b) {
    asm volatile(
        "mma.sync.aligned.m16n8k16.row.col.f32.bf16.bf16.f32 "
        "{%0,%1,%2,%3}, {%4,%5,%6,%7}, {%8,%9}, {%0,%1,%2,%3};"
        : "+f"(c[0]), "+f"(c[1]), "+f"(c[2]), "+f"(c[3])
        : "r"(a[0]), "r"(a[1]), "r"(a[2]), "r"(a[3]), "r"(b[0]), "r"(b[1]));
}
__device__ __forceinline__ void mma_f16(float* c, const uint32_t* a, const uint32_t* b) {
    asm volatile(
        "mma.sync.aligned.m16n8k16.row.col.f32.f16.f16.f32 "
        "{%0,%1,%2,%3}, {%4,%5,%6,%7}, {%8,%9}, {%0,%1,%2,%3};"
        : "+f"(c[0]), "+f"(c[1]), "+f"(c[2]), "+f"(c[3])
        : "r"(a[0]), "r"(a[1]), "r"(a[2]), "r"(a[3]), "r"(b[0]), "r"(b[1]));
}

__device__ __forceinline__ void split2h(float a, float b, uint32_t& hi, uint32_t& lo) {
    __half2 H = __floats2half2_rn(a, b);
    float ra = a - __half2float(__low2half(H));
    float rb = b - __half2float(__high2half(H));
    __half2 L = __floats2half2_rn(ra, rb);
    hi = *reinterpret_cast<uint32_t*>(&H);
    lo = *reinterpret_cast<uint32_t*>(&L);
}

// pack 4 floats -> 4 bf16 hi (uint2) + 4 bf16 lo (uint2)
__device__ __forceinline__ void pack4b(float a, float b, float c, float d,
                                       uint2& hi, uint2& lo) {
    __nv_bfloat16 h0 = __float2bfloat16(a), h1 = __float2bfloat16(b);
    __nv_bfloat16 h2 = __float2bfloat16(c), h3 = __float2bfloat16(d);
    __nv_bfloat162 H01; H01.x = h0; H01.y = h1;
    __nv_bfloat162 H23; H23.x = h2; H23.y = h3;
    __nv_bfloat162 L01, L23;
    L01.x = __float2bfloat16(a - __bfloat162float(h0));
    L01.y = __float2bfloat16(b - __bfloat162float(h1));
    L23.x = __float2bfloat16(c - __bfloat162float(h2));
    L23.y = __float2bfloat16(d - __bfloat162float(h3));
    hi.x = *reinterpret_cast<uint32_t*>(&H01);
    hi.y = *reinterpret_cast<uint32_t*>(&H23);
    lo.x = *reinterpret_cast<uint32_t*>(&L01);
    lo.y = *reinterpret_cast<uint32_t*>(&L23);
}

// ---------------- merged prep: x split + W transposes, one launch ----------------
#define PREP_X   4096
#define PREP_WQ  (PREP_X + 16384)
#define PREP_WK  (PREP_WQ + 4096)
#define PREP_WV  (PREP_WK + 4096)
#define PREP_END (PREP_WV + 16384)

__global__ void __launch_bounds__(256) prep_kernel(
    const float* __restrict__ x,
    const float* __restrict__ Wq, const float* __restrict__ Wk,
    const float* __restrict__ Wv, const float* __restrict__ Wo)
{
    __shared__ float tile[32][33];
    const int bid = blockIdx.x;
    if (bid < PREP_X) {
        int base = (bid * 256 + threadIdx.x) * 8;
#pragma unroll
        for (int half = 0; half < 2; half++) {
            int idx = base + half * 4;
            float4 v = *(const float4*)&x[idx];
            uint2 hi, lo;
            pack4b(v.x, v.y, v.z, v.w, hi, lo);
            *(uint2*)&g_xhi[idx] = hi;
            *(uint2*)&g_xlo[idx] = lo;
        }
        return;
    }
    const float* W;
    __nv_bfloat16 *Thi, *Tlo;
    int N, rel;
    bool is_half = false;
    if (bid < PREP_WQ)      { rel = bid - PREP_X;  W = Wq; N = HDq;
                              Thi = g_wahi; Tlo = g_walo; }
    else if (bid < PREP_WK) { rel = bid - PREP_WQ; W = Wk; N = HDkv;
                              Thi = g_wahi + (size_t)HDq * Cdim;
                              Tlo = g_walo + (size_t)HDq * Cdim; }
    else if (bid < PREP_WV) { rel = bid - PREP_WK; W = Wv; N = HDkv;
                              Thi = g_wahi + (size_t)(HDq + HDkv) * Cdim;
                              Tlo = g_walo + (size_t)(HDq + HDkv) * Cdim; }
    else                    { rel = bid - PREP_WV; W = Wo; N = Cdim;
                              Thi = nullptr; Tlo = nullptr; is_half = true; }

    const int ntiles = N / 32;
    int n0 = (rel % ntiles) * 32, k0 = (rel / ntiles) * 32;
    int tx = threadIdx.x & 31, ty = threadIdx.x >> 5;
#pragma unroll
    for (int j = 0; j < 4; j++)
        tile[ty + 8 * j][tx] = W[(size_t)(k0 + ty + 8 * j) * N + n0 + tx];
    __syncthreads();

    int n  = threadIdx.x >> 3;
    int kq = (threadIdx.x & 7) * 4;
    float v0 = tile[kq + 0][n], v1 = tile[kq + 1][n];
    float v2 = tile[kq + 2][n], v3 = tile[kq + 3][n];
    size_t o = (size_t)(n0 + n) * Cdim + k0 + kq;
    if (is_half) {
        __half2 a = __floats2half2_rn(v0, v1);
        __half2 b = __floats2half2_rn(v2, v3);
        uint2 pk;
        pk.x = *reinterpret_cast<uint32_t*>(&a);
        pk.y = *reinterpret_cast<uint32_t*>(&b);
        *(uint2*)&g_wohi[o] = pk;
    } else {
        uint2 hi, lo;
        pack4b(v0, v1, v2, v3, hi, lo);
        *(uint2*)&Thi[o] = hi;
        *(uint2*)&Tlo[o] = lo;
    }
}

// ---------------- GEMM common geometry ----------------
#define PITCH   80
#define T_A     10240                  // 128 rows * 80B

// ---------------- bf16 3-MMA GEMM: C = A(hi/lo) * B(hi/lo)^T ----------------
#define T_STAGE (4 * T_A)
#define G_SMEM  (2 * T_STAGE)          // 81920

__device__ __forceinline__ void g_load_pair(
    uint32_t sbase, const __nv_bfloat16* __restrict__ hi,
    const __nv_bfloat16* __restrict__ lo, int rbase, int kc, int K, int tid)
{
#pragma unroll
    for (int i = 0; i < 2; i++) {
        int s = tid + 256 * i;
        int row = s >> 2, part = s & 3;
        size_t go = (size_t)(rbase + row) * K + (size_t)kc * 32 + part * 8;
        uint32_t so = (uint32_t)(row * PITCH + part * 16);
        CP_ASYNC16(sbase + so, hi + go);
        CP_ASYNC16(sbase + T_A + so, lo + go);
    }
}

__global__ void __launch_bounds__(256, 2) tcgemm_kernel(
    const __nv_bfloat16* __restrict__ Ahi, const __nv_bfloat16* __restrict__ Alo,
    const __nv_bfloat16* __restrict__ Bhi, const __nv_bfloat16* __restrict__ Blo,
    float* __restrict__ C, int N, int K)
{
    extern __shared__ char smc[];
    const uint32_t sb0 = smem_u32(smc);
    const int tid  = threadIdx.x;
    const int lane = tid & 31;
    const int wid  = tid >> 5;
    const int wm   = wid & 1;
    const int wn   = wid >> 1;
    const int row0 = blockIdx.y * 128;
    const int col0 = blockIdx.x * 128;

    float acc[4][4][4];
#pragma unroll
    for (int m = 0; m < 4; m++)
#pragma unroll
        for (int n = 0; n < 4; n++)
#pragma unroll
            for (int e = 0; e < 4; e++) acc[m][n][e] = 0.f;

    const uint32_t a_row = (uint32_t)(wm * 64 + (lane & 15));
    const uint32_t a_kb  = (uint32_t)((lane >> 4) * 16);
    const int bmat = lane >> 3, bwin = lane & 7;
    const uint32_t b_n  = (uint32_t)(wn * 32 + bwin + (bmat >> 1) * 8);
    const uint32_t b_kb = (uint32_t)((bmat & 1) * 16);

    const int nk = K >> 5;

    g_load_pair(sb0,           Ahi, Alo, row0, 0, K, tid);
    g_load_pair(sb0 + 2 * T_A, Bhi, Blo, col0, 0, K, tid);
    CP_COMMIT();

    for (int kc = 0; kc < nk; kc++) {
        uint32_t sb = sb0 + (uint32_t)(kc & 1) * T_STAGE;
        if (kc + 1 < nk) {
            uint32_t sb2 = sb0 + (uint32_t)((kc + 1) & 1) * T_STAGE;
            g_load_pair(sb2,           Ahi, Alo, row0, kc + 1, K, tid);
            g_load_pair(sb2 + 2 * T_A, Bhi, Blo, col0, kc + 1, K, tid);
            CP_COMMIT();
            CP_WAIT(1);
        } else {
            CP_WAIT(0);
        }
        __syncthreads();

        const uint32_t aB = sb + a_row * PITCH + a_kb;
        const uint32_t bB = sb + 2 * T_A + b_n * PITCH + b_kb;

#pragma unroll
        for (int ks = 0; ks < 2; ks++) {
            uint32_t ah[4][4], al[4][4], bh[2][4], bl[2][4];
#pragma unroll
            for (int m = 0; m < 4; m++) {
                ldsm4(ah[m], aB + (uint32_t)(m * 16 * PITCH) + ks * 32);
                ldsm4(al[m], aB + T_A + (uint32_t)(m * 16 * PITCH) + ks * 32);
            }
#pragma unroll
            for (int p = 0; p < 2; p++) {
                ldsm4(bh[p], bB + (uint32_t)(p * 16 * PITCH) + ks * 32);
                ldsm4(bl[p], bB + T_A + (uint32_t)(p * 16 * PITCH) + ks * 32);
            }
#pragma unroll
            for (int m = 0; m < 4; m++)
#pragma unroll
                for (int p = 0; p < 2; p++)
#pragma unroll
                    for (int h = 0; h < 2; h++) {
                        float* c = acc[m][p * 2 + h];
                        uint32_t bhh[2] = {bh[p][h * 2], bh[p][h * 2 + 1]};
                        uint32_t bll[2] = {bl[p][h * 2], bl[p][h * 2 + 1]};
                        mma_bf16(c, ah[m], bhh);
                        mma_bf16(c, ah[m], bll);
                        mma_bf16(c, al[m], bhh);
                    }
        }
        __syncthreads();
    }

    const int g = lane >> 2, t = lane & 3;
#pragma unroll
    for (int m = 0; m < 4; m++) {
        int r0 = row0 + wm * 64 + m * 16 + g;
#pragma unroll
        for (int n = 0; n < 4; n++) {
            int c = col0 + wn * 32 + n * 8 + 2 * t;
            *(float2*)&C[(size_t)r0 * N + c] = make_float2(acc[m][n][0], acc[m][n][1]);
            *(float2*)&C[(size_t)(r0 + 8) * N + c] = make_float2(acc[m][n][2], acc[m][n][3]);
        }
    }
}

// ---------------- fp16 1-MMA GEMM (2-stage): C = Ahi * Bhi^T ----------------
#define T3_STAGE (2 * T_A)             // Ah, Bh = 20480
#define G3_SMEM  (2 * T3_STAGE)        // 40960

__global__ void __launch_bounds__(256, 2) tcgemm3_kernel(
    const __half* __restrict__ Ahi, const __half* __restrict__ Bhi,
    float* __restrict__ C, int N, int K)
{
    extern __shared__ char smc[];
    const uint32_t sb0 = smem_u32(smc);
    const int tid  = threadIdx.x;
    const int lane = tid & 31;
    const int wid  = tid >> 5;
    const int wm   = wid & 1;
    const int wn   = wid >> 1;
    const int row0 = blockIdx.y * 128;
    const int col0 = blockIdx.x * 128;

    float acc[4][4][4];
#pragma unroll
    for (int m = 0; m < 4; m++)
#pragma unroll
        for (int n = 0; n < 4; n++)
#pragma unroll
            for (int e = 0; e < 4; e++) acc[m][n][e] = 0.f;

    const uint32_t a_row = (uint32_t)(wm * 64 + (lane & 15));
    const uint32_t a_kb  = (uint32_t)((lane >> 4) * 16);
    const int bmat = lane >> 3, bwin = lane & 7;
    const uint32_t b_n  = (uint32_t)(wn * 32 + bwin + (bmat >> 1) * 8);
    const uint32_t b_kb = (uint32_t)((bmat & 1) * 16);

    const int nk = K >> 5;

    auto load_stage = [&](uint32_t sb, int kc) {
#pragma unroll
        for (int i = 0; i < 2; i++) {
            int s = tid + 256 * i;
            int row = s >> 2, part = s & 3;
            size_t goA = (size_t)(row0 + row) * K + (size_t)kc * 32 + part * 8;
            size_t goB = (size_t)(col0 + row) * K + (size_t)kc * 32 + part * 8;
            uint32_t so = (uint32_t)(row * PITCH + part * 16);
            CP_ASYNC16(sb + so,       Ahi + goA);
            CP_ASYNC16(sb + T_A + so, Bhi + goB);
        }
    };

    load_stage(sb0, 0);
    CP_COMMIT();

    for (int kc = 0; kc < nk; kc++) {
        uint32_t sb = sb0 + (uint32_t)(kc & 1) * T3_STAGE;
        if (kc + 1 < nk) {
            load_stage(sb0 + (uint32_t)((kc + 1) & 1) * T3_STAGE, kc + 1);
            CP_COMMIT();
            CP_WAIT(1);
        } else {
            CP_WAIT(0);
        }
        __syncthreads();

        const uint32_t aB = sb + a_row * PITCH + a_kb;
        const uint32_t bB = sb + T_A + b_n * PITCH + b_kb;

#pragma unroll
        for (int ks = 0; ks < 2; ks++) {
            uint32_t ah[4][4], bh[2][4];
#pragma unroll
            for (int m = 0; m < 4; m++)
                ldsm4(ah[m], aB + (uint32_t)(m * 16 * PITCH) + ks * 32);
#pragma unroll
            for (int p = 0; p < 2; p++)
                ldsm4(bh[p], bB + (uint32_t)(p * 16 * PITCH) + ks * 32);
#pragma unroll
            for (int m = 0; m < 4; m++)
#pragma unroll
                for (int p = 0; p < 2; p++)
#pragma unroll
                    for (int h = 0; h < 2; h++) {
                        float* c = acc[m][p * 2 + h];
                        uint32_t bhh[2] = {bh[p][h * 2], bh[p][h * 2 + 1]};
                        mma_f16(c, ah[m], bhh);
                    }
        }
        __syncthreads();
    }

    const int g = lane >> 2, t = lane & 3;
#pragma unroll
    for (int m = 0; m < 4; m++) {
        int r0 = row0 + wm * 64 + m * 16 + g;
#pragma unroll
        for (int n = 0; n < 4; n++) {
            int c = col0 + wn * 32 + n * 8 + 2 * t;
            *(float2*)&C[(size_t)r0 * N + c] = make_float2(acc[m][n][0], acc[m][n][1]);
            *(float2*)&C[(size_t)(r0 + 8) * N + c] = make_float2(acc[m][n][2], acc[m][n][3]);
        }
    }
}

// ---------------- merged RoPE (vectorized): q part + kv part, one launch --------
// q additionally scaled by log2(e) so flash can use exp2f.
#define ROPE_QBLOCKS ((NH * Tn * 16) / 256)     // 4096
#define ROPE_KVBLOCKS ((NKV * Tn * 16) / 256)   // 1024

__global__ void __launch_bounds__(256) rope_all_kernel(
    const float* __restrict__ cosb, const float* __restrict__ sinb,
    float* __restrict__ outK, float* __restrict__ outV)
{
    int bid = blockIdx.x;
    if (bid < ROPE_QBLOCKS) {
        int idx = bid * 256 + threadIdx.x;
        int d = (idx & 15) * 4;
        int t = (idx >> 4) & (Tn - 1);
        int h = idx >> 15;
        const float* src = g_tqkv + (size_t)t * HDA + h * Dh;
        float4 u1 = *(const float4*)(src + d);
        float4 u2 = *(const float4*)(src + d + 64);
        float4 c1 = *(const float4*)&cosb[t * Dh + d];
        float4 s1 = *(const float4*)&sinb[t * Dh + d];
        float4 c2 = *(const float4*)&cosb[t * Dh + d + 64];
        float4 s2 = *(const float4*)&sinb[t * Dh + d + 64];
        float4 y1 = make_float4((u1.x * c1.x - u2.x * s1.x) * LOG2E,
                                (u1.y * c1.y - u2.y * s1.y) * LOG2E,
                                (u1.z * c1.z - u2.z * s1.z) * LOG2E,
                                (u1.w * c1.w - u2.w * s1.w) * LOG2E);
        float4 y2 = make_float4((u2.x * c2.x + u1.x * s2.x) * LOG2E,
                                (u2.y * c2.y + u1.y * s2.y) * LOG2E,
                                (u2.z * c2.z + u1.z * s2.z) * LOG2E,
                                (u2.w * c2.w + u1.w * s2.w) * LOG2E);
        size_t o = ((size_t)h * Tn + t) * Dh + d;
        uint2 hi1, lo1, hi2, lo2;
        pack4b(y1.x, y1.y, y1.z, y1.w, hi1, lo1);
        pack4b(y2.x, y2.y, y2.z, y2.w, hi2, lo2);
        *(uint2*)&g_qhi[o]      = hi1;
        *(uint2*)&g_qlo[o]      = lo1;
        *(uint2*)&g_qhi[o + 64] = hi2;
        *(uint2*)&g_qlo[o + 64] = lo2;
    } else {
        int idx = (bid - ROPE_QBLOCKS) * 256 + threadIdx.x;
        int d  = (idx & 15) * 4;
        int t  = (idx >> 4) & (Tn - 1);
        int kh = idx >> 15;
        const float* srck = g_tqkv + (size_t)t * HDA + HDq + kh * Dh;
        float4 u1 = *(const float4*)(srck + d);
        float4 u2 = *(const float4*)(srck + d + 64);
        float4 c1 = *(const float4*)&cosb[t * Dh + d];
        float4 s1 = *(const float4*)&sinb[t * Dh + d];
        float4 c2 = *(const float4*)&cosb[t * Dh + d + 64];
        float4 s2 = *(const float4*)&sinb[t * Dh + d + 64];
        float4 y1 = make_float4(u1.x * c1.x - u2.x * s1.x, u1.y * c1.y - u2.y * s1.y,
                                u1.z * c1.z - u2.z * s1.z, u1.w * c1.w - u2.w * s1.w);
        float4 y2 = make_float4(u2.x * c2.x + u1.x * s2.x, u2.y * c2.y + u1.y * s2.y,
                                u2.z * c2.z + u1.z * s2.z, u2.w * c2.w + u1.w * s2.w);
        size_t o = ((size_t)kh * Tn + t) * Dh + d;
        *(float4*)(outK + o)      = y1;
        *(float4*)(outK + o + 64) = y2;
        uint2 hi1, lo1, hi2, lo2;
        pack4b(y1.x, y1.y, y1.z, y1.w, hi1, lo1);
        pack4b(y2.x, y2.y, y2.z, y2.w, hi2, lo2);
        *(uint2*)&g_khi[o]      = hi1;
        *(uint2*)&g_klo[o]      = lo1;
        *(uint2*)&g_khi[o + 64] = hi2;
        *(uint2*)&g_klo[o + 64] = lo2;
        const float* srcv = srck + HDkv;
        float4 v1 = *(const float4*)(srcv + d);
        float4 v2 = *(const float4*)(srcv + d + 64);
        *(float4*)(outV + o)      = v1;
        *(float4*)(outV + o + 64) = v2;
        __half2 a1 = __floats2half2_rn(v1.x, v1.y);
        __half2 b1 = __floats2half2_rn(v1.z, v1.w);
        __half2 a2 = __floats2half2_rn(v2.x, v2.y);
        __half2 b2 = __floats2half2_rn(v2.z, v2.w);
        uint2 p1, p2;
        p1.x = *reinterpret_cast<uint32_t*>(&a1);
        p1.y = *reinterpret_cast<uint32_t*>(&b1);
        p2.x = *reinterpret_cast<uint32_t*>(&a2);
        p2.y = *reinterpret_cast<uint32_t*>(&b2);
        *(uint2*)&g_vh[o]      = p1;
        *(uint2*)&g_vh[o + 64] = p2;
    }
}

// ---------------- flash attention (QK: bf16 3-MMA, PV: fp16 2-MMA) ----------------
// q pre-scaled by log2(e) -> softmax uses exp2f. y emitted as single fp16 plane.
#define FP272   272
#define QTILE   (128 * FP272)          // 34816
#define KTILE   (64 * FP272)           // 17408
#define FSTAGE  (3 * KTILE)            // Kh, Kl, Vh = 52224
#define F_SMEM  (2 * QTILE + 3 * FSTAGE)  // 226304

__device__ __forceinline__ void f_load_kv(
    uint32_t st, const __nv_bfloat16* __restrict__ kh,
    const __nv_bfloat16* __restrict__ kl, const __half* __restrict__ vh, int tid)
{
#pragma unroll
    for (int i = 0; i < 4; i++) {
        int s = tid + 256 * i;
        int r = s >> 4, c = s & 15;
        uint32_t so = (uint32_t)(r * FP272 + c * 16);
        size_t go = (size_t)r * Dh + c * 8;
        CP_ASYNC16(st + so,             kh + go);
        CP_ASYNC16(st + KTILE + so,     kl + go);
        CP_ASYNC16(st + 2 * KTILE + so, vh + go);
    }
}

__global__ void __launch_bounds__(256) flash_mma_kernel(__half* __restrict__ ybhi)
{
    extern __shared__ char smc[];
    const uint32_t sb = smem_u32(smc);
    const int tid = threadIdx.x, lane = tid & 31, w = tid >> 5;
    const int h  = blockIdx.y;
    const int qi = (int)gridDim.x - 1 - (int)blockIdx.x;   // big tiles first
    const int q0 = qi * 128;
    const int kvh = h >> 2;
    const int nb = 2 * qi + 2;

    const uint32_t sQh = sb, sQl = sb + QTILE;
    const uint32_t sKV = sb + 2 * QTILE;

    const uint32_t aQoff = (uint32_t)((16 * w + (lane & 15)) * FP272 + (lane >> 4) * 16);
    const int bmat = lane >> 3, bwin = lane & 7;
    const uint32_t bKoff = (uint32_t)((bwin + ((bmat >> 1) << 3)) * FP272 + ((bmat & 1) << 4));
    const uint32_t bVoff = (uint32_t)((lane & 15) * FP272 + ((lane >> 4) << 4));

    const __nv_bfloat16* gKh = g_khi + (size_t)kvh * Tn * Dh;
    const __nv_bfloat16* gKl = g_klo + (size_t)kvh * Tn * Dh;
    const __half*        gVh = g_vh  + (size_t)kvh * Tn * Dh;

    {
        const __nv_bfloat16* gqh = g_qhi + ((size_t)h * Tn + q0) * Dh;
        const __nv_bfloat16* gql = g_qlo + ((size_t)h * Tn + q0) * Dh;
#pragma unroll
        for (int i = 0; i < 8; i++) {
            int s = tid + 256 * i;
            int r = s >> 4, c = s & 15;
            uint32_t so = (uint32_t)(r * FP272 + c * 16);
            size_t go = (size_t)r * Dh + c * 8;
            CP_ASYNC16(sQh + so, gqh + go);
            CP_ASYNC16(sQl + so, gql + go);
        }
        f_load_kv(sKV, gKh, gKl, gVh, tid);
        CP_COMMIT();
        f_load_kv(sKV + FSTAGE, gKh + (size_t)64 * Dh, gKl + (size_t)64 * Dh,
                  gVh + (size_t)64 * Dh, tid);
        CP_COMMIT();
    }

    CP_WAIT(1);
    __syncthreads();
    uint32_t qh_f[8][4], ql_f[8][4];
#pragma unroll
    for (int ks = 0; ks < 8; ks++) {
        ldsm4(qh_f[ks], sQh + aQoff + ks * 32);
        ldsm4(ql_f[ks], sQl + aQoff + ks * 32);
    }

    float o[16][4];
#pragma unroll
    for (int dt = 0; dt < 16; dt++)
#pragma unroll
        for (int e = 0; e < 4; e++) o[dt][e] = 0.f;
    float m0 = -1e30f, m1 = -1e30f, l0 = 0.f, l1 = 0.f;

    const int row_lo = q0 + 16 * w + (lane >> 2);
    const int row_hi = row_lo + 8;

    for (int j = 0; j < nb; j++) {
        if (j > 0) {
            if (j + 1 < nb) CP_WAIT(1); else CP_WAIT(0);
            __syncthreads();
        }
        if (j + 2 < nb) {
            size_t kb = (size_t)(j + 2) * 64;
            f_load_kv(sKV + (uint32_t)((j + 2) % 3) * FSTAGE,
                      gKh + kb * Dh, gKl + kb * Dh, gVh + kb * Dh, tid);
            CP_COMMIT();
        }

        const uint32_t stg = sKV + (uint32_t)(j % 3) * FSTAGE;
        const int kb0 = j * 64;
        const bool active = (q0 + 16 * w + 15) >= kb0;

        if (active) {
            float sc[8][4];
#pragma unroll
            for (int nt = 0; nt < 8; nt++)
#pragma unroll
                for (int e = 0; e < 4; e++) sc[nt][e] = 0.f;

#pragma unroll
            for (int ks = 0; ks < 8; ks++) {
#pragma unroll
                for (int p = 0; p < 4; p++) {
                    uint32_t khf[4], klf[4];
                    uint32_t ka = stg + bKoff + (uint32_t)(p * 16 * FP272) + ks * 32;
                    ldsm4(khf, ka);
                    ldsm4(klf, ka + KTILE);
#pragma unroll
                    for (int hh = 0; hh < 2; hh++) {
                        float* c = sc[p * 2 + hh];
                        uint32_t bh2[2] = {khf[hh * 2], khf[hh * 2 + 1]};
                        uint32_t bl2[2] = {klf[hh * 2], klf[hh * 2 + 1]};
                        mma_bf16(c, qh_f[ks], bh2);
                        mma_bf16(c, qh_f[ks], bl2);
                        mma_bf16(c, ql_f[ks], bh2);
                    }
                }
            }

            if (kb0 + 63 > row_lo) {
#pragma unroll
                for (int nt = 0; nt < 8; nt++) {
                    int col = kb0 + nt * 8 + 2 * (lane & 3);
                    if (col > row_lo)     sc[nt][0] = -1e30f;
                    if (col + 1 > row_lo) sc[nt][1] = -1e30f;
                    if (col > row_hi)     sc[nt][2] = -1e30f;
                    if (col + 1 > row_hi) sc[nt][3] = -1e30f;
                }
            }

            float ml0 = -1e30f, ml1 = -1e30f;
#pragma unroll
            for (int nt = 0; nt < 8; nt++) {
                ml0 = fmaxf(ml0, fmaxf(sc[nt][0], sc[nt][1]));
                ml1 = fmaxf(ml1, fmaxf(sc[nt][2], sc[nt][3]));
            }
            ml0 = fmaxf(ml0, __shfl_xor_sync(0xffffffffu, ml0, 1));
            ml0 = fmaxf(ml0, __shfl_xor_sync(0xffffffffu, ml0, 2));
            ml1 = fmaxf(ml1, __shfl_xor_sync(0xffffffffu, ml1, 1));
            ml1 = fmaxf(ml1, __shfl_xor_sync(0xffffffffu, ml1, 2));
            float mn0 = fmaxf(m0, ml0), mn1 = fmaxf(m1, ml1);
            float es0 = exp2f(m0 - mn0), es1 = exp2f(m1 - mn1);
            float ls0 = 0.f, ls1 = 0.f;
#pragma unroll
            for (int nt = 0; nt < 8; nt++) {
                sc[nt][0] = exp2f(sc[nt][0] - mn0);
                sc[nt][1] = exp2f(sc[nt][1] - mn0);
                sc[nt][2] = exp2f(sc[nt][2] - mn1);
                sc[nt][3] = exp2f(sc[nt][3] - mn1);
                ls0 += sc[nt][0] + sc[nt][1];
                ls1 += sc[nt][2] + sc[nt][3];
            }
            ls0 += __shfl_xor_sync(0xffffffffu, ls0, 1);
            ls0 += __shfl_xor_sync(0xffffffffu, ls0, 2);
            ls1 += __shfl_xor_sync(0xffffffffu, ls1, 1);
            ls1 += __shfl_xor_sync(0xffffffffu, ls1, 2);
            l0 = l0 * es0 + ls0;  m0 = mn0;
            l1 = l1 * es1 + ls1;  m1 = mn1;
#pragma unroll
            for (int dt = 0; dt < 16; dt++) {
                o[dt][0] *= es0;  o[dt][1] *= es0;
                o[dt][2] *= es1;  o[dt][3] *= es1;
            }

#pragma unroll
            for (int j2 = 0; j2 < 4; j2++) {
                uint32_t ph[4], pl[4];
                split2h(sc[2 * j2][0],     sc[2 * j2][1],     ph[0], pl[0]);
                split2h(sc[2 * j2][2],     sc[2 * j2][3],     ph[1], pl[1]);
                split2h(sc[2 * j2 + 1][0], sc[2 * j2 + 1][1], ph[2], pl[2]);
                split2h(sc[2 * j2 + 1][2], sc[2 * j2 + 1][3], ph[3], pl[3]);
#pragma unroll
                for (int dt2 = 0; dt2 < 8; dt2++) {
                    uint32_t vhf[4];
                    uint32_t va = stg + 2 * KTILE + bVoff +
                                  (uint32_t)(j2 * 16 * FP272) + (uint32_t)(dt2 * 32);
                    ldsm4t(vhf, va);
#pragma unroll
                    for (int hf = 0; hf < 2; hf++) {
                        float* c = o[dt2 * 2 + hf];
                        uint32_t bh2[2] = {vhf[hf * 2], vhf[hf * 2 + 1]};
                        mma_f16(c, ph, bh2);
                        mma_f16(c, pl, bh2);
                    }
                }
            }
        }
    }

    // ---- epilogue: y as single fp16 plane for the Wo GEMM ----
    float inv0 = 1.f / l0, inv1 = 1.f / l1;
#pragma unroll
    for (int dt = 0; dt < 16; dt++) {
        int d = dt * 8 + 2 * (lane & 3);
        size_t o0 = (size_t)row_lo * Cdim + h * Dh + d;
        size_t o1 = (size_t)row_hi * Cdim + h * Dh + d;
        __half2 y0 = __floats2half2_rn(o[dt][0] * inv0, o[dt][1] * inv0);
        __half2 y1 = __floats2half2_rn(o[dt][2] * inv1, o[dt][3] * inv1);
        *reinterpret_cast<__half2*>(ybhi + o0) = y0;
        *reinterpret_cast<__half2*>(ybhi + o1) = y1;
    }
}

// ---------------- launch ----------------
extern "C" void kernel_launch(void* const* d_in, const int* in_sizes, int n_in,
                              void* d_out, int out_size)
{
    const float* x    = (const float*)d_in[0];
    const float* Wq   = (const float*)d_in[1];
    const float* Wk   = (const float*)d_in[2];
    const float* Wv   = (const float*)d_in[3];
    const float* Wo   = (const float*)d_in[4];
    const float* cosb = (const float*)d_in[5];
    const float* sinb = (const float*)d_in[6];
    // d_in[7] = mask (reproduced exactly by causal structure; unused)

    float* out  = (float*)d_out;
    float* outY = out;
    float* outK = out + (size_t)Tn * Cdim;
    float* outV = outK + (size_t)NKV * Tn * Dh;

    float* tqkv;
    cudaGetSymbolAddress((void**)&tqkv, g_tqkv);
    __nv_bfloat16 *xhi, *xlo, *wahi, *walo;
    __half *ybhi, *wohi;
    cudaGetSymbolAddress((void**)&xhi, g_xhi);
    cudaGetSymbolAddress((void**)&xlo, g_xlo);
    cudaGetSymbolAddress((void**)&wahi, g_wahi);
    cudaGetSymbolAddress((void**)&walo, g_walo);
    cudaGetSymbolAddress((void**)&ybhi, g_ybhi);
    cudaGetSymbolAddress((void**)&wohi, g_wohi);

    cudaFuncSetAttribute(tcgemm_kernel, cudaFuncAttributeMaxDynamicSharedMemorySize,
                         G_SMEM);
    cudaFuncSetAttribute(tcgemm3_kernel, cudaFuncAttributeMaxDynamicSharedMemorySize,
                         G3_SMEM);
    cudaFuncSetAttribute(flash_mma_kernel, cudaFuncAttributeMaxDynamicSharedMemorySize,
                         F_SMEM);

    // 0. merged prep: x split + all weight transposes (ONE launch, vectorized)
    prep_kernel<<<PREP_END, 256>>>(x, Wq, Wk, Wv, Wo);

    // 1. merged QKV projection (bf16 3-MMA, one launch, N=6144)
    tcgemm_kernel<<<dim3(HDA / 128, Tn / 128), 256, G_SMEM>>>(
        xhi, xlo, wahi, walo, tqkv, HDA, Cdim);

    // 2. merged RoPE + plane conversion (q scaled by log2e for exp2 softmax)
    rope_all_kernel<<<ROPE_QBLOCKS + ROPE_KVBLOCKS, 256>>>(cosb, sinb, outK, outV);

    // 3. causal flash attention (tensor cores, 3-stage KV pipeline)
    flash_mma_kernel<<<dim3(Tn / 128, NH), 256, F_SMEM>>>(ybhi);

    // 4. output projection (fp16 single-MMA: y-lo plane dropped)
    tcgemm3_kernel<<<dim3(Cdim / 128, Tn / 128), 256, G3_SMEM>>>(
        ybhi, wohi, outY, Cdim, Cdim);
}

// round 15
// speedup vs baseline: 1.1265x; 1.0086x over previous
#include <cuda_runtime.h>
#include <cuda_bf16.h>
#include <cuda_fp16.h>
#include <cstdint>

// Problem constants
#define Tn   2048
#define Cdim 4096
#define NH   32
#define NKV  8
#define Dh   128
#define HDq  (NH*Dh)    // 4096
#define HDkv (NKV*Dh)   // 1024
#define HDqk (HDq + HDkv)     // 5120 merged Q|K
#define HDA  (HDq + 2*HDkv)   // 6144 (q|k|v layout in g_tqkv)
#define LOG2E 1.4426950408889634f

// ---------------- scratch (device globals; no allocation) ----------------
__device__ __align__(256) float g_tqkv[(size_t)Tn * HDA];

__device__ __align__(256) __nv_bfloat16 g_xhi[Tn * Cdim];
__device__ __align__(256) __nv_bfloat16 g_xlo[Tn * Cdim];
__device__ __align__(256) __half       g_xh16[Tn * Cdim];
__device__ __align__(256) __nv_bfloat16 g_qhi[(size_t)NH * Tn * Dh];
__device__ __align__(256) __nv_bfloat16 g_qlo[(size_t)NH * Tn * Dh];
__device__ __align__(256) __nv_bfloat16 g_khi[(size_t)NKV * Tn * Dh];
__device__ __align__(256) __nv_bfloat16 g_klo[(size_t)NKV * Tn * Dh];
__device__ __align__(256) __half       g_vh [(size_t)NKV * Tn * Dh];
__device__ __align__(256) __half       g_ybhi[Tn * Cdim];
__device__ __align__(256) __nv_bfloat16 g_wahi[(size_t)HDqk * Cdim];
__device__ __align__(256) __nv_bfloat16 g_walo[(size_t)HDqk * Cdim];
__device__ __align__(256) __half       g_wvh[(size_t)HDkv * Cdim];
__device__ __align__(256) __half       g_wohi[(size_t)Cdim * Cdim];

// ---------------- baseline-ISA helpers (sm_80+ PTX only) ----------------
__device__ __forceinline__ uint32_t smem_u32(const void* p) {
    uint32_t a;
    asm("{ .reg .u64 t; cvta.to.shared.u64 t, %1; cvt.u32.u64 %0, t; }" : "=r"(a) : "l"(p));
    return a;
}

#define CP_ASYNC16(sm, gp) \
    asm volatile("cp.async.cg.shared.global [%0], [%1], 16;" :: "r"(sm), "l"(gp) : "memory")
#define CP_COMMIT() asm volatile("cp.async.commit_group;" ::: "memory")
#define CP_WAIT(n)  asm volatile("cp.async.wait_group %0;" :: "n"(n) : "memory")

__device__ __forceinline__ void ldsm4(uint32_t* r, uint32_t addr) {
    asm volatile("ldmatrix.sync.aligned.m8n8.x4.shared.b16 {%0,%1,%2,%3}, [%4];"
        : "=r"(r[0]), "=r"(r[1]), "=r"(r[2]), "=r"(r[3]) : "r"(addr));
}
__device__ __forceinline__ void ldsm4t(uint32_t* r, uint32_t addr) {
    asm volatile("ldmatrix.sync.aligned.m8n8.x4.trans.shared.b16 {%0,%1,%2,%3}, [%4];"
        : "=r"(r[0]), "=r"(r[1]), "=r"(r[2]), "=r"(r[3]) : "r"(addr));
}

__device__ __forceinline__ void mma_bf16(float* c, const uint32_t* a, const uint32_t* b) {
    asm volatile(
        "mma.sync.aligned.m16n8k16.row.col.f32.bf16.bf16.f32 "
        "{%0,%1,%2,%3}, {%4,%5,%6,%7}, {%8,%9}, {%0,%1,%2,%3};"
        : "+f"(c[0]), "+f"(c[1]), "+f"(c[2]), "+f"(c[3])
        : "r"(a[0]), "r"(a[1]), "r"(a[2]), "r"(a[3]), "r"(b[0]), "r"(b[1]));
}
__device__ __forceinline__ void mma_f16(float* c, const uint32_t* a, const uint32_t* b) {
    asm volatile(
        "mma.sync.aligned.m16n8k16.row.col.f32.f16.f16.f32 "
        "{%0,%1,%2,%3}, {%4,%5,%6,%7}, {%8,%9}, {%0,%1,%2,%3};"
        : "+f"(c[0]), "+f"(c[1]), "+f"(c[2]), "+f"(c[3])
        : "r"(a[0]), "r"(a[1]), "r"(a[2]), "r"(a[3]), "r"(b[0]), "r"(b[1]));
}

__device__ __forceinline__ void split2h(float a, float b, uint32_t& hi, uint32_t& lo) {
    __half2 H = __floats2half2_rn(a, b);
    float ra = a - __half2float(__low2half(H));
    float rb = b - __half2float(__high2half(H));
    __half2 L = __floats2half2_rn(ra, rb);
    hi = *reinterpret_cast<uint32_t*>(&H);
    lo = *reinterpret_cast<uint32_t*>(&L);
}

// pack 4 floats -> 4 bf16 hi (uint2) + 4 bf16 lo (uint2)
__device__ __forceinline__ void pack4b(float a, float b, float c, float d,
                                       uint2& hi, uint2& lo) {
    __nv_bfloat16 h0 = __float2bfloat16(a), h1 = __float2bfloat16(b);
    __nv_bfloat16 h2 = __float2bfloat16(c), h3 = __float2bfloat16(d);
    __nv_bfloat162 H01; H01.x = h0; H01.y = h1;
    __nv_bfloat162 H23; H23.x = h2; H23.y = h3;
    __nv_bfloat162 L01, L23;
    L01.x = __float2bfloat16(a - __bfloat162float(h0));
    L01.y = __float2bfloat16(b - __bfloat162float(h1));
    L23.x = __float2bfloat16(c - __bfloat162float(h2));
    L23.y = __float2bfloat16(d - __bfloat162float(h3));
    hi.x = *reinterpret_cast<uint32_t*>(&H01);
    hi.y = *reinterpret_cast<uint32_t*>(&H23);
    lo.x = *reinterpret_cast<uint32_t*>(&L01);
    lo.y = *reinterpret_cast<uint32_t*>(&L23);
}

__device__ __forceinline__ uint2 pack4h(float a, float b, float c, float d) {
    __half2 A = __floats2half2_rn(a, b);
    __half2 B = __floats2half2_rn(c, d);
    uint2 pk;
    pk.x = *reinterpret_cast<uint32_t*>(&A);
    pk.y = *reinterpret_cast<uint32_t*>(&B);
    return pk;
}

// ---------------- merged prep: x split + W transposes, one launch ----------------
#define PREP_X   4096
#define PREP_WQ  (PREP_X + 16384)
#define PREP_WK  (PREP_WQ + 4096)
#define PREP_WV  (PREP_WK + 4096)
#define PREP_END (PREP_WV + 16384)

__global__ void __launch_bounds__(256) prep_kernel(
    const float* __restrict__ x,
    const float* __restrict__ Wq, const float* __restrict__ Wk,
    const float* __restrict__ Wv, const float* __restrict__ Wo)
{
    __shared__ float tile[32][33];
    const int bid = blockIdx.x;
    if (bid < PREP_X) {
        int base = (bid * 256 + threadIdx.x) * 8;
#pragma unroll
        for (int half = 0; half < 2; half++) {
            int idx = base + half * 4;
            float4 v = *(const float4*)&x[idx];
            uint2 hi, lo;
            pack4b(v.x, v.y, v.z, v.w, hi, lo);
            *(uint2*)&g_xhi[idx] = hi;
            *(uint2*)&g_xlo[idx] = lo;
            *(uint2*)&g_xh16[idx] = pack4h(v.x, v.y, v.z, v.w);
        }
        return;
    }
    const float* W;
    __nv_bfloat16 *Thi, *Tlo;
    __half* Th16 = nullptr;
    int N, rel;
    if (bid < PREP_WQ)      { rel = bid - PREP_X;  W = Wq; N = HDq;
                              Thi = g_wahi; Tlo = g_walo; }
    else if (bid < PREP_WK) { rel = bid - PREP_WQ; W = Wk; N = HDkv;
                              Thi = g_wahi + (size_t)HDq * Cdim;
                              Tlo = g_walo + (size_t)HDq * Cdim; }
    else if (bid < PREP_WV) { rel = bid - PREP_WK; W = Wv; N = HDkv;
                              Thi = nullptr; Tlo = nullptr; Th16 = g_wvh; }
    else                    { rel = bid - PREP_WV; W = Wo; N = Cdim;
                              Thi = nullptr; Tlo = nullptr; Th16 = g_wohi; }

    const int ntiles = N / 32;
    int n0 = (rel % ntiles) * 32, k0 = (rel / ntiles) * 32;
    int tx = threadIdx.x & 31, ty = threadIdx.x >> 5;
#pragma unroll
    for (int j = 0; j < 4; j++)
        tile[ty + 8 * j][tx] = W[(size_t)(k0 + ty + 8 * j) * N + n0 + tx];
    __syncthreads();

    int n  = threadIdx.x >> 3;
    int kq = (threadIdx.x & 7) * 4;
    float v0 = tile[kq + 0][n], v1 = tile[kq + 1][n];
    float v2 = tile[kq + 2][n], v3 = tile[kq + 3][n];
    size_t o = (size_t)(n0 + n) * Cdim + k0 + kq;
    if (Th16) {
        *(uint2*)&Th16[o] = pack4h(v0, v1, v2, v3);
    } else {
        uint2 hi, lo;
        pack4b(v0, v1, v2, v3, hi, lo);
        *(uint2*)&Thi[o] = hi;
        *(uint2*)&Tlo[o] = lo;
    }
}

// ---------------- GEMM common geometry ----------------
#define PITCH   80
#define T_A     10240                  // 128 rows * 80B

// ---------------- bf16 3-MMA GEMM: C = A(hi/lo) * B(hi/lo)^T (ldc = Nld) ---------
#define T_STAGE (4 * T_A)
#define G_SMEM  (2 * T_STAGE)          // 81920

__device__ __forceinline__ void g_load_pair(
    uint32_t sbase, const __nv_bfloat16* __restrict__ hi,
    const __nv_bfloat16* __restrict__ lo, int rbase, int kc, int K, int tid)
{
#pragma unroll
    for (int i = 0; i < 2; i++) {
        int s = tid + 256 * i;
        int row = s >> 2, part = s & 3;
        size_t go = (size_t)(rbase + row) * K + (size_t)kc * 32 + part * 8;
        uint32_t so = (uint32_t)(row * PITCH + part * 16);
        CP_ASYNC16(sbase + so, hi + go);
        CP_ASYNC16(sbase + T_A + so, lo + go);
    }
}

__global__ void __launch_bounds__(256, 2) tcgemm_kernel(
    const __nv_bfloat16* __restrict__ Ahi, const __nv_bfloat16* __restrict__ Alo,
    const __nv_bfloat16* __restrict__ Bhi, const __nv_bfloat16* __restrict__ Blo,
    float* __restrict__ C, int Nld, int K)
{
    extern __shared__ char smc[];
    const uint32_t sb0 = smem_u32(smc);
    const int tid  = threadIdx.x;
    const int lane = tid & 31;
    const int wid  = tid >> 5;
    const int wm   = wid & 1;
    const int wn   = wid >> 1;
    const int row0 = blockIdx.y * 128;
    const int col0 = blockIdx.x * 128;

    float acc[4][4][4];
#pragma unroll
    for (int m = 0; m < 4; m++)
#pragma unroll
        for (int n = 0; n < 4; n++)
#pragma unroll
            for (int e = 0; e < 4; e++) acc[m][n][e] = 0.f;

    const uint32_t a_row = (uint32_t)(wm * 64 + (lane & 15));
    const uint32_t a_kb  = (uint32_t)((lane >> 4) * 16);
    const int bmat = lane >> 3, bwin = lane & 7;
    const uint32_t b_n  = (uint32_t)(wn * 32 + bwin + (bmat >> 1) * 8);
    const uint32_t b_kb = (uint32_t)((bmat & 1) * 16);

    const int nk = K >> 5;

    g_load_pair(sb0,           Ahi, Alo, row0, 0, K, tid);
    g_load_pair(sb0 + 2 * T_A, Bhi, Blo, col0, 0, K, tid);
    CP_COMMIT();

    for (int kc = 0; kc < nk; kc++) {
        uint32_t sb = sb0 + (uint32_t)(kc & 1) * T_STAGE;
        if (kc + 1 < nk) {
            uint32_t sb2 = sb0 + (uint32_t)((kc + 1) & 1) * T_STAGE;
            g_load_pair(sb2,           Ahi, Alo, row0, kc + 1, K, tid);
            g_load_pair(sb2 + 2 * T_A, Bhi, Blo, col0, kc + 1, K, tid);
            CP_COMMIT();
            CP_WAIT(1);
        } else {
            CP_WAIT(0);
        }
        __syncthreads();

        const uint32_t aB = sb + a_row * PITCH + a_kb;
        const uint32_t bB = sb + 2 * T_A + b_n * PITCH + b_kb;

#pragma unroll
        for (int ks = 0; ks < 2; ks++) {
            uint32_t ah[4][4], al[4][4], bh[2][4], bl[2][4];
#pragma unroll
            for (int m = 0; m < 4; m++) {
                ldsm4(ah[m], aB + (uint32_t)(m * 16 * PITCH) + ks * 32);
                ldsm4(al[m], aB + T_A + (uint32_t)(m * 16 * PITCH) + ks * 32);
            }
#pragma unroll
            for (int p = 0; p < 2; p++) {
                ldsm4(bh[p], bB + (uint32_t)(p * 16 * PITCH) + ks * 32);
                ldsm4(bl[p], bB + T_A + (uint32_t)(p * 16 * PITCH) + ks * 32);
            }
#pragma unroll
            for (int m = 0; m < 4; m++)
#pragma unroll
                for (int p = 0; p < 2; p++)
#pragma unroll
                    for (int h = 0; h < 2; h++) {
                        float* c = acc[m][p * 2 + h];
                        uint32_t bhh[2] = {bh[p][h * 2], bh[p][h * 2 + 1]};
                        uint32_t bll[2] = {bl[p][h * 2], bl[p][h * 2 + 1]};
                        mma_bf16(c, ah[m], bhh);
                        mma_bf16(c, ah[m], bll);
                        mma_bf16(c, al[m], bhh);
                    }
        }
        __syncthreads();
    }

    const int g = lane >> 2, t = lane & 3;
#pragma unroll
    for (int m = 0; m < 4; m++) {
        int r0 = row0 + wm * 64 + m * 16 + g;
#pragma unroll
        for (int n = 0; n < 4; n++) {
            int c = col0 + wn * 32 + n * 8 + 2 * t;
            *(float2*)&C[(size_t)r0 * Nld + c] = make_float2(acc[m][n][0], acc[m][n][1]);
            *(float2*)&C[(size_t)(r0 + 8) * Nld + c] = make_float2(acc[m][n][2], acc[m][n][3]);
        }
    }
}

// ---------------- fp16 1-MMA GEMM (2-stage): C = Ahi * Bhi^T (ldc param) --------
#define T3_STAGE (2 * T_A)             // Ah, Bh = 20480
#define G3_SMEM  (2 * T3_STAGE)        // 40960

__global__ void __launch_bounds__(256, 2) tcgemm3_kernel(
    const __half* __restrict__ Ahi, const __half* __restrict__ Bhi,
    float* __restrict__ C, int ldc, int K)
{
    extern __shared__ char smc[];
    const uint32_t sb0 = smem_u32(smc);
    const int tid  = threadIdx.x;
    const int lane = tid & 31;
    const int wid  = tid >> 5;
    const int wm   = wid & 1;
    const int wn   = wid >> 1;
    const int row0 = blockIdx.y * 128;
    const int col0 = blockIdx.x * 128;

    float acc[4][4][4];
#pragma unroll
    for (int m = 0; m < 4; m++)
#pragma unroll
        for (int n = 0; n < 4; n++)
#pragma unroll
            for (int e = 0; e < 4; e++) acc[m][n][e] = 0.f;

    const uint32_t a_row = (uint32_t)(wm * 64 + (lane & 15));
    const uint32_t a_kb  = (uint32_t)((lane >> 4) * 16);
    const int bmat = lane >> 3, bwin = lane & 7;
    const uint32_t b_n  = (uint32_t)(wn * 32 + bwin + (bmat >> 1) * 8);
    const uint32_t b_kb = (uint32_t)((bmat & 1) * 16);

    const int nk = K >> 5;

    auto load_stage = [&](uint32_t sb, int kc) {
#pragma unroll
        for (int i = 0; i < 2; i++) {
            int s = tid + 256 * i;
            int row = s >> 2, part = s & 3;
            size_t goA = (size_t)(row0 + row) * K + (size_t)kc * 32 + part * 8;
            size_t goB = (size_t)(col0 + row) * K + (size_t)kc * 32 + part * 8;
            uint32_t so = (uint32_t)(row * PITCH + part * 16);
            CP_ASYNC16(sb + so,       Ahi + goA);
            CP_ASYNC16(sb + T_A + so, Bhi + goB);
        }
    };

    load_stage(sb0, 0);
    CP_COMMIT();

    for (int kc = 0; kc < nk; kc++) {
        uint32_t sb = sb0 + (uint32_t)(kc & 1) * T3_STAGE;
        if (kc + 1 < nk) {
            load_stage(sb0 + (uint32_t)((kc + 1) & 1) * T3_STAGE, kc + 1);
            CP_COMMIT();
            CP_WAIT(1);
        } else {
            CP_WAIT(0);
        }
        __syncthreads();

        const uint32_t aB = sb + a_row * PITCH + a_kb;
        const uint32_t bB = sb + T_A + b_n * PITCH + b_kb;

#pragma unroll
        for (int ks = 0; ks < 2; ks++) {
            uint32_t ah[4][4], bh[2][4];
#pragma unroll
            for (int m = 0; m < 4; m++)
                ldsm4(ah[m], aB + (uint32_t)(m * 16 * PITCH) + ks * 32);
#pragma unroll
            for (int p = 0; p < 2; p++)
                ldsm4(bh[p], bB + (uint32_t)(p * 16 * PITCH) + ks * 32);
#pragma unroll
            for (int m = 0; m < 4; m++)
#pragma unroll
                for (int p = 0; p < 2; p++)
#pragma unroll
                    for (int h = 0; h < 2; h++) {
                        float* c = acc[m][p * 2 + h];
                        uint32_t bhh[2] = {bh[p][h * 2], bh[p][h * 2 + 1]};
                        mma_f16(c, ah[m], bhh);
                    }
        }
        __syncthreads();
    }

    const int g = lane >> 2, t = lane & 3;
#pragma unroll
    for (int m = 0; m < 4; m++) {
        int r0 = row0 + wm * 64 + m * 16 + g;
#pragma unroll
        for (int n = 0; n < 4; n++) {
            int c = col0 + wn * 32 + n * 8 + 2 * t;
            *(float2*)&C[(size_t)r0 * ldc + c] = make_float2(acc[m][n][0], acc[m][n][1]);
            *(float2*)&C[(size_t)(r0 + 8) * ldc + c] = make_float2(acc[m][n][2], acc[m][n][3]);
        }
    }
}

// ---------------- merged RoPE (vectorized): q part + kv part, one launch --------
// q additionally scaled by log2(e) so flash can use exp2f.
#define ROPE_QBLOCKS ((NH * Tn * 16) / 256)     // 4096
#define ROPE_KVBLOCKS ((NKV * Tn * 16) / 256)   // 1024

__global__ void __launch_bounds__(256) rope_all_kernel(
    const float* __restrict__ cosb, const float* __restrict__ sinb,
    float* __restrict__ outK, float* __restrict__ outV)
{
    int bid = blockIdx.x;
    if (bid < ROPE_QBLOCKS) {
        int idx = bid * 256 + threadIdx.x;
        int d = (idx & 15) * 4;
        int t = (idx >> 4) & (Tn - 1);
        int h = idx >> 15;
        const float* src = g_tqkv + (size_t)t * HDA + h * Dh;
        float4 u1 = *(const float4*)(src + d);
        float4 u2 = *(const float4*)(src + d + 64);
        float4 c1 = *(const float4*)&cosb[t * Dh + d];
        float4 s1 = *(const float4*)&sinb[t * Dh + d];
        float4 c2 = *(const float4*)&cosb[t * Dh + d + 64];
        float4 s2 = *(const float4*)&sinb[t * Dh + d + 64];
        float4 y1 = make_float4((u1.x * c1.x - u2.x * s1.x) * LOG2E,
                                (u1.y * c1.y - u2.y * s1.y) * LOG2E,
                                (u1.z * c1.z - u2.z * s1.z) * LOG2E,
                                (u1.w * c1.w - u2.w * s1.w) * LOG2E);
        float4 y2 = make_float4((u2.x * c2.x + u1.x * s2.x) * LOG2E,
                                (u2.y * c2.y + u1.y * s2.y) * LOG2E,
                                (u2.z * c2.z + u1.z * s2.z) * LOG2E,
                                (u2.w * c2.w + u1.w * s2.w) * LOG2E);
        size_t o = ((size_t)h * Tn + t) * Dh + d;
        uint2 hi1, lo1, hi2, lo2;
        pack4b(y1.x, y1.y, y1.z, y1.w, hi1, lo1);
        pack4b(y2.x, y2.y, y2.z, y2.w, hi2, lo2);
        *(uint2*)&g_qhi[o]      = hi1;
        *(uint2*)&g_qlo[o]      = lo1;
        *(uint2*)&g_qhi[o + 64] = hi2;
        *(uint2*)&g_qlo[o + 64] = lo2;
    } else {
        int idx = (bid - ROPE_QBLOCKS) * 256 + threadIdx.x;
        int d  = (idx & 15) * 4;
        int t  = (idx >> 4) & (Tn - 1);
        int kh = idx >> 15;
        const float* srck = g_tqkv + (size_t)t * HDA + HDq + kh * Dh;
        float4 u1 = *(const float4*)(srck + d);
        float4 u2 = *(const float4*)(srck + d + 64);
        float4 c1 = *(const float4*)&cosb[t * Dh + d];
        float4 s1 = *(const float4*)&sinb[t * Dh + d];
        float4 c2 = *(const float4*)&cosb[t * Dh + d + 64];
        float4 s2 = *(const float4*)&sinb[t * Dh + d + 64];
        float4 y1 = make_float4(u1.x * c1.x - u2.x * s1.x, u1.y * c1.y - u2.y * s1.y,
                                u1.z * c1.z - u2.z * s1.z, u1.w * c1.w - u2.w * s1.w);
        float4 y2 = make_float4(u2.x * c2.x + u1.x * s2.x, u2.y * c2.y + u1.y * s2.y,
                                u2.z * c2.z + u1.z * s2.z, u2.w * c2.w + u1.w * s2.w);
        size_t o = ((size_t)kh * Tn + t) * Dh + d;
        *(float4*)(outK + o)      = y1;
        *(float4*)(outK + o + 64) = y2;
        uint2 hi1, lo1, hi2, lo2;
        pack4b(y1.x, y1.y, y1.z, y1.w, hi1, lo1);
        pack4b(y2.x, y2.y, y2.z, y2.w, hi2, lo2);
        *(uint2*)&g_khi[o]      = hi1;
        *(uint2*)&g_klo[o]      = lo1;
        *(uint2*)&g_khi[o + 64] = hi2;
        *(uint2*)&g_klo[o + 64] = lo2;
        const float* srcv = srck + HDkv;
        float4 v1 = *(const float4*)(srcv + d);
        float4 v2 = *(const float4*)(srcv + d + 64);
        *(float4*)(outV + o)      = v1;
        *(float4*)(outV + o + 64) = v2;
        *(uint2*)&g_vh[o]      = pack4h(v1.x, v1.y, v1.z, v1.w);
        *(uint2*)&g_vh[o + 64] = pack4h(v2.x, v2.y, v2.z, v2.w);
    }
}

// ---------------- flash attention (QK: bf16 3-MMA, PV: fp16 2-MMA) ----------------
// q pre-scaled by log2(e) -> softmax uses exp2f. y emitted as single fp16 plane.
#define FP272   272
#define QTILE   (128 * FP272)          // 34816
#define KTILE   (64 * FP272)           // 17408
#define FSTAGE  (3 * KTILE)            // Kh, Kl, Vh = 52224
#define F_SMEM  (2 * QTILE + 3 * FSTAGE)  // 226304

__device__ __forceinline__ void f_load_kv(
    uint32_t st, const __nv_bfloat16* __restrict__ kh,
    const __nv_bfloat16* __restrict__ kl, const __half* __restrict__ vh, int tid)
{
#pragma unroll
    for (int i = 0; i < 4; i++) {
        int s = tid + 256 * i;
        int r = s >> 4, c = s & 15;
        uint32_t so = (uint32_t)(r * FP272 + c * 16);
        size_t go = (size_t)r * Dh + c * 8;
        CP_ASYNC16(st + so,             kh + go);
        CP_ASYNC16(st + KTILE + so,     kl + go);
        CP_ASYNC16(st + 2 * KTILE + so, vh + go);
    }
}

__global__ void __launch_bounds__(256) flash_mma_kernel(__half* __restrict__ ybhi)
{
    extern __shared__ char smc[];
    const uint32_t sb = smem_u32(smc);
    const int tid = threadIdx.x, lane = tid & 31, w = tid >> 5;
    const int h  = blockIdx.y;
    const int qi = (int)gridDim.x - 1 - (int)blockIdx.x;   // big tiles first
    const int q0 = qi * 128;
    const int kvh = h >> 2;
    const int nb = 2 * qi + 2;

    const uint32_t sQh = sb, sQl = sb + QTILE;
    const uint32_t sKV = sb + 2 * QTILE;

    const uint32_t aQoff = (uint32_t)((16 * w + (lane & 15)) * FP272 + (lane >> 4) * 16);
    const int bmat = lane >> 3, bwin = lane & 7;
    const uint32_t bKoff = (uint32_t)((bwin + ((bmat >> 1) << 3)) * FP272 + ((bmat & 1) << 4));
    const uint32_t bVoff = (uint32_t)((lane & 15) * FP272 + ((lane >> 4) << 4));

    const __nv_bfloat16* gKh = g_khi + (size_t)kvh * Tn * Dh;
    const __nv_bfloat16* gKl = g_klo + (size_t)kvh * Tn * Dh;
    const __half*        gVh = g_vh  + (size_t)kvh * Tn * Dh;

    {
        const __nv_bfloat16* gqh = g_qhi + ((size_t)h * Tn + q0) * Dh;
        const __nv_bfloat16* gql = g_qlo + ((size_t)h * Tn + q0) * Dh;
#pragma unroll
        for (int i = 0; i < 8; i++) {
            int s = tid + 256 * i;
            int r = s >> 4, c = s & 15;
            uint32_t so = (uint32_t)(r * FP272 + c * 16);
            size_t go = (size_t)r * Dh + c * 8;
            CP_ASYNC16(sQh + so, gqh + go);
            CP_ASYNC16(sQl + so, gql + go);
        }
        f_load_kv(sKV, gKh, gKl, gVh, tid);
        CP_COMMIT();
        f_load_kv(sKV + FSTAGE, gKh + (size_t)64 * Dh, gKl + (size_t)64 * Dh,
                  gVh + (size_t)64 * Dh, tid);
        CP_COMMIT();
    }

    CP_WAIT(1);
    __syncthreads();
    uint32_t qh_f[8][4], ql_f[8][4];
#pragma unroll
    for (int ks = 0; ks < 8; ks++) {
        ldsm4(qh_f[ks], sQh + aQoff + ks * 32);
        ldsm4(ql_f[ks], sQl + aQoff + ks * 32);
    }

    float o[16][4];
#pragma unroll
    for (int dt = 0; dt < 16; dt++)
#pragma unroll
        for (int e = 0; e < 4; e++) o[dt][e] = 0.f;
    float m0 = -1e30f, m1 = -1e30f, l0 = 0.f, l1 = 0.f;

    const int row_lo = q0 + 16 * w + (lane >> 2);
    const int row_hi = row_lo + 8;

    for (int j = 0; j < nb; j++) {
        if (j > 0) {
            if (j + 1 < nb) CP_WAIT(1); else CP_WAIT(0);
            __syncthreads();
        }
        if (j + 2 < nb) {
            size_t kb = (size_t)(j + 2) * 64;
            f_load_kv(sKV + (uint32_t)((j + 2) % 3) * FSTAGE,
                      gKh + kb * Dh, gKl + kb * Dh, gVh + kb * Dh, tid);
            CP_COMMIT();
        }

        const uint32_t stg = sKV + (uint32_t)(j % 3) * FSTAGE;
        const int kb0 = j * 64;
        const bool active = (q0 + 16 * w + 15) >= kb0;

        if (active) {
            float sc[8][4];
#pragma unroll
            for (int nt = 0; nt < 8; nt++)
#pragma unroll
                for (int e = 0; e < 4; e++) sc[nt][e] = 0.f;

#pragma unroll
            for (int ks = 0; ks < 8; ks++) {
#pragma unroll
                for (int p = 0; p < 4; p++) {
                    uint32_t khf[4], klf[4];
                    uint32_t ka = stg + bKoff + (uint32_t)(p * 16 * FP272) + ks * 32;
                    ldsm4(khf, ka);
                    ldsm4(klf, ka + KTILE);
#pragma unroll
                    for (int hh = 0; hh < 2; hh++) {
                        float* c = sc[p * 2 + hh];
                        uint32_t bh2[2] = {khf[hh * 2], khf[hh * 2 + 1]};
                        uint32_t bl2[2] = {klf[hh * 2], klf[hh * 2 + 1]};
                        mma_bf16(c, qh_f[ks], bh2);
                        mma_bf16(c, qh_f[ks], bl2);
                        mma_bf16(c, ql_f[ks], bh2);
                    }
                }
            }

            if (kb0 + 63 > row_lo) {
#pragma unroll
                for (int nt = 0; nt < 8; nt++) {
                    int col = kb0 + nt * 8 + 2 * (lane & 3);
                    if (col > row_lo)     sc[nt][0] = -1e30f;
                    if (col + 1 > row_lo) sc[nt][1] = -1e30f;
                    if (col > row_hi)     sc[nt][2] = -1e30f;
                    if (col + 1 > row_hi) sc[nt][3] = -1e30f;
                }
            }

            float ml0 = -1e30f, ml1 = -1e30f;
#pragma unroll
            for (int nt = 0; nt < 8; nt++) {
                ml0 = fmaxf(ml0, fmaxf(sc[nt][0], sc[nt][1]));
                ml1 = fmaxf(ml1, fmaxf(sc[nt][2], sc[nt][3]));
            }
            ml0 = fmaxf(ml0, __shfl_xor_sync(0xffffffffu, ml0, 1));
            ml0 = fmaxf(ml0, __shfl_xor_sync(0xffffffffu, ml0, 2));
            ml1 = fmaxf(ml1, __shfl_xor_sync(0xffffffffu, ml1, 1));
            ml1 = fmaxf(ml1, __shfl_xor_sync(0xffffffffu, ml1, 2));
            float mn0 = fmaxf(m0, ml0), mn1 = fmaxf(m1, ml1);
            float es0 = exp2f(m0 - mn0), es1 = exp2f(m1 - mn1);
            float ls0 = 0.f, ls1 = 0.f;
#pragma unroll
            for (int nt = 0; nt < 8; nt++) {
                sc[nt][0] = exp2f(sc[nt][0] - mn0);
                sc[nt][1] = exp2f(sc[nt][1] - mn0);
                sc[nt][2] = exp2f(sc[nt][2] - mn1);
                sc[nt][3] = exp2f(sc[nt][3] - mn1);
                ls0 += sc[nt][0] + sc[nt][1];
                ls1 += sc[nt][2] + sc[nt][3];
            }
            ls0 += __shfl_xor_sync(0xffffffffu, ls0, 1);
            ls0 += __shfl_xor_sync(0xffffffffu, ls0, 2);
            ls1 += __shfl_xor_sync(0xffffffffu, ls1, 1);
            ls1 += __shfl_xor_sync(0xffffffffu, ls1, 2);
            l0 = l0 * es0 + ls0;  m0 = mn0;
            l1 = l1 * es1 + ls1;  m1 = mn1;
#pragma unroll
            for (int dt = 0; dt < 16; dt++) {
                o[dt][0] *= es0;  o[dt][1] *= es0;
                o[dt][2] *= es1;  o[dt][3] *= es1;
            }

#pragma unroll
            for (int j2 = 0; j2 < 4; j2++) {
                uint32_t ph[4], pl[4];
                split2h(sc[2 * j2][0],     sc[2 * j2][1],     ph[0], pl[0]);
                split2h(sc[2 * j2][2],     sc[2 * j2][3],     ph[1], pl[1]);
                split2h(sc[2 * j2 + 1][0], sc[2 * j2 + 1][1], ph[2], pl[2]);
                split2h(sc[2 * j2 + 1][2], sc[2 * j2 + 1][3], ph[3], pl[3]);
#pragma unroll
                for (int dt2 = 0; dt2 < 8; dt2++) {
                    uint32_t vhf[4];
                    uint32_t va = stg + 2 * KTILE + bVoff +
                                  (uint32_t)(j2 * 16 * FP272) + (uint32_t)(dt2 * 32);
                    ldsm4t(vhf, va);
#pragma unroll
                    for (int hf = 0; hf < 2; hf++) {
                        float* c = o[dt2 * 2 + hf];
                        uint32_t bh2[2] = {vhf[hf * 2], vhf[hf * 2 + 1]};
                        mma_f16(c, ph, bh2);
                        mma_f16(c, pl, bh2);
                    }
                }
            }
        }
    }

    // ---- epilogue: y as single fp16 plane for the Wo GEMM ----
    float inv0 = 1.f / l0, inv1 = 1.f / l1;
#pragma unroll
    for (int dt = 0; dt < 16; dt++) {
        int d = dt * 8 + 2 * (lane & 3);
        size_t o0 = (size_t)row_lo * Cdim + h * Dh + d;
        size_t o1 = (size_t)row_hi * Cdim + h * Dh + d;
        __half2 y0 = __floats2half2_rn(o[dt][0] * inv0, o[dt][1] * inv0);
        __half2 y1 = __floats2half2_rn(o[dt][2] * inv1, o[dt][3] * inv1);
        *reinterpret_cast<__half2*>(ybhi + o0) = y0;
        *reinterpret_cast<__half2*>(ybhi + o1) = y1;
    }
}

// ---------------- launch ----------------
extern "C" void kernel_launch(void* const* d_in, const int* in_sizes, int n_in,
                              void* d_out, int out_size)
{
    const float* x    = (const float*)d_in[0];
    const float* Wq   = (const float*)d_in[1];
    const float* Wk   = (const float*)d_in[2];
    const float* Wv   = (const float*)d_in[3];
    const float* Wo   = (const float*)d_in[4];
    const float* cosb = (const float*)d_in[5];
    const float* sinb = (const float*)d_in[6];
    // d_in[7] = mask (reproduced exactly by causal structure; unused)

    float* out  = (float*)d_out;
    float* outY = out;
    float* outK = out + (size_t)Tn * Cdim;
    float* outV = outK + (size_t)NKV * Tn * Dh;

    float* tqkv;
    cudaGetSymbolAddress((void**)&tqkv, g_tqkv);
    __nv_bfloat16 *xhi, *xlo, *wahi, *walo;
    __half *xh16, *ybhi, *wvh, *wohi;
    cudaGetSymbolAddress((void**)&xhi, g_xhi);
    cudaGetSymbolAddress((void**)&xlo, g_xlo);
    cudaGetSymbolAddress((void**)&xh16, g_xh16);
    cudaGetSymbolAddress((void**)&wahi, g_wahi);
    cudaGetSymbolAddress((void**)&walo, g_walo);
    cudaGetSymbolAddress((void**)&ybhi, g_ybhi);
    cudaGetSymbolAddress((void**)&wvh, g_wvh);
    cudaGetSymbolAddress((void**)&wohi, g_wohi);

    cudaFuncSetAttribute(tcgemm_kernel, cudaFuncAttributeMaxDynamicSharedMemorySize,
                         G_SMEM);
    cudaFuncSetAttribute(tcgemm3_kernel, cudaFuncAttributeMaxDynamicSharedMemorySize,
                         G3_SMEM);
    cudaFuncSetAttribute(flash_mma_kernel, cudaFuncAttributeMaxDynamicSharedMemorySize,
                         F_SMEM);

    // 0. merged prep: x split (bf16 hi/lo + fp16) + weight transposes (ONE launch)
    prep_kernel<<<PREP_END, 256>>>(x, Wq, Wk, Wv, Wo);

    // 1a. Q|K projection (bf16 3-MMA, N=5120, ldc=HDA into g_tqkv)
    tcgemm_kernel<<<dim3(HDqk / 128, Tn / 128), 256, G_SMEM>>>(
        xhi, xlo, wahi, walo, tqkv, HDA, Cdim);

    // 1b. V projection (fp16 1-MMA, N=1024, ldc=HDA into g_tqkv V-columns)
    tcgemm3_kernel<<<dim3(HDkv / 128, Tn / 128), 256, G3_SMEM>>>(
        xh16, wvh, tqkv + HDq + HDkv, HDA, Cdim);

    // 2. merged RoPE + plane conversion (q scaled by log2e for exp2 softmax)
    rope_all_kernel<<<ROPE_QBLOCKS + ROPE_KVBLOCKS, 256>>>(cosb, sinb, outK, outV);

    // 3. causal flash attention (tensor cores, 3-stage KV pipeline)
    flash_mma_kernel<<<dim3(Tn / 128, NH), 256, F_SMEM>>>(ybhi);

    // 4. output projection (fp16 single-MMA)
    tcgemm3_kernel<<<dim3(Cdim / 128, Tn / 128), 256, G3_SMEM>>>(
        ybhi, wohi, outY, Cdim, Cdim);
}

// round 16
// speedup vs baseline: 1.1468x; 1.0180x over previous
#include <cuda_runtime.h>
#include <cuda_bf16.h>
#include <cuda_fp16.h>
#include <cstdint>

// Problem constants
#define Tn   2048
#define Cdim 4096
#define NH   32
#define NKV  8
#define Dh   128
#define HDq  (NH*Dh)    // 4096
#define HDkv (NKV*Dh)   // 1024
#define HDqk (HDq + HDkv)     // 5120 merged Q|K
#define HDA  (HDq + 2*HDkv)   // 6144 (q|k|v layout in g_tqkv)
#define LOG2E 1.4426950408889634f

// ---------------- scratch (device globals; no allocation) ----------------
__device__ __align__(256) float g_tqkv[(size_t)Tn * HDA];

__device__ __align__(256) __nv_bfloat16 g_xhi[Tn * Cdim];
__device__ __align__(256) __nv_bfloat16 g_xlo[Tn * Cdim];
__device__ __align__(256) __half       g_xh16[Tn * Cdim];
__device__ __align__(256) __nv_bfloat16 g_qhi[(size_t)NH * Tn * Dh];
__device__ __align__(256) __nv_bfloat16 g_qlo[(size_t)NH * Tn * Dh];
__device__ __align__(256) __nv_bfloat16 g_khi[(size_t)NKV * Tn * Dh];
__device__ __align__(256) __nv_bfloat16 g_klo[(size_t)NKV * Tn * Dh];
__device__ __align__(256) __half       g_vh [(size_t)NKV * Tn * Dh];
__device__ __align__(256) __half       g_ybhi[Tn * Cdim];
__device__ __align__(256) __nv_bfloat16 g_wahi[(size_t)HDqk * Cdim];
__device__ __align__(256) __nv_bfloat16 g_walo[(size_t)HDqk * Cdim];
__device__ __align__(256) __half       g_wvh[(size_t)HDkv * Cdim];
__device__ __align__(256) __half       g_wohi[(size_t)Cdim * Cdim];

// ---------------- baseline-ISA helpers (sm_80+ PTX only) ----------------
__device__ __forceinline__ uint32_t smem_u32(const void* p) {
    uint32_t a;
    asm("{ .reg .u64 t; cvta.to.shared.u64 t, %1; cvt.u32.u64 %0, t; }" : "=r"(a) : "l"(p));
    return a;
}

#define CP_ASYNC16(sm, gp) \
    asm volatile("cp.async.cg.shared.global [%0], [%1], 16;" :: "r"(sm), "l"(gp) : "memory")
#define CP_COMMIT() asm volatile("cp.async.commit_group;" ::: "memory")
#define CP_WAIT(n)  asm volatile("cp.async.wait_group %0;" :: "n"(n) : "memory")

__device__ __forceinline__ void ldsm4(uint32_t* r, uint32_t addr) {
    asm volatile("ldmatrix.sync.aligned.m8n8.x4.shared.b16 {%0,%1,%2,%3}, [%4];"
        : "=r"(r[0]), "=r"(r[1]), "=r"(r[2]), "=r"(r[3]) : "r"(addr));
}
__device__ __forceinline__ void ldsm4t(uint32_t* r, uint32_t addr) {
    asm volatile("ldmatrix.sync.aligned.m8n8.x4.trans.shared.b16 {%0,%1,%2,%3}, [%4];"
        : "=r"(r[0]), "=r"(r[1]), "=r"(r[2]), "=r"(r[3]) : "r"(addr));
}

__device__ __forceinline__ void mma_bf16(float* c, const uint32_t* a, const uint32_t* b) {
    asm volatile(
        "mma.sync.aligned.m16n8k16.row.col.f32.bf16.bf16.f32 "
        "{%0,%1,%2,%3}, {%4,%5,%6,%7}, {%8,%9}, {%0,%1,%2,%3};"
        : "+f"(c[0]), "+f"(c[1]), "+f"(c[2]), "+f"(c[3])
        : "r"(a[0]), "r"(a[1]), "r"(a[2]), "r"(a[3]), "r"(b[0]), "r"(b[1]));
}
__device__ __forceinline__ void mma_f16(float* c, const uint32_t* a, const uint32_t* b) {
    asm volatile(
        "mma.sync.aligned.m16n8k16.row.col.f32.f16.f16.f32 "
        "{%0,%1,%2,%3}, {%4,%5,%6,%7}, {%8,%9}, {%0,%1,%2,%3};"
        : "+f"(c[0]), "+f"(c[1]), "+f"(c[2]), "+f"(c[3])
        : "r"(a[0]), "r"(a[1]), "r"(a[2]), "r"(a[3]), "r"(b[0]), "r"(b[1]));
}

__device__ __forceinline__ void split2h(float a, float b, uint32_t& hi, uint32_t& lo) {
    __half2 H = __floats2half2_rn(a, b);
    float ra = a - __half2float(__low2half(H));
    float rb = b - __half2float(__high2half(H));
    __half2 L = __floats2half2_rn(ra, rb);
    hi = *reinterpret_cast<uint32_t*>(&H);
    lo = *reinterpret_cast<uint32_t*>(&L);
}

// pack 4 floats -> 4 bf16 hi (uint2) + 4 bf16 lo (uint2)
__device__ __forceinline__ void pack4b(float a, float b, float c, float d,
                                       uint2& hi, uint2& lo) {
    __nv_bfloat16 h0 = __float2bfloat16(a), h1 = __float2bfloat16(b);
    __nv_bfloat16 h2 = __float2bfloat16(c), h3 = __float2bfloat16(d);
    __nv_bfloat162 H01; H01.x = h0; H01.y = h1;
    __nv_bfloat162 H23; H23.x = h2; H23.y = h3;
    __nv_bfloat162 L01, L23;
    L01.x = __float2bfloat16(a - __bfloat162float(h0));
    L01.y = __float2bfloat16(b - __bfloat162float(h1));
    L23.x = __float2bfloat16(c - __bfloat162float(h2));
    L23.y = __float2bfloat16(d - __bfloat162float(h3));
    hi.x = *reinterpret_cast<uint32_t*>(&H01);
    hi.y = *reinterpret_cast<uint32_t*>(&H23);
    lo.x = *reinterpret_cast<uint32_t*>(&L01);
    lo.y = *reinterpret_cast<uint32_t*>(&L23);
}

__device__ __forceinline__ uint2 pack4h(float a, float b, float c, float d) {
    __half2 A = __floats2half2_rn(a, b);
    __half2 B = __floats2half2_rn(c, d);
    uint2 pk;
    pk.x = *reinterpret_cast<uint32_t*>(&A);
    pk.y = *reinterpret_cast<uint32_t*>(&B);
    return pk;
}

// ---------------- merged prep: x split + W transposes, one launch ----------------
#define PREP_X   4096
#define PREP_WQ  (PREP_X + 16384)
#define PREP_WK  (PREP_WQ + 4096)
#define PREP_WV  (PREP_WK + 4096)
#define PREP_END (PREP_WV + 16384)

__global__ void __launch_bounds__(256) prep_kernel(
    const float* __restrict__ x,
    const float* __restrict__ Wq, const float* __restrict__ Wk,
    const float* __restrict__ Wv, const float* __restrict__ Wo)
{
    __shared__ float tile[32][33];
    const int bid = blockIdx.x;
    if (bid < PREP_X) {
        int base = (bid * 256 + threadIdx.x) * 8;
#pragma unroll
        for (int half = 0; half < 2; half++) {
            int idx = base + half * 4;
            float4 v = *(const float4*)&x[idx];
            uint2 hi, lo;
            pack4b(v.x, v.y, v.z, v.w, hi, lo);
            *(uint2*)&g_xhi[idx] = hi;
            *(uint2*)&g_xlo[idx] = lo;
            *(uint2*)&g_xh16[idx] = pack4h(v.x, v.y, v.z, v.w);
        }
        return;
    }
    const float* W;
    __nv_bfloat16 *Thi, *Tlo;
    __half* Th16 = nullptr;
    int N, rel;
    if (bid < PREP_WQ)      { rel = bid - PREP_X;  W = Wq; N = HDq;
                              Thi = g_wahi; Tlo = g_walo; }
    else if (bid < PREP_WK) { rel = bid - PREP_WQ; W = Wk; N = HDkv;
                              Thi = g_wahi + (size_t)HDq * Cdim;
                              Tlo = g_walo + (size_t)HDq * Cdim; }
    else if (bid < PREP_WV) { rel = bid - PREP_WK; W = Wv; N = HDkv;
                              Thi = nullptr; Tlo = nullptr; Th16 = g_wvh; }
    else                    { rel = bid - PREP_WV; W = Wo; N = Cdim;
                              Thi = nullptr; Tlo = nullptr; Th16 = g_wohi; }

    const int ntiles = N / 32;
    int n0 = (rel % ntiles) * 32, k0 = (rel / ntiles) * 32;
    int tx = threadIdx.x & 31, ty = threadIdx.x >> 5;
#pragma unroll
    for (int j = 0; j < 4; j++)
        tile[ty + 8 * j][tx] = W[(size_t)(k0 + ty + 8 * j) * N + n0 + tx];
    __syncthreads();

    int n  = threadIdx.x >> 3;
    int kq = (threadIdx.x & 7) * 4;
    float v0 = tile[kq + 0][n], v1 = tile[kq + 1][n];
    float v2 = tile[kq + 2][n], v3 = tile[kq + 3][n];
    size_t o = (size_t)(n0 + n) * Cdim + k0 + kq;
    if (Th16) {
        *(uint2*)&Th16[o] = pack4h(v0, v1, v2, v3);
    } else {
        uint2 hi, lo;
        pack4b(v0, v1, v2, v3, hi, lo);
        *(uint2*)&Thi[o] = hi;
        *(uint2*)&Tlo[o] = lo;
    }
}

// ---------------- GEMM common geometry ----------------
#define PITCH   80
#define T_A     10240                  // 128 rows * 80B

// ---------------- fused QKV projection: one launch, grid (48, 16) ----------------
// blockIdx.x < 40 : bf16 3-MMA Q|K path (cols [0,5120) of g_tqkv)
// blockIdx.x >= 40: fp16 1-MMA V path  (cols [5120,6144) of g_tqkv)
#define T_STAGE (4 * T_A)
#define G_SMEM  (2 * T_STAGE)          // 81920 (covers both paths)
#define QK_CBLK (HDqk / 128)           // 40

__device__ __forceinline__ void g_load_pair(
    uint32_t sbase, const __nv_bfloat16* __restrict__ hi,
    const __nv_bfloat16* __restrict__ lo, int rbase, int kc, int K, int tid)
{
#pragma unroll
    for (int i = 0; i < 2; i++) {
        int s = tid + 256 * i;
        int row = s >> 2, part = s & 3;
        size_t go = (size_t)(rbase + row) * K + (size_t)kc * 32 + part * 8;
        uint32_t so = (uint32_t)(row * PITCH + part * 16);
        CP_ASYNC16(sbase + so, hi + go);
        CP_ASYNC16(sbase + T_A + so, lo + go);
    }
}

__global__ void __launch_bounds__(256, 2) tcgemm_qkv_kernel(
    const __nv_bfloat16* __restrict__ Ahi, const __nv_bfloat16* __restrict__ Alo,
    const __nv_bfloat16* __restrict__ Bhi, const __nv_bfloat16* __restrict__ Blo,
    const __half* __restrict__ Ah16, const __half* __restrict__ Bv16,
    float* __restrict__ C)
{
    extern __shared__ char smc[];
    const uint32_t sb0 = smem_u32(smc);
    const int tid  = threadIdx.x;
    const int lane = tid & 31;
    const int wid  = tid >> 5;
    const int wm   = wid & 1;
    const int wn   = wid >> 1;
    const int row0 = blockIdx.y * 128;
    const int K = Cdim;
    const int nk = K >> 5;

    const uint32_t a_row = (uint32_t)(wm * 64 + (lane & 15));
    const uint32_t a_kb  = (uint32_t)((lane >> 4) * 16);
    const int bmat = lane >> 3, bwin = lane & 7;
    const uint32_t b_n  = (uint32_t)(wn * 32 + bwin + (bmat >> 1) * 8);
    const uint32_t b_kb = (uint32_t)((bmat & 1) * 16);
    const int g = lane >> 2, t4 = lane & 3;

    if (blockIdx.x < QK_CBLK) {
        // ================= bf16 3-MMA Q|K path =================
        const int col0 = blockIdx.x * 128;

        float acc[4][4][4];
#pragma unroll
        for (int m = 0; m < 4; m++)
#pragma unroll
            for (int n = 0; n < 4; n++)
#pragma unroll
                for (int e = 0; e < 4; e++) acc[m][n][e] = 0.f;

        g_load_pair(sb0,           Ahi, Alo, row0, 0, K, tid);
        g_load_pair(sb0 + 2 * T_A, Bhi, Blo, col0, 0, K, tid);
        CP_COMMIT();

        for (int kc = 0; kc < nk; kc++) {
            uint32_t sb = sb0 + (uint32_t)(kc & 1) * T_STAGE;
            if (kc + 1 < nk) {
                uint32_t sb2 = sb0 + (uint32_t)((kc + 1) & 1) * T_STAGE;
                g_load_pair(sb2,           Ahi, Alo, row0, kc + 1, K, tid);
                g_load_pair(sb2 + 2 * T_A, Bhi, Blo, col0, kc + 1, K, tid);
                CP_COMMIT();
                CP_WAIT(1);
            } else {
                CP_WAIT(0);
            }
            __syncthreads();

            const uint32_t aB = sb + a_row * PITCH + a_kb;
            const uint32_t bB = sb + 2 * T_A + b_n * PITCH + b_kb;

#pragma unroll
            for (int ks = 0; ks < 2; ks++) {
                uint32_t ah[4][4], al[4][4], bh[2][4], bl[2][4];
#pragma unroll
                for (int m = 0; m < 4; m++) {
                    ldsm4(ah[m], aB + (uint32_t)(m * 16 * PITCH) + ks * 32);
                    ldsm4(al[m], aB + T_A + (uint32_t)(m * 16 * PITCH) + ks * 32);
                }
#pragma unroll
                for (int p = 0; p < 2; p++) {
                    ldsm4(bh[p], bB + (uint32_t)(p * 16 * PITCH) + ks * 32);
                    ldsm4(bl[p], bB + T_A + (uint32_t)(p * 16 * PITCH) + ks * 32);
                }
#pragma unroll
                for (int m = 0; m < 4; m++)
#pragma unroll
                    for (int p = 0; p < 2; p++)
#pragma unroll
                        for (int h = 0; h < 2; h++) {
                            float* c = acc[m][p * 2 + h];
                            uint32_t bhh[2] = {bh[p][h * 2], bh[p][h * 2 + 1]};
                            uint32_t bll[2] = {bl[p][h * 2], bl[p][h * 2 + 1]};
                            mma_bf16(c, ah[m], bhh);
                            mma_bf16(c, ah[m], bll);
                            mma_bf16(c, al[m], bhh);
                        }
            }
            __syncthreads();
        }

#pragma unroll
        for (int m = 0; m < 4; m++) {
            int r0 = row0 + wm * 64 + m * 16 + g;
#pragma unroll
            for (int n = 0; n < 4; n++) {
                int c = col0 + wn * 32 + n * 8 + 2 * t4;
                *(float2*)&C[(size_t)r0 * HDA + c] =
                    make_float2(acc[m][n][0], acc[m][n][1]);
                *(float2*)&C[(size_t)(r0 + 8) * HDA + c] =
                    make_float2(acc[m][n][2], acc[m][n][3]);
            }
        }
    } else {
        // ================= fp16 1-MMA V path =================
        const int col0 = (blockIdx.x - QK_CBLK) * 128;
        float* Cv = C + HDqk;

        float acc[4][4][4];
#pragma unroll
        for (int m = 0; m < 4; m++)
#pragma unroll
            for (int n = 0; n < 4; n++)
#pragma unroll
                for (int e = 0; e < 4; e++) acc[m][n][e] = 0.f;

        auto load_stage = [&](uint32_t sb, int kc) {
#pragma unroll
            for (int i = 0; i < 2; i++) {
                int s = tid + 256 * i;
                int row = s >> 2, part = s & 3;
                size_t goA = (size_t)(row0 + row) * K + (size_t)kc * 32 + part * 8;
                size_t goB = (size_t)(col0 + row) * K + (size_t)kc * 32 + part * 8;
                uint32_t so = (uint32_t)(row * PITCH + part * 16);
                CP_ASYNC16(sb + so,       Ah16 + goA);
                CP_ASYNC16(sb + T_A + so, Bv16 + goB);
            }
        };

        load_stage(sb0, 0);
        CP_COMMIT();

        for (int kc = 0; kc < nk; kc++) {
            uint32_t sb = sb0 + (uint32_t)(kc & 1) * (2 * T_A);
            if (kc + 1 < nk) {
                load_stage(sb0 + (uint32_t)((kc + 1) & 1) * (2 * T_A), kc + 1);
                CP_COMMIT();
                CP_WAIT(1);
            } else {
                CP_WAIT(0);
            }
            __syncthreads();

            const uint32_t aB = sb + a_row * PITCH + a_kb;
            const uint32_t bB = sb + T_A + b_n * PITCH + b_kb;

#pragma unroll
            for (int ks = 0; ks < 2; ks++) {
                uint32_t ah[4][4], bh[2][4];
#pragma unroll
                for (int m = 0; m < 4; m++)
                    ldsm4(ah[m], aB + (uint32_t)(m * 16 * PITCH) + ks * 32);
#pragma unroll
                for (int p = 0; p < 2; p++)
                    ldsm4(bh[p], bB + (uint32_t)(p * 16 * PITCH) + ks * 32);
#pragma unroll
                for (int m = 0; m < 4; m++)
#pragma unroll
                    for (int p = 0; p < 2; p++)
#pragma unroll
                        for (int h = 0; h < 2; h++) {
                            float* c = acc[m][p * 2 + h];
                            uint32_t bhh[2] = {bh[p][h * 2], bh[p][h * 2 + 1]};
                            mma_f16(c, ah[m], bhh);
                        }
            }
            __syncthreads();
        }

#pragma unroll
        for (int m = 0; m < 4; m++) {
            int r0 = row0 + wm * 64 + m * 16 + g;
#pragma unroll
            for (int n = 0; n < 4; n++) {
                int c = col0 + wn * 32 + n * 8 + 2 * t4;
                *(float2*)&Cv[(size_t)r0 * HDA + c] =
                    make_float2(acc[m][n][0], acc[m][n][1]);
                *(float2*)&Cv[(size_t)(r0 + 8) * HDA + c] =
                    make_float2(acc[m][n][2], acc[m][n][3]);
            }
        }
    }
}

// ---------------- fp16 1-MMA GEMM (2-stage): C = Ahi * Bhi^T ----------------
#define T3_STAGE (2 * T_A)             // Ah, Bh = 20480
#define G3_SMEM  (2 * T3_STAGE)        // 40960

__global__ void __launch_bounds__(256, 2) tcgemm3_kernel(
    const __half* __restrict__ Ahi, const __half* __restrict__ Bhi,
    float* __restrict__ C, int ldc, int K)
{
    extern __shared__ char smc[];
    const uint32_t sb0 = smem_u32(smc);
    const int tid  = threadIdx.x;
    const int lane = tid & 31;
    const int wid  = tid >> 5;
    const int wm   = wid & 1;
    const int wn   = wid >> 1;
    const int row0 = blockIdx.y * 128;
    const int col0 = blockIdx.x * 128;

    float acc[4][4][4];
#pragma unroll
    for (int m = 0; m < 4; m++)
#pragma unroll
        for (int n = 0; n < 4; n++)
#pragma unroll
            for (int e = 0; e < 4; e++) acc[m][n][e] = 0.f;

    const uint32_t a_row = (uint32_t)(wm * 64 + (lane & 15));
    const uint32_t a_kb  = (uint32_t)((lane >> 4) * 16);
    const int bmat = lane >> 3, bwin = lane & 7;
    const uint32_t b_n  = (uint32_t)(wn * 32 + bwin + (bmat >> 1) * 8);
    const uint32_t b_kb = (uint32_t)((bmat & 1) * 16);

    const int nk = K >> 5;

    auto load_stage = [&](uint32_t sb, int kc) {
#pragma unroll
        for (int i = 0; i < 2; i++) {
            int s = tid + 256 * i;
            int row = s >> 2, part = s & 3;
            size_t goA = (size_t)(row0 + row) * K + (size_t)kc * 32 + part * 8;
            size_t goB = (size_t)(col0 + row) * K + (size_t)kc * 32 + part * 8;
            uint32_t so = (uint32_t)(row * PITCH + part * 16);
            CP_ASYNC16(sb + so,       Ahi + goA);
            CP_ASYNC16(sb + T_A + so, Bhi + goB);
        }
    };

    load_stage(sb0, 0);
    CP_COMMIT();

    for (int kc = 0; kc < nk; kc++) {
        uint32_t sb = sb0 + (uint32_t)(kc & 1) * T3_STAGE;
        if (kc + 1 < nk) {
            load_stage(sb0 + (uint32_t)((kc + 1) & 1) * T3_STAGE, kc + 1);
            CP_COMMIT();
            CP_WAIT(1);
        } else {
            CP_WAIT(0);
        }
        __syncthreads();

        const uint32_t aB = sb + a_row * PITCH + a_kb;
        const uint32_t bB = sb + T_A + b_n * PITCH + b_kb;

#pragma unroll
        for (int ks = 0; ks < 2; ks++) {
            uint32_t ah[4][4], bh[2][4];
#pragma unroll
            for (int m = 0; m < 4; m++)
                ldsm4(ah[m], aB + (uint32_t)(m * 16 * PITCH) + ks * 32);
#pragma unroll
            for (int p = 0; p < 2; p++)
                ldsm4(bh[p], bB + (uint32_t)(p * 16 * PITCH) + ks * 32);
#pragma unroll
            for (int m = 0; m < 4; m++)
#pragma unroll
                for (int p = 0; p < 2; p++)
#pragma unroll
                    for (int h = 0; h < 2; h++) {
                        float* c = acc[m][p * 2 + h];
                        uint32_t bhh[2] = {bh[p][h * 2], bh[p][h * 2 + 1]};
                        mma_f16(c, ah[m], bhh);
                    }
        }
        __syncthreads();
    }

    const int g = lane >> 2, t = lane & 3;
#pragma unroll
    for (int m = 0; m < 4; m++) {
        int r0 = row0 + wm * 64 + m * 16 + g;
#pragma unroll
        for (int n = 0; n < 4; n++) {
            int c = col0 + wn * 32 + n * 8 + 2 * t;
            *(float2*)&C[(size_t)r0 * ldc + c] = make_float2(acc[m][n][0], acc[m][n][1]);
            *(float2*)&C[(size_t)(r0 + 8) * ldc + c] = make_float2(acc[m][n][2], acc[m][n][3]);
        }
    }
}

// ---------------- merged RoPE (vectorized): q part + kv part, one launch --------
// q additionally scaled by log2(e) so flash can use exp2f.
#define ROPE_QBLOCKS ((NH * Tn * 16) / 256)     // 4096
#define ROPE_KVBLOCKS ((NKV * Tn * 16) / 256)   // 1024

__global__ void __launch_bounds__(256) rope_all_kernel(
    const float* __restrict__ cosb, const float* __restrict__ sinb,
    float* __restrict__ outK, float* __restrict__ outV)
{
    int bid = blockIdx.x;
    if (bid < ROPE_QBLOCKS) {
        int idx = bid * 256 + threadIdx.x;
        int d = (idx & 15) * 4;
        int t = (idx >> 4) & (Tn - 1);
        int h = idx >> 15;
        const float* src = g_tqkv + (size_t)t * HDA + h * Dh;
        float4 u1 = *(const float4*)(src + d);
        float4 u2 = *(const float4*)(src + d + 64);
        float4 c1 = *(const float4*)&cosb[t * Dh + d];
        float4 s1 = *(const float4*)&sinb[t * Dh + d];
        float4 c2 = *(const float4*)&cosb[t * Dh + d + 64];
        float4 s2 = *(const float4*)&sinb[t * Dh + d + 64];
        float4 y1 = make_float4((u1.x * c1.x - u2.x * s1.x) * LOG2E,
                                (u1.y * c1.y - u2.y * s1.y) * LOG2E,
                                (u1.z * c1.z - u2.z * s1.z) * LOG2E,
                                (u1.w * c1.w - u2.w * s1.w) * LOG2E);
        float4 y2 = make_float4((u2.x * c2.x + u1.x * s2.x) * LOG2E,
                                (u2.y * c2.y + u1.y * s2.y) * LOG2E,
                                (u2.z * c2.z + u1.z * s2.z) * LOG2E,
                                (u2.w * c2.w + u1.w * s2.w) * LOG2E);
        size_t o = ((size_t)h * Tn + t) * Dh + d;
        uint2 hi1, lo1, hi2, lo2;
        pack4b(y1.x, y1.y, y1.z, y1.w, hi1, lo1);
        pack4b(y2.x, y2.y, y2.z, y2.w, hi2, lo2);
        *(uint2*)&g_qhi[o]      = hi1;
        *(uint2*)&g_qlo[o]      = lo1;
        *(uint2*)&g_qhi[o + 64] = hi2;
        *(uint2*)&g_qlo[o + 64] = lo2;
    } else {
        int idx = (bid - ROPE_QBLOCKS) * 256 + threadIdx.x;
        int d  = (idx & 15) * 4;
        int t  = (idx >> 4) & (Tn - 1);
        int kh = idx >> 15;
        const float* srck = g_tqkv + (size_t)t * HDA + HDq + kh * Dh;
        float4 u1 = *(const float4*)(srck + d);
        float4 u2 = *(const float4*)(srck + d + 64);
        float4 c1 = *(const float4*)&cosb[t * Dh + d];
        float4 s1 = *(const float4*)&sinb[t * Dh + d];
        float4 c2 = *(const float4*)&cosb[t * Dh + d + 64];
        float4 s2 = *(const float4*)&sinb[t * Dh + d + 64];
        float4 y1 = make_float4(u1.x * c1.x - u2.x * s1.x, u1.y * c1.y - u2.y * s1.y,
                                u1.z * c1.z - u2.z * s1.z, u1.w * c1.w - u2.w * s1.w);
        float4 y2 = make_float4(u2.x * c2.x + u1.x * s2.x, u2.y * c2.y + u1.y * s2.y,
                                u2.z * c2.z + u1.z * s2.z, u2.w * c2.w + u1.w * s2.w);
        size_t o = ((size_t)kh * Tn + t) * Dh + d;
        *(float4*)(outK + o)      = y1;
        *(float4*)(outK + o + 64) = y2;
        uint2 hi1, lo1, hi2, lo2;
        pack4b(y1.x, y1.y, y1.z, y1.w, hi1, lo1);
        pack4b(y2.x, y2.y, y2.z, y2.w, hi2, lo2);
        *(uint2*)&g_khi[o]      = hi1;
        *(uint2*)&g_klo[o]      = lo1;
        *(uint2*)&g_khi[o + 64] = hi2;
        *(uint2*)&g_klo[o + 64] = lo2;
        const float* srcv = srck + HDkv;
        float4 v1 = *(const float4*)(srcv + d);
        float4 v2 = *(const float4*)(srcv + d + 64);
        *(float4*)(outV + o)      = v1;
        *(float4*)(outV + o + 64) = v2;
        *(uint2*)&g_vh[o]      = pack4h(v1.x, v1.y, v1.z, v1.w);
        *(uint2*)&g_vh[o + 64] = pack4h(v2.x, v2.y, v2.z, v2.w);
    }
}

// ---------------- flash attention (QK: bf16 3-MMA, PV: fp16 2-MMA) ----------------
// q pre-scaled by log2(e) -> softmax uses exp2f. y emitted as single fp16 plane.
#define FP272   272
#define QTILE   (128 * FP272)          // 34816
#define KTILE   (64 * FP272)           // 17408
#define FSTAGE  (3 * KTILE)            // Kh, Kl, Vh = 52224
#define F_SMEM  (2 * QTILE + 3 * FSTAGE)  // 226304

__device__ __forceinline__ void f_load_kv(
    uint32_t st, const __nv_bfloat16* __restrict__ kh,
    const __nv_bfloat16* __restrict__ kl, const __half* __restrict__ vh, int tid)
{
#pragma unroll
    for (int i = 0; i < 4; i++) {
        int s = tid + 256 * i;
        int r = s >> 4, c = s & 15;
        uint32_t so = (uint32_t)(r * FP272 + c * 16);
        size_t go = (size_t)r * Dh + c * 8;
        CP_ASYNC16(st + so,             kh + go);
        CP_ASYNC16(st + KTILE + so,     kl + go);
        CP_ASYNC16(st + 2 * KTILE + so, vh + go);
    }
}

__global__ void __launch_bounds__(256) flash_mma_kernel(__half* __restrict__ ybhi)
{
    extern __shared__ char smc[];
    const uint32_t sb = smem_u32(smc);
    const int tid = threadIdx.x, lane = tid & 31, w = tid >> 5;
    const int h  = blockIdx.y;
    const int qi = (int)gridDim.x - 1 - (int)blockIdx.x;   // big tiles first
    const int q0 = qi * 128;
    const int kvh = h >> 2;
    const int nb = 2 * qi + 2;

    const uint32_t sQh = sb, sQl = sb + QTILE;
    const uint32_t sKV = sb + 2 * QTILE;

    const uint32_t aQoff = (uint32_t)((16 * w + (lane & 15)) * FP272 + (lane >> 4) * 16);
    const int bmat = lane >> 3, bwin = lane & 7;
    const uint32_t bKoff = (uint32_t)((bwin + ((bmat >> 1) << 3)) * FP272 + ((bmat & 1) << 4));
    const uint32_t bVoff = (uint32_t)((lane & 15) * FP272 + ((lane >> 4) << 4));

    const __nv_bfloat16* gKh = g_khi + (size_t)kvh * Tn * Dh;
    const __nv_bfloat16* gKl = g_klo + (size_t)kvh * Tn * Dh;
    const __half*        gVh = g_vh  + (size_t)kvh * Tn * Dh;

    {
        const __nv_bfloat16* gqh = g_qhi + ((size_t)h * Tn + q0) * Dh;
        const __nv_bfloat16* gql = g_qlo + ((size_t)h * Tn + q0) * Dh;
#pragma unroll
        for (int i = 0; i < 8; i++) {
            int s = tid + 256 * i;
            int r = s >> 4, c = s & 15;
            uint32_t so = (uint32_t)(r * FP272 + c * 16);
            size_t go = (size_t)r * Dh + c * 8;
            CP_ASYNC16(sQh + so, gqh + go);
            CP_ASYNC16(sQl + so, gql + go);
        }
        f_load_kv(sKV, gKh, gKl, gVh, tid);
        CP_COMMIT();
        f_load_kv(sKV + FSTAGE, gKh + (size_t)64 * Dh, gKl + (size_t)64 * Dh,
                  gVh + (size_t)64 * Dh, tid);
        CP_COMMIT();
    }

    CP_WAIT(1);
    __syncthreads();
    uint32_t qh_f[8][4], ql_f[8][4];
#pragma unroll
    for (int ks = 0; ks < 8; ks++) {
        ldsm4(qh_f[ks], sQh + aQoff + ks * 32);
        ldsm4(ql_f[ks], sQl + aQoff + ks * 32);
    }

    float o[16][4];
#pragma unroll
    for (int dt = 0; dt < 16; dt++)
#pragma unroll
        for (int e = 0; e < 4; e++) o[dt][e] = 0.f;
    float m0 = -1e30f, m1 = -1e30f, l0 = 0.f, l1 = 0.f;

    const int row_lo = q0 + 16 * w + (lane >> 2);
    const int row_hi = row_lo + 8;

    for (int j = 0; j < nb; j++) {
        if (j > 0) {
            if (j + 1 < nb) CP_WAIT(1); else CP_WAIT(0);
            __syncthreads();
        }
        if (j + 2 < nb) {
            size_t kb = (size_t)(j + 2) * 64;
            f_load_kv(sKV + (uint32_t)((j + 2) % 3) * FSTAGE,
                      gKh + kb * Dh, gKl + kb * Dh, gVh + kb * Dh, tid);
            CP_COMMIT();
        }

        const uint32_t stg = sKV + (uint32_t)(j % 3) * FSTAGE;
        const int kb0 = j * 64;
        const bool active = (q0 + 16 * w + 15) >= kb0;

        if (active) {
            float sc[8][4];
#pragma unroll
            for (int nt = 0; nt < 8; nt++)
#pragma unroll
                for (int e = 0; e < 4; e++) sc[nt][e] = 0.f;

#pragma unroll
            for (int ks = 0; ks < 8; ks++) {
#pragma unroll
                for (int p = 0; p < 4; p++) {
                    uint32_t khf[4], klf[4];
                    uint32_t ka = stg + bKoff + (uint32_t)(p * 16 * FP272) + ks * 32;
                    ldsm4(khf, ka);
                    ldsm4(klf, ka + KTILE);
#pragma unroll
                    for (int hh = 0; hh < 2; hh++) {
                        float* c = sc[p * 2 + hh];
                        uint32_t bh2[2] = {khf[hh * 2], khf[hh * 2 + 1]};
                        uint32_t bl2[2] = {klf[hh * 2], klf[hh * 2 + 1]};
                        mma_bf16(c, qh_f[ks], bh2);
                        mma_bf16(c, qh_f[ks], bl2);
                        mma_bf16(c, ql_f[ks], bh2);
                    }
                }
            }

            if (kb0 + 63 > row_lo) {
#pragma unroll
                for (int nt = 0; nt < 8; nt++) {
                    int col = kb0 + nt * 8 + 2 * (lane & 3);
                    if (col > row_lo)     sc[nt][0] = -1e30f;
                    if (col + 1 > row_lo) sc[nt][1] = -1e30f;
                    if (col > row_hi)     sc[nt][2] = -1e30f;
                    if (col + 1 > row_hi) sc[nt][3] = -1e30f;
                }
            }

            float ml0 = -1e30f, ml1 = -1e30f;
#pragma unroll
            for (int nt = 0; nt < 8; nt++) {
                ml0 = fmaxf(ml0, fmaxf(sc[nt][0], sc[nt][1]));
                ml1 = fmaxf(ml1, fmaxf(sc[nt][2], sc[nt][3]));
            }
            ml0 = fmaxf(ml0, __shfl_xor_sync(0xffffffffu, ml0, 1));
            ml0 = fmaxf(ml0, __shfl_xor_sync(0xffffffffu, ml0, 2));
            ml1 = fmaxf(ml1, __shfl_xor_sync(0xffffffffu, ml1, 1));
            ml1 = fmaxf(ml1, __shfl_xor_sync(0xffffffffu, ml1, 2));
            float mn0 = fmaxf(m0, ml0), mn1 = fmaxf(m1, ml1);
            float es0 = exp2f(m0 - mn0), es1 = exp2f(m1 - mn1);
            float ls0 = 0.f, ls1 = 0.f;
#pragma unroll
            for (int nt = 0; nt < 8; nt++) {
                sc[nt][0] = exp2f(sc[nt][0] - mn0);
                sc[nt][1] = exp2f(sc[nt][1] - mn0);
                sc[nt][2] = exp2f(sc[nt][2] - mn1);
                sc[nt][3] = exp2f(sc[nt][3] - mn1);
                ls0 += sc[nt][0] + sc[nt][1];
                ls1 += sc[nt][2] + sc[nt][3];
            }
            ls0 += __shfl_xor_sync(0xffffffffu, ls0, 1);
            ls0 += __shfl_xor_sync(0xffffffffu, ls0, 2);
            ls1 += __shfl_xor_sync(0xffffffffu, ls1, 1);
            ls1 += __shfl_xor_sync(0xffffffffu, ls1, 2);
            l0 = l0 * es0 + ls0;  m0 = mn0;
            l1 = l1 * es1 + ls1;  m1 = mn1;
#pragma unroll
            for (int dt = 0; dt < 16; dt++) {
                o[dt][0] *= es0;  o[dt][1] *= es0;
                o[dt][2] *= es1;  o[dt][3] *= es1;
            }

#pragma unroll
            for (int j2 = 0; j2 < 4; j2++) {
                uint32_t ph[4], pl[4];
                split2h(sc[2 * j2][0],     sc[2 * j2][1],     ph[0], pl[0]);
                split2h(sc[2 * j2][2],     sc[2 * j2][3],     ph[1], pl[1]);
                split2h(sc[2 * j2 + 1][0], sc[2 * j2 + 1][1], ph[2], pl[2]);
                split2h(sc[2 * j2 + 1][2], sc[2 * j2 + 1][3], ph[3], pl[3]);
#pragma unroll
                for (int dt2 = 0; dt2 < 8; dt2++) {
                    uint32_t vhf[4];
                    uint32_t va = stg + 2 * KTILE + bVoff +
                                  (uint32_t)(j2 * 16 * FP272) + (uint32_t)(dt2 * 32);
                    ldsm4t(vhf, va);
#pragma unroll
                    for (int hf = 0; hf < 2; hf++) {
                        float* c = o[dt2 * 2 + hf];
                        uint32_t bh2[2] = {vhf[hf * 2], vhf[hf * 2 + 1]};
                        mma_f16(c, ph, bh2);
                        mma_f16(c, pl, bh2);
                    }
                }
            }
        }
    }

    // ---- epilogue: y as single fp16 plane for the Wo GEMM ----
    float inv0 = 1.f / l0, inv1 = 1.f / l1;
#pragma unroll
    for (int dt = 0; dt < 16; dt++) {
        int d = dt * 8 + 2 * (lane & 3);
        size_t o0 = (size_t)row_lo * Cdim + h * Dh + d;
        size_t o1 = (size_t)row_hi * Cdim + h * Dh + d;
        __half2 y0 = __floats2half2_rn(o[dt][0] * inv0, o[dt][1] * inv0);
        __half2 y1 = __floats2half2_rn(o[dt][2] * inv1, o[dt][3] * inv1);
        *reinterpret_cast<__half2*>(ybhi + o0) = y0;
        *reinterpret_cast<__half2*>(ybhi + o1) = y1;
    }
}

// ---------------- launch ----------------
extern "C" void kernel_launch(void* const* d_in, const int* in_sizes, int n_in,
                              void* d_out, int out_size)
{
    const float* x    = (const float*)d_in[0];
    const float* Wq   = (const float*)d_in[1];
    const float* Wk   = (const float*)d_in[2];
    const float* Wv   = (const float*)d_in[3];
    const float* Wo   = (const float*)d_in[4];
    const float* cosb = (const float*)d_in[5];
    const float* sinb = (const float*)d_in[6];
    // d_in[7] = mask (reproduced exactly by causal structure; unused)

    float* out  = (float*)d_out;
    float* outY = out;
    float* outK = out + (size_t)Tn * Cdim;
    float* outV = outK + (size_t)NKV * Tn * Dh;

    float* tqkv;
    cudaGetSymbolAddress((void**)&tqkv, g_tqkv);
    __nv_bfloat16 *xhi, *xlo, *wahi, *walo;
    __half *xh16, *ybhi, *wvh, *wohi;
    cudaGetSymbolAddress((void**)&xhi, g_xhi);
    cudaGetSymbolAddress((void**)&xlo, g_xlo);
    cudaGetSymbolAddress((void**)&xh16, g_xh16);
    cudaGetSymbolAddress((void**)&wahi, g_wahi);
    cudaGetSymbolAddress((void**)&walo, g_walo);
    cudaGetSymbolAddress((void**)&ybhi, g_ybhi);
    cudaGetSymbolAddress((void**)&wvh, g_wvh);
    cudaGetSymbolAddress((void**)&wohi, g_wohi);

    cudaFuncSetAttribute(tcgemm_qkv_kernel, cudaFuncAttributeMaxDynamicSharedMemorySize,
                         G_SMEM);
    cudaFuncSetAttribute(tcgemm3_kernel, cudaFuncAttributeMaxDynamicSharedMemorySize,
                         G3_SMEM);
    cudaFuncSetAttribute(flash_mma_kernel, cudaFuncAttributeMaxDynamicSharedMemorySize,
                         F_SMEM);

    // 0. merged prep: x split (bf16 hi/lo + fp16) + weight transposes (ONE launch)
    prep_kernel<<<PREP_END, 256>>>(x, Wq, Wk, Wv, Wo);

    // 1. fused Q|K (bf16 3-MMA) + V (fp16 1-MMA) projection — ONE launch, grid (48,16)
    tcgemm_qkv_kernel<<<dim3(48, Tn / 128), 256, G_SMEM>>>(
        xhi, xlo, wahi, walo, xh16, wvh, tqkv);

    // 2. merged RoPE + plane conversion (q scaled by log2e for exp2 softmax)
    rope_all_kernel<<<ROPE_QBLOCKS + ROPE_KVBLOCKS, 256>>>(cosb, sinb, outK, outV);

    // 3. causal flash attention (tensor cores, 3-stage KV pipeline)
    flash_mma_kernel<<<dim3(Tn / 128, NH), 256, F_SMEM>>>(ybhi);

    // 4. output projection (fp16 single-MMA)
    tcgemm3_kernel<<<dim3(Cdim / 128, Tn / 128), 256, G3_SMEM>>>(
        ybhi, wohi, outY, Cdim, Cdim);
}

// round 17
// speedup vs baseline: 1.1808x; 1.0296x over previous
#include <cuda_runtime.h>
#include <cuda_bf16.h>
#include <cuda_fp16.h>
#include <cstdint>

// Problem constants
#define Tn   2048
#define Cdim 4096
#define NH   32
#define NKV  8
#define Dh   128
#define HDq  (NH*Dh)    // 4096
#define HDkv (NKV*Dh)   // 1024
#define HDqk (HDq + HDkv)     // 5120 merged Q|K
#define HDA  (HDq + 2*HDkv)   // 6144 (q|k|v layout in g_tqkv)
#define LOG2E 1.4426950408889634f

// ---------------- scratch (device globals; no allocation) ----------------
__device__ __align__(256) float g_tqkv[(size_t)Tn * HDA];

__device__ __align__(256) __nv_bfloat16 g_xhi[Tn * Cdim];
__device__ __align__(256) __nv_bfloat16 g_xlo[Tn * Cdim];
__device__ __align__(256) __half       g_xh16[Tn * Cdim];
__device__ __align__(256) __nv_bfloat16 g_qhi[(size_t)NH * Tn * Dh];
__device__ __align__(256) __nv_bfloat16 g_qlo[(size_t)NH * Tn * Dh];
__device__ __align__(256) __nv_bfloat16 g_khi[(size_t)NKV * Tn * Dh];
__device__ __align__(256) __nv_bfloat16 g_klo[(size_t)NKV * Tn * Dh];
__device__ __align__(256) __half       g_vh [(size_t)NKV * Tn * Dh];
__device__ __align__(256) __half       g_ybhi[Tn * Cdim];
__device__ __align__(256) __nv_bfloat16 g_wahi[(size_t)HDqk * Cdim];
__device__ __align__(256) __nv_bfloat16 g_walo[(size_t)HDqk * Cdim];
__device__ __align__(256) __half       g_wvh[(size_t)HDkv * Cdim];
__device__ __align__(256) __half       g_wohi[(size_t)Cdim * Cdim];

// ---------------- baseline-ISA helpers (sm_80+ PTX only) ----------------
__device__ __forceinline__ uint32_t smem_u32(const void* p) {
    uint32_t a;
    asm("{ .reg .u64 t; cvta.to.shared.u64 t, %1; cvt.u32.u64 %0, t; }" : "=r"(a) : "l"(p));
    return a;
}

#define CP_ASYNC16(sm, gp) \
    asm volatile("cp.async.cg.shared.global [%0], [%1], 16;" :: "r"(sm), "l"(gp) : "memory")
#define CP_COMMIT() asm volatile("cp.async.commit_group;" ::: "memory")
#define CP_WAIT(n)  asm volatile("cp.async.wait_group %0;" :: "n"(n) : "memory")

__device__ __forceinline__ void ldsm4(uint32_t* r, uint32_t addr) {
    asm volatile("ldmatrix.sync.aligned.m8n8.x4.shared.b16 {%0,%1,%2,%3}, [%4];"
        : "=r"(r[0]), "=r"(r[1]), "=r"(r[2]), "=r"(r[3]) : "r"(addr));
}
__device__ __forceinline__ void ldsm4t(uint32_t* r, uint32_t addr) {
    asm volatile("ldmatrix.sync.aligned.m8n8.x4.trans.shared.b16 {%0,%1,%2,%3}, [%4];"
        : "=r"(r[0]), "=r"(r[1]), "=r"(r[2]), "=r"(r[3]) : "r"(addr));
}

__device__ __forceinline__ void mma_bf16(float* c, const uint32_t* a, const uint32_t* b) {
    asm volatile(
        "mma.sync.aligned.m16n8k16.row.col.f32.bf16.bf16.f32 "
        "{%0,%1,%2,%3}, {%4,%5,%6,%7}, {%8,%9}, {%0,%1,%2,%3};"
        : "+f"(c[0]), "+f"(c[1]), "+f"(c[2]), "+f"(c[3])
        : "r"(a[0]), "r"(a[1]), "r"(a[2]), "r"(a[3]), "r"(b[0]), "r"(b[1]));
}
__device__ __forceinline__ void mma_f16(float* c, const uint32_t* a, const uint32_t* b) {
    asm volatile(
        "mma.sync.aligned.m16n8k16.row.col.f32.f16.f16.f32 "
        "{%0,%1,%2,%3}, {%4,%5,%6,%7}, {%8,%9}, {%0,%1,%2,%3};"
        : "+f"(c[0]), "+f"(c[1]), "+f"(c[2]), "+f"(c[3])
        : "r"(a[0]), "r"(a[1]), "r"(a[2]), "r"(a[3]), "r"(b[0]), "r"(b[1]));
}

// pack 4 floats -> 4 bf16 hi (uint2) + 4 bf16 lo (uint2)
__device__ __forceinline__ void pack4b(float a, float b, float c, float d,
                                       uint2& hi, uint2& lo) {
    __nv_bfloat16 h0 = __float2bfloat16(a), h1 = __float2bfloat16(b);
    __nv_bfloat16 h2 = __float2bfloat16(c), h3 = __float2bfloat16(d);
    __nv_bfloat162 H01; H01.x = h0; H01.y = h1;
    __nv_bfloat162 H23; H23.x = h2; H23.y = h3;
    __nv_bfloat162 L01, L23;
    L01.x = __float2bfloat16(a - __bfloat162float(h0));
    L01.y = __float2bfloat16(b - __bfloat162float(h1));
    L23.x = __float2bfloat16(c - __bfloat162float(h2));
    L23.y = __float2bfloat16(d - __bfloat162float(h3));
    hi.x = *reinterpret_cast<uint32_t*>(&H01);
    hi.y = *reinterpret_cast<uint32_t*>(&H23);
    lo.x = *reinterpret_cast<uint32_t*>(&L01);
    lo.y = *reinterpret_cast<uint32_t*>(&L23);
}

__device__ __forceinline__ uint2 pack4h(float a, float b, float c, float d) {
    __half2 A = __floats2half2_rn(a, b);
    __half2 B = __floats2half2_rn(c, d);
    uint2 pk;
    pk.x = *reinterpret_cast<uint32_t*>(&A);
    pk.y = *reinterpret_cast<uint32_t*>(&B);
    return pk;
}

// ---------------- merged prep: x split + W transposes, one launch ----------------
#define PREP_X   4096
#define PREP_WQ  (PREP_X + 16384)
#define PREP_WK  (PREP_WQ + 4096)
#define PREP_WV  (PREP_WK + 4096)
#define PREP_END (PREP_WV + 16384)

__global__ void __launch_bounds__(256) prep_kernel(
    const float* __restrict__ x,
    const float* __restrict__ Wq, const float* __restrict__ Wk,
    const float* __restrict__ Wv, const float* __restrict__ Wo)
{
    __shared__ float tile[32][33];
    const int bid = blockIdx.x;
    if (bid < PREP_X) {
        int base = (bid * 256 + threadIdx.x) * 8;
#pragma unroll
        for (int half = 0; half < 2; half++) {
            int idx = base + half * 4;
            float4 v = *(const float4*)&x[idx];
            uint2 hi, lo;
            pack4b(v.x, v.y, v.z, v.w, hi, lo);
            *(uint2*)&g_xhi[idx] = hi;
            *(uint2*)&g_xlo[idx] = lo;
            *(uint2*)&g_xh16[idx] = pack4h(v.x, v.y, v.z, v.w);
        }
        return;
    }
    const float* W;
    __nv_bfloat16 *Thi, *Tlo;
    __half* Th16 = nullptr;
    int N, rel;
    if (bid < PREP_WQ)      { rel = bid - PREP_X;  W = Wq; N = HDq;
                              Thi = g_wahi; Tlo = g_walo; }
    else if (bid < PREP_WK) { rel = bid - PREP_WQ; W = Wk; N = HDkv;
                              Thi = g_wahi + (size_t)HDq * Cdim;
                              Tlo = g_walo + (size_t)HDq * Cdim; }
    else if (bid < PREP_WV) { rel = bid - PREP_WK; W = Wv; N = HDkv;
                              Thi = nullptr; Tlo = nullptr; Th16 = g_wvh; }
    else                    { rel = bid - PREP_WV; W = Wo; N = Cdim;
                              Thi = nullptr; Tlo = nullptr; Th16 = g_wohi; }

    const int ntiles = N / 32;
    int n0 = (rel % ntiles) * 32, k0 = (rel / ntiles) * 32;
    int tx = threadIdx.x & 31, ty = threadIdx.x >> 5;
#pragma unroll
    for (int j = 0; j < 4; j++)
        tile[ty + 8 * j][tx] = W[(size_t)(k0 + ty + 8 * j) * N + n0 + tx];
    __syncthreads();

    int n  = threadIdx.x >> 3;
    int kq = (threadIdx.x & 7) * 4;
    float v0 = tile[kq + 0][n], v1 = tile[kq + 1][n];
    float v2 = tile[kq + 2][n], v3 = tile[kq + 3][n];
    size_t o = (size_t)(n0 + n) * Cdim + k0 + kq;
    if (Th16) {
        *(uint2*)&Th16[o] = pack4h(v0, v1, v2, v3);
    } else {
        uint2 hi, lo;
        pack4b(v0, v1, v2, v3, hi, lo);
        *(uint2*)&Thi[o] = hi;
        *(uint2*)&Tlo[o] = lo;
    }
}

// ---------------- GEMM common geometry ----------------
#define PITCH   80
#define T_A     10240                  // 128 rows * 80B

// ---------------- fused QKV projection: one launch, grid (48, 16) ----------------
// blockIdx.x < 40 : bf16 3-MMA Q|K path (cols [0,5120) of g_tqkv)
// blockIdx.x >= 40: fp16 1-MMA V path  (cols [5120,6144) of g_tqkv)
#define T_STAGE (4 * T_A)
#define G_SMEM  (2 * T_STAGE)          // 81920 (covers both paths)
#define QK_CBLK (HDqk / 128)           // 40

__device__ __forceinline__ void g_load_pair(
    uint32_t sbase, const __nv_bfloat16* __restrict__ hi,
    const __nv_bfloat16* __restrict__ lo, int rbase, int kc, int K, int tid)
{
#pragma unroll
    for (int i = 0; i < 2; i++) {
        int s = tid + 256 * i;
        int row = s >> 2, part = s & 3;
        size_t go = (size_t)(rbase + row) * K + (size_t)kc * 32 + part * 8;
        uint32_t so = (uint32_t)(row * PITCH + part * 16);
        CP_ASYNC16(sbase + so, hi + go);
        CP_ASYNC16(sbase + T_A + so, lo + go);
    }
}

__global__ void __launch_bounds__(256, 2) tcgemm_qkv_kernel(
    const __nv_bfloat16* __restrict__ Ahi, const __nv_bfloat16* __restrict__ Alo,
    const __nv_bfloat16* __restrict__ Bhi, const __nv_bfloat16* __restrict__ Blo,
    const __half* __restrict__ Ah16, const __half* __restrict__ Bv16,
    float* __restrict__ C)
{
    extern __shared__ char smc[];
    const uint32_t sb0 = smem_u32(smc);
    const int tid  = threadIdx.x;
    const int lane = tid & 31;
    const int wid  = tid >> 5;
    const int wm   = wid & 1;
    const int wn   = wid >> 1;
    const int row0 = blockIdx.y * 128;
    const int K = Cdim;
    const int nk = K >> 5;

    const uint32_t a_row = (uint32_t)(wm * 64 + (lane & 15));
    const uint32_t a_kb  = (uint32_t)((lane >> 4) * 16);
    const int bmat = lane >> 3, bwin = lane & 7;
    const uint32_t b_n  = (uint32_t)(wn * 32 + bwin + (bmat >> 1) * 8);
    const uint32_t b_kb = (uint32_t)((bmat & 1) * 16);
    const int g = lane >> 2, t4 = lane & 3;

    if (blockIdx.x < QK_CBLK) {
        // ================= bf16 3-MMA Q|K path =================
        const int col0 = blockIdx.x * 128;

        float acc[4][4][4];
#pragma unroll
        for (int m = 0; m < 4; m++)
#pragma unroll
            for (int n = 0; n < 4; n++)
#pragma unroll
                for (int e = 0; e < 4; e++) acc[m][n][e] = 0.f;

        g_load_pair(sb0,           Ahi, Alo, row0, 0, K, tid);
        g_load_pair(sb0 + 2 * T_A, Bhi, Blo, col0, 0, K, tid);
        CP_COMMIT();

        for (int kc = 0; kc < nk; kc++) {
            uint32_t sb = sb0 + (uint32_t)(kc & 1) * T_STAGE;
            if (kc + 1 < nk) {
                uint32_t sb2 = sb0 + (uint32_t)((kc + 1) & 1) * T_STAGE;
                g_load_pair(sb2,           Ahi, Alo, row0, kc + 1, K, tid);
                g_load_pair(sb2 + 2 * T_A, Bhi, Blo, col0, kc + 1, K, tid);
                CP_COMMIT();
                CP_WAIT(1);
            } else {
                CP_WAIT(0);
            }
            __syncthreads();

            const uint32_t aB = sb + a_row * PITCH + a_kb;
            const uint32_t bB = sb + 2 * T_A + b_n * PITCH + b_kb;

#pragma unroll
            for (int ks = 0; ks < 2; ks++) {
                uint32_t ah[4][4], al[4][4], bh[2][4], bl[2][4];
#pragma unroll
                for (int m = 0; m < 4; m++) {
                    ldsm4(ah[m], aB + (uint32_t)(m * 16 * PITCH) + ks * 32);
                    ldsm4(al[m], aB + T_A + (uint32_t)(m * 16 * PITCH) + ks * 32);
                }
#pragma unroll
                for (int p = 0; p < 2; p++) {
                    ldsm4(bh[p], bB + (uint32_t)(p * 16 * PITCH) + ks * 32);
                    ldsm4(bl[p], bB + T_A + (uint32_t)(p * 16 * PITCH) + ks * 32);
                }
#pragma unroll
                for (int m = 0; m < 4; m++)
#pragma unroll
                    for (int p = 0; p < 2; p++)
#pragma unroll
                        for (int h = 0; h < 2; h++) {
                            float* c = acc[m][p * 2 + h];
                            uint32_t bhh[2] = {bh[p][h * 2], bh[p][h * 2 + 1]};
                            uint32_t bll[2] = {bl[p][h * 2], bl[p][h * 2 + 1]};
                            mma_bf16(c, ah[m], bhh);
                            mma_bf16(c, ah[m], bll);
                            mma_bf16(c, al[m], bhh);
                        }
            }
            __syncthreads();
        }

#pragma unroll
        for (int m = 0; m < 4; m++) {
            int r0 = row0 + wm * 64 + m * 16 + g;
#pragma unroll
            for (int n = 0; n < 4; n++) {
                int c = col0 + wn * 32 + n * 8 + 2 * t4;
                *(float2*)&C[(size_t)r0 * HDA + c] =
                    make_float2(acc[m][n][0], acc[m][n][1]);
                *(float2*)&C[(size_t)(r0 + 8) * HDA + c] =
                    make_float2(acc[m][n][2], acc[m][n][3]);
            }
        }
    } else {
        // ================= fp16 1-MMA V path =================
        const int col0 = (blockIdx.x - QK_CBLK) * 128;
        float* Cv = C + HDqk;

        float acc[4][4][4];
#pragma unroll
        for (int m = 0; m < 4; m++)
#pragma unroll
            for (int n = 0; n < 4; n++)
#pragma unroll
                for (int e = 0; e < 4; e++) acc[m][n][e] = 0.f;

        auto load_stage = [&](uint32_t sb, int kc) {
#pragma unroll
            for (int i = 0; i < 2; i++) {
                int s = tid + 256 * i;
                int row = s >> 2, part = s & 3;
                size_t goA = (size_t)(row0 + row) * K + (size_t)kc * 32 + part * 8;
                size_t goB = (size_t)(col0 + row) * K + (size_t)kc * 32 + part * 8;
                uint32_t so = (uint32_t)(row * PITCH + part * 16);
                CP_ASYNC16(sb + so,       Ah16 + goA);
                CP_ASYNC16(sb + T_A + so, Bv16 + goB);
            }
        };

        load_stage(sb0, 0);
        CP_COMMIT();

        for (int kc = 0; kc < nk; kc++) {
            uint32_t sb = sb0 + (uint32_t)(kc & 1) * (2 * T_A);
            if (kc + 1 < nk) {
                load_stage(sb0 + (uint32_t)((kc + 1) & 1) * (2 * T_A), kc + 1);
                CP_COMMIT();
                CP_WAIT(1);
            } else {
                CP_WAIT(0);
            }
            __syncthreads();

            const uint32_t aB = sb + a_row * PITCH + a_kb;
            const uint32_t bB = sb + T_A + b_n * PITCH + b_kb;

#pragma unroll
            for (int ks = 0; ks < 2; ks++) {
                uint32_t ah[4][4], bh[2][4];
#pragma unroll
                for (int m = 0; m < 4; m++)
                    ldsm4(ah[m], aB + (uint32_t)(m * 16 * PITCH) + ks * 32);
#pragma unroll
                for (int p = 0; p < 2; p++)
                    ldsm4(bh[p], bB + (uint32_t)(p * 16 * PITCH) + ks * 32);
#pragma unroll
                for (int m = 0; m < 4; m++)
#pragma unroll
                    for (int p = 0; p < 2; p++)
#pragma unroll
                        for (int h = 0; h < 2; h++) {
                            float* c = acc[m][p * 2 + h];
                            uint32_t bhh[2] = {bh[p][h * 2], bh[p][h * 2 + 1]};
                            mma_f16(c, ah[m], bhh);
                        }
            }
            __syncthreads();
        }

#pragma unroll
        for (int m = 0; m < 4; m++) {
            int r0 = row0 + wm * 64 + m * 16 + g;
#pragma unroll
            for (int n = 0; n < 4; n++) {
                int c = col0 + wn * 32 + n * 8 + 2 * t4;
                *(float2*)&Cv[(size_t)r0 * HDA + c] =
                    make_float2(acc[m][n][0], acc[m][n][1]);
                *(float2*)&Cv[(size_t)(r0 + 8) * HDA + c] =
                    make_float2(acc[m][n][2], acc[m][n][3]);
            }
        }
    }
}

// ---------------- fp16 1-MMA GEMM (2-stage): C = Ahi * Bhi^T ----------------
#define T3_STAGE (2 * T_A)             // Ah, Bh = 20480
#define G3_SMEM  (2 * T3_STAGE)        // 40960

__global__ void __launch_bounds__(256, 2) tcgemm3_kernel(
    const __half* __restrict__ Ahi, const __half* __restrict__ Bhi,
    float* __restrict__ C, int ldc, int K)
{
    extern __shared__ char smc[];
    const uint32_t sb0 = smem_u32(smc);
    const int tid  = threadIdx.x;
    const int lane = tid & 31;
    const int wid  = tid >> 5;
    const int wm   = wid & 1;
    const int wn   = wid >> 1;
    const int row0 = blockIdx.y * 128;
    const int col0 = blockIdx.x * 128;

    float acc[4][4][4];
#pragma unroll
    for (int m = 0; m < 4; m++)
#pragma unroll
        for (int n = 0; n < 4; n++)
#pragma unroll
            for (int e = 0; e < 4; e++) acc[m][n][e] = 0.f;

    const uint32_t a_row = (uint32_t)(wm * 64 + (lane & 15));
    const uint32_t a_kb  = (uint32_t)((lane >> 4) * 16);
    const int bmat = lane >> 3, bwin = lane & 7;
    const uint32_t b_n  = (uint32_t)(wn * 32 + bwin + (bmat >> 1) * 8);
    const uint32_t b_kb = (uint32_t)((bmat & 1) * 16);

    const int nk = K >> 5;

    auto load_stage = [&](uint32_t sb, int kc) {
#pragma unroll
        for (int i = 0; i < 2; i++) {
            int s = tid + 256 * i;
            int row = s >> 2, part = s & 3;
            size_t goA = (size_t)(row0 + row) * K + (size_t)kc * 32 + part * 8;
            size_t goB = (size_t)(col0 + row) * K + (size_t)kc * 32 + part * 8;
            uint32_t so = (uint32_t)(row * PITCH + part * 16);
            CP_ASYNC16(sb + so,       Ahi + goA);
            CP_ASYNC16(sb + T_A + so, Bhi + goB);
        }
    };

    load_stage(sb0, 0);
    CP_COMMIT();

    for (int kc = 0; kc < nk; kc++) {
        uint32_t sb = sb0 + (uint32_t)(kc & 1) * T3_STAGE;
        if (kc + 1 < nk) {
            load_stage(sb0 + (uint32_t)((kc + 1) & 1) * T3_STAGE, kc + 1);
            CP_COMMIT();
            CP_WAIT(1);
        } else {
            CP_WAIT(0);
        }
        __syncthreads();

        const uint32_t aB = sb + a_row * PITCH + a_kb;
        const uint32_t bB = sb + T_A + b_n * PITCH + b_kb;

#pragma unroll
        for (int ks = 0; ks < 2; ks++) {
            uint32_t ah[4][4], bh[2][4];
#pragma unroll
            for (int m = 0; m < 4; m++)
                ldsm4(ah[m], aB + (uint32_t)(m * 16 * PITCH) + ks * 32);
#pragma unroll
            for (int p = 0; p < 2; p++)
                ldsm4(bh[p], bB + (uint32_t)(p * 16 * PITCH) + ks * 32);
#pragma unroll
            for (int m = 0; m < 4; m++)
#pragma unroll
                for (int p = 0; p < 2; p++)
#pragma unroll
                    for (int h = 0; h < 2; h++) {
                        float* c = acc[m][p * 2 + h];
                        uint32_t bhh[2] = {bh[p][h * 2], bh[p][h * 2 + 1]};
                        mma_f16(c, ah[m], bhh);
                    }
        }
        __syncthreads();
    }

    const int g = lane >> 2, t = lane & 3;
#pragma unroll
    for (int m = 0; m < 4; m++) {
        int r0 = row0 + wm * 64 + m * 16 + g;
#pragma unroll
        for (int n = 0; n < 4; n++) {
            int c = col0 + wn * 32 + n * 8 + 2 * t;
            *(float2*)&C[(size_t)r0 * ldc + c] = make_float2(acc[m][n][0], acc[m][n][1]);
            *(float2*)&C[(size_t)(r0 + 8) * ldc + c] = make_float2(acc[m][n][2], acc[m][n][3]);
        }
    }
}

// ---------------- merged RoPE (vectorized): q part + kv part, one launch --------
// q additionally scaled by log2(e) so flash can use exp2f.
#define ROPE_QBLOCKS ((NH * Tn * 16) / 256)     // 4096
#define ROPE_KVBLOCKS ((NKV * Tn * 16) / 256)   // 1024

__global__ void __launch_bounds__(256) rope_all_kernel(
    const float* __restrict__ cosb, const float* __restrict__ sinb,
    float* __restrict__ outK, float* __restrict__ outV)
{
    int bid = blockIdx.x;
    if (bid < ROPE_QBLOCKS) {
        int idx = bid * 256 + threadIdx.x;
        int d = (idx & 15) * 4;
        int t = (idx >> 4) & (Tn - 1);
        int h = idx >> 15;
        const float* src = g_tqkv + (size_t)t * HDA + h * Dh;
        float4 u1 = *(const float4*)(src + d);
        float4 u2 = *(const float4*)(src + d + 64);
        float4 c1 = *(const float4*)&cosb[t * Dh + d];
        float4 s1 = *(const float4*)&sinb[t * Dh + d];
        float4 c2 = *(const float4*)&cosb[t * Dh + d + 64];
        float4 s2 = *(const float4*)&sinb[t * Dh + d + 64];
        float4 y1 = make_float4((u1.x * c1.x - u2.x * s1.x) * LOG2E,
                                (u1.y * c1.y - u2.y * s1.y) * LOG2E,
                                (u1.z * c1.z - u2.z * s1.z) * LOG2E,
                                (u1.w * c1.w - u2.w * s1.w) * LOG2E);
        float4 y2 = make_float4((u2.x * c2.x + u1.x * s2.x) * LOG2E,
                                (u2.y * c2.y + u1.y * s2.y) * LOG2E,
                                (u2.z * c2.z + u1.z * s2.z) * LOG2E,
                                (u2.w * c2.w + u1.w * s2.w) * LOG2E);
        size_t o = ((size_t)h * Tn + t) * Dh + d;
        uint2 hi1, lo1, hi2, lo2;
        pack4b(y1.x, y1.y, y1.z, y1.w, hi1, lo1);
        pack4b(y2.x, y2.y, y2.z, y2.w, hi2, lo2);
        *(uint2*)&g_qhi[o]      = hi1;
        *(uint2*)&g_qlo[o]      = lo1;
        *(uint2*)&g_qhi[o + 64] = hi2;
        *(uint2*)&g_qlo[o + 64] = lo2;
    } else {
        int idx = (bid - ROPE_QBLOCKS) * 256 + threadIdx.x;
        int d  = (idx & 15) * 4;
        int t  = (idx >> 4) & (Tn - 1);
        int kh = idx >> 15;
        const float* srck = g_tqkv + (size_t)t * HDA + HDq + kh * Dh;
        float4 u1 = *(const float4*)(srck + d);
        float4 u2 = *(const float4*)(srck + d + 64);
        float4 c1 = *(const float4*)&cosb[t * Dh + d];
        float4 s1 = *(const float4*)&sinb[t * Dh + d];
        float4 c2 = *(const float4*)&cosb[t * Dh + d + 64];
        float4 s2 = *(const float4*)&sinb[t * Dh + d + 64];
        float4 y1 = make_float4(u1.x * c1.x - u2.x * s1.x, u1.y * c1.y - u2.y * s1.y,
                                u1.z * c1.z - u2.z * s1.z, u1.w * c1.w - u2.w * s1.w);
        float4 y2 = make_float4(u2.x * c2.x + u1.x * s2.x, u2.y * c2.y + u1.y * s2.y,
                                u2.z * c2.z + u1.z * s2.z, u2.w * c2.w + u1.w * s2.w);
        size_t o = ((size_t)kh * Tn + t) * Dh + d;
        *(float4*)(outK + o)      = y1;
        *(float4*)(outK + o + 64) = y2;
        uint2 hi1, lo1, hi2, lo2;
        pack4b(y1.x, y1.y, y1.z, y1.w, hi1, lo1);
        pack4b(y2.x, y2.y, y2.z, y2.w, hi2, lo2);
        *(uint2*)&g_khi[o]      = hi1;
        *(uint2*)&g_klo[o]      = lo1;
        *(uint2*)&g_khi[o + 64] = hi2;
        *(uint2*)&g_klo[o + 64] = lo2;
        const float* srcv = srck + HDkv;
        float4 v1 = *(const float4*)(srcv + d);
        float4 v2 = *(const float4*)(srcv + d + 64);
        *(float4*)(outV + o)      = v1;
        *(float4*)(outV + o + 64) = v2;
        *(uint2*)&g_vh[o]      = pack4h(v1.x, v1.y, v1.z, v1.w);
        *(uint2*)&g_vh[o + 64] = pack4h(v2.x, v2.y, v2.z, v2.w);
    }
}

// ---------------- flash attention (QK: bf16 3-MMA, PV: fp16 1-MMA) ----------------
// q pre-scaled by log2(e) -> softmax uses exp2f. y emitted as single fp16 plane.
#define FP272   272
#define QTILE   (128 * FP272)          // 34816
#define KTILE   (64 * FP272)           // 17408
#define FSTAGE  (3 * KTILE)            // Kh, Kl, Vh = 52224
#define F_SMEM  (2 * QTILE + 3 * FSTAGE)  // 226304

__device__ __forceinline__ void f_load_kv(
    uint32_t st, const __nv_bfloat16* __restrict__ kh,
    const __nv_bfloat16* __restrict__ kl, const __half* __restrict__ vh, int tid)
{
#pragma unroll
    for (int i = 0; i < 4; i++) {
        int s = tid + 256 * i;
        int r = s >> 4, c = s & 15;
        uint32_t so = (uint32_t)(r * FP272 + c * 16);
        size_t go = (size_t)r * Dh + c * 8;
        CP_ASYNC16(st + so,             kh + go);
        CP_ASYNC16(st + KTILE + so,     kl + go);
        CP_ASYNC16(st + 2 * KTILE + so, vh + go);
    }
}

__global__ void __launch_bounds__(256) flash_mma_kernel(__half* __restrict__ ybhi)
{
    extern __shared__ char smc[];
    const uint32_t sb = smem_u32(smc);
    const int tid = threadIdx.x, lane = tid & 31, w = tid >> 5;
    const int h  = blockIdx.y;
    const int qi = (int)gridDim.x - 1 - (int)blockIdx.x;   // big tiles first
    const int q0 = qi * 128;
    const int kvh = h >> 2;
    const int nb = 2 * qi + 2;

    const uint32_t sQh = sb, sQl = sb + QTILE;
    const uint32_t sKV = sb + 2 * QTILE;

    const uint32_t aQoff = (uint32_t)((16 * w + (lane & 15)) * FP272 + (lane >> 4) * 16);
    const int bmat = lane >> 3, bwin = lane & 7;
    const uint32_t bKoff = (uint32_t)((bwin + ((bmat >> 1) << 3)) * FP272 + ((bmat & 1) << 4));
    const uint32_t bVoff = (uint32_t)((lane & 15) * FP272 + ((lane >> 4) << 4));

    const __nv_bfloat16* gKh = g_khi + (size_t)kvh * Tn * Dh;
    const __nv_bfloat16* gKl = g_klo + (size_t)kvh * Tn * Dh;
    const __half*        gVh = g_vh  + (size_t)kvh * Tn * Dh;

    {
        const __nv_bfloat16* gqh = g_qhi + ((size_t)h * Tn + q0) * Dh;
        const __nv_bfloat16* gql = g_qlo + ((size_t)h * Tn + q0) * Dh;
#pragma unroll
        for (int i = 0; i < 8; i++) {
            int s = tid + 256 * i;
            int r = s >> 4, c = s & 15;
            uint32_t so = (uint32_t)(r * FP272 + c * 16);
            size_t go = (size_t)r * Dh + c * 8;
            CP_ASYNC16(sQh + so, gqh + go);
            CP_ASYNC16(sQl + so, gql + go);
        }
        f_load_kv(sKV, gKh, gKl, gVh, tid);
        CP_COMMIT();
        f_load_kv(sKV + FSTAGE, gKh + (size_t)64 * Dh, gKl + (size_t)64 * Dh,
                  gVh + (size_t)64 * Dh, tid);
        CP_COMMIT();
    }

    CP_WAIT(1);
    __syncthreads();
    uint32_t qh_f[8][4], ql_f[8][4];
#pragma unroll
    for (int ks = 0; ks < 8; ks++) {
        ldsm4(qh_f[ks], sQh + aQoff + ks * 32);
        ldsm4(ql_f[ks], sQl + aQoff + ks * 32);
    }

    float o[16][4];
#pragma unroll
    for (int dt = 0; dt < 16; dt++)
#pragma unroll
        for (int e = 0; e < 4; e++) o[dt][e] = 0.f;
    float m0 = -1e30f, m1 = -1e30f, l0 = 0.f, l1 = 0.f;

    const int row_lo = q0 + 16 * w + (lane >> 2);
    const int row_hi = row_lo + 8;

    for (int j = 0; j < nb; j++) {
        if (j > 0) {
            if (j + 1 < nb) CP_WAIT(1); else CP_WAIT(0);
            __syncthreads();
        }
        if (j + 2 < nb) {
            size_t kb = (size_t)(j + 2) * 64;
            f_load_kv(sKV + (uint32_t)((j + 2) % 3) * FSTAGE,
                      gKh + kb * Dh, gKl + kb * Dh, gVh + kb * Dh, tid);
            CP_COMMIT();
        }

        const uint32_t stg = sKV + (uint32_t)(j % 3) * FSTAGE;
        const int kb0 = j * 64;
        const bool active = (q0 + 16 * w + 15) >= kb0;

        if (active) {
            float sc[8][4];
#pragma unroll
            for (int nt = 0; nt < 8; nt++)
#pragma unroll
                for (int e = 0; e < 4; e++) sc[nt][e] = 0.f;

#pragma unroll
            for (int ks = 0; ks < 8; ks++) {
#pragma unroll
                for (int p = 0; p < 4; p++) {
                    uint32_t khf[4], klf[4];
                    uint32_t ka = stg + bKoff + (uint32_t)(p * 16 * FP272) + ks * 32;
                    ldsm4(khf, ka);
                    ldsm4(klf, ka + KTILE);
#pragma unroll
                    for (int hh = 0; hh < 2; hh++) {
                        float* c = sc[p * 2 + hh];
                        uint32_t bh2[2] = {khf[hh * 2], khf[hh * 2 + 1]};
                        uint32_t bl2[2] = {klf[hh * 2], klf[hh * 2 + 1]};
                        mma_bf16(c, qh_f[ks], bh2);
                        mma_bf16(c, qh_f[ks], bl2);
                        mma_bf16(c, ql_f[ks], bh2);
                    }
                }
            }

            if (kb0 + 63 > row_lo) {
#pragma unroll
                for (int nt = 0; nt < 8; nt++) {
                    int col = kb0 + nt * 8 + 2 * (lane & 3);
                    if (col > row_lo)     sc[nt][0] = -1e30f;
                    if (col + 1 > row_lo) sc[nt][1] = -1e30f;
                    if (col > row_hi)     sc[nt][2] = -1e30f;
                    if (col + 1 > row_hi) sc[nt][3] = -1e30f;
                }
            }

            float ml0 = -1e30f, ml1 = -1e30f;
#pragma unroll
            for (int nt = 0; nt < 8; nt++) {
                ml0 = fmaxf(ml0, fmaxf(sc[nt][0], sc[nt][1]));
                ml1 = fmaxf(ml1, fmaxf(sc[nt][2], sc[nt][3]));
            }
            ml0 = fmaxf(ml0, __shfl_xor_sync(0xffffffffu, ml0, 1));
            ml0 = fmaxf(ml0, __shfl_xor_sync(0xffffffffu, ml0, 2));
            ml1 = fmaxf(ml1, __shfl_xor_sync(0xffffffffu, ml1, 1));
            ml1 = fmaxf(ml1, __shfl_xor_sync(0xffffffffu, ml1, 2));
            float mn0 = fmaxf(m0, ml0), mn1 = fmaxf(m1, ml1);
            float es0 = exp2f(m0 - mn0), es1 = exp2f(m1 - mn1);
            float ls0 = 0.f, ls1 = 0.f;
#pragma unroll
            for (int nt = 0; nt < 8; nt++) {
                sc[nt][0] = exp2f(sc[nt][0] - mn0);
                sc[nt][1] = exp2f(sc[nt][1] - mn0);
                sc[nt][2] = exp2f(sc[nt][2] - mn1);
                sc[nt][3] = exp2f(sc[nt][3] - mn1);
                ls0 += sc[nt][0] + sc[nt][1];
                ls1 += sc[nt][2] + sc[nt][3];
            }
            ls0 += __shfl_xor_sync(0xffffffffu, ls0, 1);
            ls0 += __shfl_xor_sync(0xffffffffu, ls0, 2);
            ls1 += __shfl_xor_sync(0xffffffffu, ls1, 1);
            ls1 += __shfl_xor_sync(0xffffffffu, ls1, 2);
            l0 = l0 * es0 + ls0;  m0 = mn0;
            l1 = l1 * es1 + ls1;  m1 = mn1;
#pragma unroll
            for (int dt = 0; dt < 16; dt++) {
                o[dt][0] *= es0;  o[dt][1] *= es0;
                o[dt][2] *= es1;  o[dt][3] *= es1;
            }

            // ---- O += P * V : fp16 1-MMA (P hi only; fp32 l normalizes exactly) ----
#pragma unroll
            for (int j2 = 0; j2 < 4; j2++) {
                uint32_t ph[4];
                {
                    __half2 p0 = __floats2half2_rn(sc[2 * j2][0],     sc[2 * j2][1]);
                    __half2 p1 = __floats2half2_rn(sc[2 * j2][2],     sc[2 * j2][3]);
                    __half2 p2 = __floats2half2_rn(sc[2 * j2 + 1][0], sc[2 * j2 + 1][1]);
                    __half2 p3 = __floats2half2_rn(sc[2 * j2 + 1][2], sc[2 * j2 + 1][3]);
                    ph[0] = *reinterpret_cast<uint32_t*>(&p0);
                    ph[1] = *reinterpret_cast<uint32_t*>(&p1);
                    ph[2] = *reinterpret_cast<uint32_t*>(&p2);
                    ph[3] = *reinterpret_cast<uint32_t*>(&p3);
                }
#pragma unroll
                for (int dt2 = 0; dt2 < 8; dt2++) {
                    uint32_t vhf[4];
                    uint32_t va = stg + 2 * KTILE + bVoff +
                                  (uint32_t)(j2 * 16 * FP272) + (uint32_t)(dt2 * 32);
                    ldsm4t(vhf, va);
#pragma unroll
                    for (int hf = 0; hf < 2; hf++) {
                        float* c = o[dt2 * 2 + hf];
                        uint32_t bh2[2] = {vhf[hf * 2], vhf[hf * 2 + 1]};
                        mma_f16(c, ph, bh2);
                    }
                }
            }
        }
    }

    // ---- epilogue: y as single fp16 plane for the Wo GEMM ----
    float inv0 = 1.f / l0, inv1 = 1.f / l1;
#pragma unroll
    for (int dt = 0; dt < 16; dt++) {
        int d = dt * 8 + 2 * (lane & 3);
        size_t o0 = (size_t)row_lo * Cdim + h * Dh + d;
        size_t o1 = (size_t)row_hi * Cdim + h * Dh + d;
        __half2 y0 = __floats2half2_rn(o[dt][0] * inv0, o[dt][1] * inv0);
        __half2 y1 = __floats2half2_rn(o[dt][2] * inv1, o[dt][3] * inv1);
        *reinterpret_cast<__half2*>(ybhi + o0) = y0;
        *reinterpret_cast<__half2*>(ybhi + o1) = y1;
    }
}

// ---------------- launch ----------------
extern "C" void kernel_launch(void* const* d_in, const int* in_sizes, int n_in,
                              void* d_out, int out_size)
{
    const float* x    = (const float*)d_in[0];
    const float* Wq   = (const float*)d_in[1];
    const float* Wk   = (const float*)d_in[2];
    const float* Wv   = (const float*)d_in[3];
    const float* Wo   = (const float*)d_in[4];
    const float* cosb = (const float*)d_in[5];
    const float* sinb = (const float*)d_in[6];
    // d_in[7] = mask (reproduced exactly by causal structure; unused)

    float* out  = (float*)d_out;
    float* outY = out;
    float* outK = out + (size_t)Tn * Cdim;
    float* outV = outK + (size_t)NKV * Tn * Dh;

    float* tqkv;
    cudaGetSymbolAddress((void**)&tqkv, g_tqkv);
    __nv_bfloat16 *xhi, *xlo, *wahi, *walo;
    __half *xh16, *ybhi, *wvh, *wohi;
    cudaGetSymbolAddress((void**)&xhi, g_xhi);
    cudaGetSymbolAddress((void**)&xlo, g_xlo);
    cudaGetSymbolAddress((void**)&xh16, g_xh16);
    cudaGetSymbolAddress((void**)&wahi, g_wahi);
    cudaGetSymbolAddress((void**)&walo, g_walo);
    cudaGetSymbolAddress((void**)&ybhi, g_ybhi);
    cudaGetSymbolAddress((void**)&wvh, g_wvh);
    cudaGetSymbolAddress((void**)&wohi, g_wohi);

    cudaFuncSetAttribute(tcgemm_qkv_kernel, cudaFuncAttributeMaxDynamicSharedMemorySize,
                         G_SMEM);
    cudaFuncSetAttribute(tcgemm3_kernel, cudaFuncAttributeMaxDynamicSharedMemorySize,
                         G3_SMEM);
    cudaFuncSetAttribute(flash_mma_kernel, cudaFuncAttributeMaxDynamicSharedMemorySize,
                         F_SMEM);

    // 0. merged prep: x split (bf16 hi/lo + fp16) + weight transposes (ONE launch)
    prep_kernel<<<PREP_END, 256>>>(x, Wq, Wk, Wv, Wo);

    // 1. fused Q|K (bf16 3-MMA) + V (fp16 1-MMA) projection — ONE launch, grid (48,16)
    tcgemm_qkv_kernel<<<dim3(48, Tn / 128), 256, G_SMEM>>>(
        xhi, xlo, wahi, walo, xh16, wvh, tqkv);

    // 2. merged RoPE + plane conversion (q scaled by log2e for exp2 softmax)
    rope_all_kernel<<<ROPE_QBLOCKS + ROPE_KVBLOCKS, 256>>>(cosb, sinb, outK, outV);

    // 3. causal flash attention (QK 3-MMA bf16, PV 1-MMA fp16)
    flash_mma_kernel<<<dim3(Tn / 128, NH), 256, F_SMEM>>>(ybhi);

    // 4. output projection (fp16 single-MMA)
    tcgemm3_kernel<<<dim3(Cdim / 128, Tn / 128), 256, G3_SMEM>>>(
        ybhi, wohi, outY, Cdim, Cdim);
}